// round 7
// baseline (speedup 1.0000x reference)
#include <cuda_runtime.h>
#include <cuda_bf16.h>
#include <cstdint>

#define NPIX 65536

// ---------------- scratch (device globals; no allocation) ----------------
__device__ float g_tilt[3 * NPIX];
__device__ float g_h1[(size_t)NPIX * 200];
__device__ float g_h2[(size_t)NPIX * 200];
__device__ float g_coef[(size_t)NPIX * 100];
__device__ float g_A[40 * NPIX];
__device__ float g_Bmu[30 * NPIX];
__device__ float g_denmu;

// ---------------- warp-mma helpers ----------------
__device__ __forceinline__ void mma_bf16(float* c, uint32_t a0, uint32_t a1, uint32_t a2,
                                         uint32_t a3, uint32_t b0, uint32_t b1) {
    asm volatile(
        "mma.sync.aligned.m16n8k16.row.col.f32.bf16.bf16.f32 "
        "{%0,%1,%2,%3}, {%4,%5,%6,%7}, {%8,%9}, {%0,%1,%2,%3};"
        : "+f"(c[0]), "+f"(c[1]), "+f"(c[2]), "+f"(c[3])
        : "r"(a0), "r"(a1), "r"(a2), "r"(a3), "r"(b0), "r"(b1));
}
__device__ __forceinline__ uint32_t pack_bf16x2(float a, float b) {
    __nv_bfloat162 t;
    t.x = __float2bfloat16(a);
    t.y = __float2bfloat16(b);
    return *reinterpret_cast<uint32_t*>(&t);
}

// ---------------- per-warp MLP body over an N-subrange ----------------
template <int NOUT, int K, int LDA, int AOFF, int ACT, int NTH>
__device__ __forceinline__ void mlp_body(const float* __restrict__ A, float* __restrict__ C,
                                         const __nv_bfloat16* sh, const __nv_bfloat16* sl,
                                         const float* bias_s, int lane, int gp, int gstride,
                                         int noff) {
    constexpr int KC = (K + 15) / 16;
    constexpr int KP = KC * 16;
    constexpr int KS = KP + 8;   // row stride (elems): conflict-free quad mapping
    constexpr bool VEC = (LDA % 2 == 0) && (AOFF % 2 == 0);
    const int k0 = (lane & 3) * 2;
    const int nrow = lane >> 2;

    for (int wt = gp; wt < 4096; wt += gstride) {
        int row0 = wt * 16 + nrow;
        int row1 = row0 + 8;
        const float* ar0 = A + (size_t)row0 * LDA + AOFF;
        const float* ar1 = A + (size_t)row1 * LDA + AOFF;

        float acc[NTH][4];
#pragma unroll
        for (int nt = 0; nt < NTH; nt++)
#pragma unroll
            for (int q = 0; q < 4; q++) acc[nt][q] = 0.0f;

#pragma unroll
        for (int kc = 0; kc < KC; kc++) {
            int kb = kc * 16 + k0;
            float x00, x01, x02, x03, x10, x11, x12, x13;
            if (VEC) {
                float2 p0 = (kb + 1 < K) ? *(const float2*)(ar0 + kb)
                                         : make_float2(kb < K ? ar0[kb] : 0.f, 0.f);
                float2 p1 = (kb + 1 < K) ? *(const float2*)(ar1 + kb)
                                         : make_float2(kb < K ? ar1[kb] : 0.f, 0.f);
                float2 p2 = (kb + 9 < K) ? *(const float2*)(ar0 + kb + 8)
                                         : make_float2(kb + 8 < K ? ar0[kb + 8] : 0.f, 0.f);
                float2 p3 = (kb + 9 < K) ? *(const float2*)(ar1 + kb + 8)
                                         : make_float2(kb + 8 < K ? ar1[kb + 8] : 0.f, 0.f);
                x00 = p0.x; x01 = p0.y; x10 = p1.x; x11 = p1.y;
                x02 = p2.x; x03 = p2.y; x12 = p3.x; x13 = p3.y;
            } else {
                x00 = (kb < K) ? ar0[kb] : 0.f;
                x01 = (kb + 1 < K) ? ar0[kb + 1] : 0.f;
                x10 = (kb < K) ? ar1[kb] : 0.f;
                x11 = (kb + 1 < K) ? ar1[kb + 1] : 0.f;
                x02 = (kb + 8 < K) ? ar0[kb + 8] : 0.f;
                x03 = (kb + 9 < K) ? ar0[kb + 9] : 0.f;
                x12 = (kb + 8 < K) ? ar1[kb + 8] : 0.f;
                x13 = (kb + 9 < K) ? ar1[kb + 9] : 0.f;
            }
            uint32_t ah0 = pack_bf16x2(x00, x01);
            uint32_t ah1 = pack_bf16x2(x10, x11);
            uint32_t ah2 = pack_bf16x2(x02, x03);
            uint32_t ah3 = pack_bf16x2(x12, x13);
            float r00 = x00 - __bfloat162float(__float2bfloat16(x00));
            float r01 = x01 - __bfloat162float(__float2bfloat16(x01));
            float r10 = x10 - __bfloat162float(__float2bfloat16(x10));
            float r11 = x11 - __bfloat162float(__float2bfloat16(x11));
            float r02 = x02 - __bfloat162float(__float2bfloat16(x02));
            float r03 = x03 - __bfloat162float(__float2bfloat16(x03));
            float r12 = x12 - __bfloat162float(__float2bfloat16(x12));
            float r13 = x13 - __bfloat162float(__float2bfloat16(x13));
            uint32_t al0 = pack_bf16x2(r00, r01);
            uint32_t al1 = pack_bf16x2(r10, r11);
            uint32_t al2 = pack_bf16x2(r02, r03);
            uint32_t al3 = pack_bf16x2(r12, r13);

#pragma unroll
            for (int nt = 0; nt < NTH; nt++) {
                int n = noff + nt * 8 + nrow;
                const __nv_bfloat16* ph = sh + n * KS + kc * 16 + k0;
                const __nv_bfloat16* pl = sl + n * KS + kc * 16 + k0;
                uint32_t bh0 = *reinterpret_cast<const uint32_t*>(ph);
                uint32_t bh1 = *reinterpret_cast<const uint32_t*>(ph + 8);
                uint32_t bl0 = *reinterpret_cast<const uint32_t*>(pl);
                uint32_t bl1 = *reinterpret_cast<const uint32_t*>(pl + 8);
                mma_bf16(acc[nt], ah0, ah1, ah2, ah3, bh0, bh1);
                mma_bf16(acc[nt], ah0, ah1, ah2, ah3, bl0, bl1);
                mma_bf16(acc[nt], al0, al1, al2, al3, bh0, bh1);
            }
        }

        float* c0 = C + (size_t)row0 * NOUT;
        float* c1 = C + (size_t)row1 * NOUT;
#pragma unroll
        for (int nt = 0; nt < NTH; nt++) {
            int cc = noff + nt * 8 + k0;
            if (cc < NOUT) {
                float b0v = bias_s[cc], b1v = bias_s[cc + 1];
                float v0 = acc[nt][0] + b0v, v1 = acc[nt][1] + b1v;
                float v2 = acc[nt][2] + b0v, v3 = acc[nt][3] + b1v;
                if (ACT) {
                    v0 = v0 > 0.f ? v0 : 0.01f * v0;
                    v1 = v1 > 0.f ? v1 : 0.01f * v1;
                    v2 = v2 > 0.f ? v2 : 0.01f * v2;
                    v3 = v3 > 0.f ? v3 : 0.01f * v3;
                }
                *reinterpret_cast<float2*>(c0 + cc) = make_float2(v0, v1);
                *reinterpret_cast<float2*>(c1 + cc) = make_float2(v2, v3);
            }
        }
    }
}

// ================= split-bf16 warp-mma MLP layer =================
// 768 threads = 24 warps = 6 warp-quads; a quad shares one 16-row M-tile,
// its 4 warps split the N range (NT0 + 3*NT1 n-tiles).
template <int NOUT, int K, int LDA, int AOFF, int ACT>
__global__ __launch_bounds__(768, 1) void k_mlp(const float* __restrict__ A,
                                                const float* __restrict__ W,
                                                const float* __restrict__ bias,
                                                float* __restrict__ C) {
    constexpr int NP = (NOUT + 7) & ~7;
    constexpr int NT = NP / 8;
    constexpr int NT1 = NT / 4;
    constexpr int NT0 = NT - 3 * NT1;
    constexpr int KC = (K + 15) / 16;
    constexpr int KP = KC * 16;
    constexpr int KS = KP + 8;

    extern __shared__ char smraw[];
    __nv_bfloat16* sh = reinterpret_cast<__nv_bfloat16*>(smraw);
    __nv_bfloat16* sl = sh + NP * KS;
    float* bias_s = reinterpret_cast<float*>(sl + NP * KS);

    int tid = threadIdx.x;
    int lane = tid & 31, warp = tid >> 5;

    for (int idx = tid; idx < NP * KP; idx += 768) {
        int n = idx / KP, k = idx % KP;
        float v = (n < NOUT && k < K) ? W[n * K + k] : 0.0f;
        __nv_bfloat16 h = __float2bfloat16(v);
        float lo = v - __bfloat162float(h);
        sh[n * KS + k] = h;
        sl[n * KS + k] = __float2bfloat16(lo);
    }
    for (int i = tid; i < NP; i += 768) bias_s[i] = (i < NOUT) ? bias[i] : 0.0f;
    __syncthreads();

    const int sub = warp & 3;
    const int gp = blockIdx.x * 6 + (warp >> 2);
    const int gstride = gridDim.x * 6;
    if (sub == 0)
        mlp_body<NOUT, K, LDA, AOFF, ACT, NT0>(A, C, sh, sl, bias_s, lane, gp, gstride, 0);
    else
        mlp_body<NOUT, K, LDA, AOFF, ACT, NT1>(A, C, sh, sl, bias_s, lane, gp, gstride,
                                               (NT0 + (sub - 1) * NT1) * 8);
}

// ---------------- denominator mu constant ----------------
__global__ void k_denmu(const float* __restrict__ mu) {
    int tid = threadIdx.x;
    __shared__ float S[10];
    if (tid < 10) {
        float s = 0.f;
        for (int t = 0; t < 65; t++) s += mu[t * 10 + tid];
        S[tid] = s * s;
    }
    __syncthreads();
    if (tid == 0) {
        float d = 0.f;
        for (int m = 0; m < 10; m++) d += S[m];
        g_denmu = d;
    }
}

// ---------------- bilinear grid sample ----------------
__global__ void k_gridsample(const float* __restrict__ img, const float* __restrict__ zern) {
    int p = blockIdx.x * blockDim.x + threadIdx.x;
    if (p >= NPIX) return;
    int y = p >> 8, x = p & 255;
    float px = zern[p * 35 + 0], py = zern[p * 35 + 1];
    float fx = 2.0f * ((float)x + px) / 255.0f - 1.0f;
    float fy = 2.0f * ((float)y + py) / 255.0f - 1.0f;
    float ix = ((fx + 1.0f) * 256.0f - 1.0f) * 0.5f;
    float iy = ((fy + 1.0f) * 256.0f - 1.0f) * 0.5f;
    ix = fminf(fmaxf(ix, 0.f), 255.f);
    iy = fminf(fmaxf(iy, 0.f), 255.f);
    float x0f = floorf(ix), y0f = floorf(iy);
    float wx = ix - x0f, wy = iy - y0f;
    int x0 = (int)x0f, y0 = (int)y0f;
    int x1 = min(x0 + 1, 255), y1 = min(y0 + 1, 255);
#pragma unroll
    for (int c = 0; c < 3; c++) {
        const float* im = img + c * NPIX;
        float g00 = im[y0 * 256 + x0], g01 = im[y0 * 256 + x1];
        float g10 = im[y1 * 256 + x0], g11 = im[y1 * 256 + x1];
        float top = g00 * (1.f - wx) + g01 * wx;
        float bot = g10 * (1.f - wx) + g11 * wx;
        g_tilt[c * NPIX + p] = top * (1.f - wy) + bot * wy;
    }
}

// ---------------- vertical pass: 2 outputs (h, h+1) per thread ----------------
__global__ __launch_bounds__(128) void k_vert(const float* __restrict__ basis_left) {
    extern __shared__ float smv[];
    float* coefE = smv;
    float* coefO = smv + 128 * 102;
    float* tiltS = coefO + 128 * 102;
    float* Lsm = tiltS + 3 * 257;
    int w = blockIdx.x, tid = threadIdx.x;
    for (int i = tid; i < 650; i += 128) Lsm[i] = basis_left[i];
    for (int li = tid; li < 6400; li += 128) {
        int hh = li / 25, q = li % 25;
        float4 v = *(const float4*)&g_coef[(size_t)(hh * 256 + w) * 100 + q * 4];
        float* dst = ((hh & 1) ? coefO : coefE) + (hh >> 1) * 102 + q * 4;
        dst[0] = v.x; dst[1] = v.y; dst[2] = v.z; dst[3] = v.w;
    }
    for (int li = tid; li < 768; li += 128) {
        int k = li >> 8, hh = li & 255;
        tiltS[k * 257 + hh] = g_tilt[k * NPIX + hh * 256 + w];
    }
    __syncthreads();

    const int h1 = 2 * tid;
    float acc1[40], acc2[40];
#pragma unroll
    for (int p = 0; p < 40; p++) { acc1[p] = 0.f; acc2[p] = 0.f; }

#pragma unroll 2
    for (int ro = -32; ro <= 33; ro++) {
        int r = h1 + ro;
        r = (r < 0) ? -r : ((r > 255) ? 510 - r : r);
        int t1 = ro + 32, t2 = ro + 31;
        bool va = (t1 <= 64), vb = (t2 >= 0);
        int t1c = va ? t1 : 64, t2c = vb ? t2 : 0;
        const float* crow = ((r & 1) ? coefO : coefE) + (r >> 1) * 102;
        float s1[10], s2[10];
#pragma unroll
        for (int j = 0; j < 10; j++) { s1[j] = 0.f; s2[j] = 0.f; }
#pragma unroll
        for (int i = 0; i < 10; i++) {
            float L1 = va ? Lsm[t1c * 10 + i] : 0.f;
            float L2 = vb ? Lsm[t2c * 10 + i] : 0.f;
#pragma unroll
            for (int u = 0; u < 5; u++) {
                float2 cc = *(const float2*)&crow[i * 10 + 2 * u];
                s1[2 * u]     += L1 * cc.x;
                s1[2 * u + 1] += L1 * cc.y;
                s2[2 * u]     += L2 * cc.x;
                s2[2 * u + 1] += L2 * cc.y;
            }
        }
        float T0 = tiltS[r], T1 = tiltS[257 + r], T2 = tiltS[514 + r];
#pragma unroll
        for (int j = 0; j < 10; j++) {
            acc1[j]      += T0 * s1[j];
            acc1[10 + j] += T1 * s1[j];
            acc1[20 + j] += T2 * s1[j];
            acc1[30 + j] += s1[j];
            acc2[j]      += T0 * s2[j];
            acc2[10 + j] += T1 * s2[j];
            acc2[20 + j] += T2 * s2[j];
            acc2[30 + j] += s2[j];
        }
    }
#pragma unroll
    for (int p = 0; p < 40; p++) {
        g_A[p * NPIX + h1 * 256 + w] = acc1[p];
        g_A[p * NPIX + (h1 + 1) * 256 + w] = acc2[p];
    }
}

// ---------------- vertical mu pass ----------------
__global__ void k_vmu(const float* __restrict__ mu) {
    __shared__ float tiltS[3 * 257];
    __shared__ float Msm[650];
    int w = blockIdx.x, tid = threadIdx.x;
    for (int i = tid; i < 650; i += 256) Msm[i] = mu[i];
    for (int li = tid; li < 768; li += 256) {
        int k = li >> 8, hh = li & 255;
        tiltS[k * 257 + hh] = g_tilt[k * NPIX + hh * 256 + w];
    }
    __syncthreads();
    int h = tid;
    float acc[30];
#pragma unroll
    for (int q = 0; q < 30; q++) acc[q] = 0.f;
    for (int t = 0; t < 65; t++) {
        int r = h + t - 32;
        r = (r < 0) ? -r : ((r > 255) ? 510 - r : r);
        float t0 = tiltS[r], t1 = tiltS[257 + r], t2 = tiltS[514 + r];
#pragma unroll
        for (int m = 0; m < 10; m++) {
            float mv = Msm[t * 10 + m];
            acc[m] += mv * t0;
            acc[10 + m] += mv * t1;
            acc[20 + m] += mv * t2;
        }
    }
#pragma unroll
    for (int p = 0; p < 30; p++) g_Bmu[p * NPIX + h * 256 + w] = acc[p];
}

// ---------------- horizontal pass: 2 outputs (w, w+1) per thread ----------------
__global__ __launch_bounds__(128) void k_horiz(const float* __restrict__ basis_right,
                                               const float* __restrict__ mu,
                                               float* __restrict__ out) {
    extern __shared__ float smh[];
    float* P = smh;
    float* Rsm = P + 70 * 258;
    float* Msm = Rsm + 650;
    int h = blockIdx.x, tid = threadIdx.x;
    for (int i = tid; i < 650; i += 128) {
        Rsm[i] = basis_right[i];
        Msm[i] = mu[i];
    }
    for (int p = 0; p < 40; p++)
        for (int c = tid; c < 256; c += 128) P[p * 258 + c] = g_A[p * NPIX + h * 256 + c];
    for (int p = 0; p < 30; p++)
        for (int c = tid; c < 256; c += 128) P[(40 + p) * 258 + c] = g_Bmu[p * NPIX + h * 256 + c];
    __syncthreads();

    const int w0 = 2 * tid;
    float n0a = 0, n0b = 0, n1a = 0, n1b = 0, n2a = 0, n2b = 0, dna = 0, dnb = 0;

    for (int ke = 0; ke <= 64; ke += 2) {
        int c = w0 + ke - 32;
        bool fast = (c >= 0) && (c <= 254);
        int ca = (c < 0) ? -c : ((c > 255) ? 510 - c : c);
        int cd = c + 1;
        int cb = (cd < 0) ? -cd : ((cd > 255) ? 510 - cd : cd);

        float Rm[10], R0[10], Rp[10], Mm[10], M0[10], Mp[10];
#pragma unroll
        for (int j = 0; j < 10; j++) {
            R0[j] = Rsm[ke * 10 + j];
            M0[j] = Msm[ke * 10 + j];
            Rp[j] = (ke < 64) ? Rsm[(ke + 1) * 10 + j] : 0.f;
            Mp[j] = (ke < 64) ? Msm[(ke + 1) * 10 + j] : 0.f;
            Rm[j] = (ke > 0) ? Rsm[(ke - 1) * 10 + j] : 0.f;
            Mm[j] = (ke > 0) ? Msm[(ke - 1) * 10 + j] : 0.f;
        }
#pragma unroll
        for (int j = 0; j < 10; j++) {
            float2 g;
#define LOADP(p) (fast ? *(const float2*)&P[(p) * 258 + c] \
                       : make_float2(P[(p) * 258 + ca], P[(p) * 258 + cb]))
            g = LOADP(j);
            n0a += R0[j] * g.x + Rp[j] * g.y;  n0b += Rm[j] * g.x + R0[j] * g.y;
            g = LOADP(10 + j);
            n1a += R0[j] * g.x + Rp[j] * g.y;  n1b += Rm[j] * g.x + R0[j] * g.y;
            g = LOADP(20 + j);
            n2a += R0[j] * g.x + Rp[j] * g.y;  n2b += Rm[j] * g.x + R0[j] * g.y;
            g = LOADP(30 + j);
            dna += R0[j] * g.x + Rp[j] * g.y;  dnb += Rm[j] * g.x + R0[j] * g.y;
            g = LOADP(40 + j);
            n0a += M0[j] * g.x + Mp[j] * g.y;  n0b += Mm[j] * g.x + M0[j] * g.y;
            g = LOADP(50 + j);
            n1a += M0[j] * g.x + Mp[j] * g.y;  n1b += Mm[j] * g.x + M0[j] * g.y;
            g = LOADP(60 + j);
            n2a += M0[j] * g.x + Mp[j] * g.y;  n2b += Mm[j] * g.x + M0[j] * g.y;
#undef LOADP
        }
    }
    float dmu = g_denmu;
    dna += dmu;
    dnb += dmu;
    size_t base = (size_t)h * 256 + w0;
    *reinterpret_cast<float2*>(&out[0 * NPIX + base]) = make_float2(n0a / dna, n0b / dnb);
    *reinterpret_cast<float2*>(&out[1 * NPIX + base]) = make_float2(n1a / dna, n1b / dnb);
    *reinterpret_cast<float2*>(&out[2 * NPIX + base]) = make_float2(n2a / dna, n2b / dnb);
}

// ---------------- launcher ----------------
extern "C" void kernel_launch(void* const* d_in, const int* in_sizes, int n_in,
                              void* d_out, int out_size) {
    const float* img  = (const float*)d_in[0];
    const float* zern = (const float*)d_in[1];
    const float* fc1w = (const float*)d_in[2];
    const float* fc1b = (const float*)d_in[3];
    const float* fc2w = (const float*)d_in[4];
    const float* fc2b = (const float*)d_in[5];
    const float* fc3w = (const float*)d_in[6];
    const float* fc3b = (const float*)d_in[7];
    const float* bl   = (const float*)d_in[8];
    const float* br   = (const float*)d_in[9];
    const float* mu   = (const float*)d_in[10];
    float* out = (float*)d_out;

    auto l1 = k_mlp<200, 33, 35, 2, 1>;
    auto l2 = k_mlp<200, 200, 200, 0, 1>;
    auto l3 = k_mlp<100, 200, 200, 0, 0>;
    cudaFuncSetAttribute(l1, cudaFuncAttributeMaxDynamicSharedMemorySize, 45600);
    cudaFuncSetAttribute(l2, cudaFuncAttributeMaxDynamicSharedMemorySize, 173600);
    cudaFuncSetAttribute(l3, cudaFuncAttributeMaxDynamicSharedMemorySize, 90272);
    cudaFuncSetAttribute(k_vert, cudaFuncAttributeMaxDynamicSharedMemorySize, 110132);
    cudaFuncSetAttribute(k_horiz, cudaFuncAttributeMaxDynamicSharedMemorySize, 77440);

    float *h1, *h2, *coef;
    cudaGetSymbolAddress((void**)&h1, g_h1);
    cudaGetSymbolAddress((void**)&h2, g_h2);
    cudaGetSymbolAddress((void**)&coef, g_coef);

    k_denmu<<<1, 64>>>(mu);
    k_gridsample<<<256, 256>>>(img, zern);
    l1<<<148, 768, 45600>>>(zern, fc1w, fc1b, h1);
    l2<<<148, 768, 173600>>>(h1, fc2w, fc2b, h2);
    l3<<<148, 768, 90272>>>(h2, fc3w, fc3b, coef);
    k_vert<<<256, 128, 110132>>>(bl);
    k_vmu<<<256, 256>>>(mu);
    k_horiz<<<256, 128, 77440>>>(br, mu, out);
}

// round 8
// speedup vs baseline: 1.0784x; 1.0784x over previous
#include <cuda_runtime.h>
#include <cuda_fp16.h>
#include <cstdint>

#define NPIX 65536

// ---------------- scratch (device globals; no allocation) ----------------
__device__ float g_tilt[3 * NPIX];
__device__ float g_h1[(size_t)NPIX * 200];
__device__ float g_h2[(size_t)NPIX * 200];
__device__ float g_coef[(size_t)NPIX * 100];
__device__ float g_A[40 * NPIX];
__device__ float g_Bmu[30 * NPIX];
__device__ float g_denmu;

// ---------------- warp-mma helpers ----------------
__device__ __forceinline__ void mma_f16(float* c, uint32_t a0, uint32_t a1, uint32_t a2,
                                        uint32_t a3, uint32_t b0, uint32_t b1) {
    asm volatile(
        "mma.sync.aligned.m16n8k16.row.col.f32.f16.f16.f32 "
        "{%0,%1,%2,%3}, {%4,%5,%6,%7}, {%8,%9}, {%0,%1,%2,%3};"
        : "+f"(c[0]), "+f"(c[1]), "+f"(c[2]), "+f"(c[3])
        : "r"(a0), "r"(a1), "r"(a2), "r"(a3), "r"(b0), "r"(b1));
}
__device__ __forceinline__ uint32_t pack_h2(float a, float b) {
    __half2 t;
    t.x = __float2half(a);
    t.y = __float2half(b);
    return *reinterpret_cast<uint32_t*>(&t);
}

// ---------------- per-warp MLP body over an N-subrange ----------------
// fp16 2-pass: A split hi/lo in registers, W single fp16 copy in smem.
template <int NOUT, int K, int LDA, int AOFF, int ACT, int NTH>
__device__ __forceinline__ void mlp_body(const float* __restrict__ A, float* __restrict__ C,
                                         const __half* sh, const float* bias_s,
                                         int lane, int gp, int gstride, int noff) {
    constexpr int KC = (K + 15) / 16;
    constexpr int KP = KC * 16;
    constexpr int KS = KP + 8;   // conflict-free row stride
    constexpr bool VEC = (LDA % 2 == 0) && (AOFF % 2 == 0);
    const int k0 = (lane & 3) * 2;
    const int nrow = lane >> 2;

    for (int wt = gp; wt < 4096; wt += gstride) {
        int row0 = wt * 16 + nrow;
        int row1 = row0 + 8;
        const float* ar0 = A + (size_t)row0 * LDA + AOFF;
        const float* ar1 = A + (size_t)row1 * LDA + AOFF;

        float acc[NTH][4];
#pragma unroll
        for (int nt = 0; nt < NTH; nt++)
#pragma unroll
            for (int q = 0; q < 4; q++) acc[nt][q] = 0.0f;

#pragma unroll
        for (int kc = 0; kc < KC; kc++) {
            int kb = kc * 16 + k0;
            float x00, x01, x02, x03, x10, x11, x12, x13;
            if (VEC) {
                float2 p0 = (kb + 1 < K) ? *(const float2*)(ar0 + kb)
                                         : make_float2(kb < K ? ar0[kb] : 0.f, 0.f);
                float2 p1 = (kb + 1 < K) ? *(const float2*)(ar1 + kb)
                                         : make_float2(kb < K ? ar1[kb] : 0.f, 0.f);
                float2 p2 = (kb + 9 < K) ? *(const float2*)(ar0 + kb + 8)
                                         : make_float2(kb + 8 < K ? ar0[kb + 8] : 0.f, 0.f);
                float2 p3 = (kb + 9 < K) ? *(const float2*)(ar1 + kb + 8)
                                         : make_float2(kb + 8 < K ? ar1[kb + 8] : 0.f, 0.f);
                x00 = p0.x; x01 = p0.y; x10 = p1.x; x11 = p1.y;
                x02 = p2.x; x03 = p2.y; x12 = p3.x; x13 = p3.y;
            } else {
                x00 = (kb < K) ? ar0[kb] : 0.f;
                x01 = (kb + 1 < K) ? ar0[kb + 1] : 0.f;
                x10 = (kb < K) ? ar1[kb] : 0.f;
                x11 = (kb + 1 < K) ? ar1[kb + 1] : 0.f;
                x02 = (kb + 8 < K) ? ar0[kb + 8] : 0.f;
                x03 = (kb + 9 < K) ? ar0[kb + 9] : 0.f;
                x12 = (kb + 8 < K) ? ar1[kb + 8] : 0.f;
                x13 = (kb + 9 < K) ? ar1[kb + 9] : 0.f;
            }
            uint32_t ah0 = pack_h2(x00, x01);
            uint32_t ah1 = pack_h2(x10, x11);
            uint32_t ah2 = pack_h2(x02, x03);
            uint32_t ah3 = pack_h2(x12, x13);
            float r00 = x00 - __half2float(__float2half(x00));
            float r01 = x01 - __half2float(__float2half(x01));
            float r10 = x10 - __half2float(__float2half(x10));
            float r11 = x11 - __half2float(__float2half(x11));
            float r02 = x02 - __half2float(__float2half(x02));
            float r03 = x03 - __half2float(__float2half(x03));
            float r12 = x12 - __half2float(__float2half(x12));
            float r13 = x13 - __half2float(__float2half(x13));
            uint32_t al0 = pack_h2(r00, r01);
            uint32_t al1 = pack_h2(r10, r11);
            uint32_t al2 = pack_h2(r02, r03);
            uint32_t al3 = pack_h2(r12, r13);

#pragma unroll
            for (int nt = 0; nt < NTH; nt++) {
                int n = noff + nt * 8 + nrow;
                const __half* ph = sh + n * KS + kc * 16 + k0;
                uint32_t bh0 = *reinterpret_cast<const uint32_t*>(ph);
                uint32_t bh1 = *reinterpret_cast<const uint32_t*>(ph + 8);
                mma_f16(acc[nt], ah0, ah1, ah2, ah3, bh0, bh1);
                mma_f16(acc[nt], al0, al1, al2, al3, bh0, bh1);
            }
        }

        float* c0 = C + (size_t)row0 * NOUT;
        float* c1 = C + (size_t)row1 * NOUT;
#pragma unroll
        for (int nt = 0; nt < NTH; nt++) {
            int cc = noff + nt * 8 + k0;
            if (cc < NOUT) {
                float b0v = bias_s[cc], b1v = bias_s[cc + 1];
                float v0 = acc[nt][0] + b0v, v1 = acc[nt][1] + b1v;
                float v2 = acc[nt][2] + b0v, v3 = acc[nt][3] + b1v;
                if (ACT) {
                    v0 = v0 > 0.f ? v0 : 0.01f * v0;
                    v1 = v1 > 0.f ? v1 : 0.01f * v1;
                    v2 = v2 > 0.f ? v2 : 0.01f * v2;
                    v3 = v3 > 0.f ? v3 : 0.01f * v3;
                }
                *reinterpret_cast<float2*>(c0 + cc) = make_float2(v0, v1);
                *reinterpret_cast<float2*>(c1 + cc) = make_float2(v2, v3);
            }
        }
    }
}

// ================= fp16 2-pass warp-mma MLP layer =================
// 512 threads = 16 warps = 8 warp pairs; pair shares a 16-row M-tile, halves split N.
template <int NOUT, int K, int LDA, int AOFF, int ACT>
__global__ __launch_bounds__(512, 1) void k_mlp(const float* __restrict__ A,
                                                const float* __restrict__ W,
                                                const float* __restrict__ bias,
                                                float* __restrict__ C) {
    constexpr int NP = (NOUT + 7) & ~7;
    constexpr int NT = NP / 8;
    constexpr int NT0 = (NT + 1) / 2;
    constexpr int NT1 = NT - NT0;
    constexpr int KC = (K + 15) / 16;
    constexpr int KP = KC * 16;
    constexpr int KS = KP + 8;

    extern __shared__ char smraw[];
    __half* sh = reinterpret_cast<__half*>(smraw);
    float* bias_s = reinterpret_cast<float*>(sh + NP * KS);

    int tid = threadIdx.x;
    int lane = tid & 31, warp = tid >> 5;

    for (int idx = tid; idx < NP * KP; idx += 512) {
        int n = idx / KP, k = idx % KP;
        float v = (n < NOUT && k < K) ? W[n * K + k] : 0.0f;
        sh[n * KS + k] = __float2half(v);
    }
    for (int i = tid; i < NP; i += 512) bias_s[i] = (i < NOUT) ? bias[i] : 0.0f;
    __syncthreads();

    const int gp = blockIdx.x * 8 + (warp >> 1);
    const int gstride = gridDim.x * 8;
    if ((warp & 1) == 0)
        mlp_body<NOUT, K, LDA, AOFF, ACT, NT0>(A, C, sh, bias_s, lane, gp, gstride, 0);
    else
        mlp_body<NOUT, K, LDA, AOFF, ACT, NT1>(A, C, sh, bias_s, lane, gp, gstride, NT0 * 8);
}

// ---------------- denominator mu constant ----------------
__global__ void k_denmu(const float* __restrict__ mu) {
    int tid = threadIdx.x;
    __shared__ float S[10];
    if (tid < 10) {
        float s = 0.f;
        for (int t = 0; t < 65; t++) s += mu[t * 10 + tid];
        S[tid] = s * s;
    }
    __syncthreads();
    if (tid == 0) {
        float d = 0.f;
        for (int m = 0; m < 10; m++) d += S[m];
        g_denmu = d;
    }
}

// ---------------- bilinear grid sample ----------------
__global__ void k_gridsample(const float* __restrict__ img, const float* __restrict__ zern) {
    int p = blockIdx.x * blockDim.x + threadIdx.x;
    if (p >= NPIX) return;
    int y = p >> 8, x = p & 255;
    float px = zern[p * 35 + 0], py = zern[p * 35 + 1];
    float fx = 2.0f * ((float)x + px) / 255.0f - 1.0f;
    float fy = 2.0f * ((float)y + py) / 255.0f - 1.0f;
    float ix = ((fx + 1.0f) * 256.0f - 1.0f) * 0.5f;
    float iy = ((fy + 1.0f) * 256.0f - 1.0f) * 0.5f;
    ix = fminf(fmaxf(ix, 0.f), 255.f);
    iy = fminf(fmaxf(iy, 0.f), 255.f);
    float x0f = floorf(ix), y0f = floorf(iy);
    float wx = ix - x0f, wy = iy - y0f;
    int x0 = (int)x0f, y0 = (int)y0f;
    int x1 = min(x0 + 1, 255), y1 = min(y0 + 1, 255);
#pragma unroll
    for (int c = 0; c < 3; c++) {
        const float* im = img + c * NPIX;
        float g00 = im[y0 * 256 + x0], g01 = im[y0 * 256 + x1];
        float g10 = im[y1 * 256 + x0], g11 = im[y1 * 256 + x1];
        float top = g00 * (1.f - wx) + g01 * wx;
        float bot = g10 * (1.f - wx) + g11 * wx;
        g_tilt[c * NPIX + p] = top * (1.f - wy) + bot * wy;
    }
}

// ---------------- vertical pass: 2 outputs (h, h+1) per thread ----------------
__global__ __launch_bounds__(128) void k_vert(const float* __restrict__ basis_left) {
    extern __shared__ float smv[];
    float* coefE = smv;
    float* coefO = smv + 128 * 102;
    float* tiltS = coefO + 128 * 102;
    float* Lsm = tiltS + 3 * 257;
    int w = blockIdx.x, tid = threadIdx.x;
    for (int i = tid; i < 650; i += 128) Lsm[i] = basis_left[i];
    for (int li = tid; li < 6400; li += 128) {
        int hh = li / 25, q = li % 25;
        float4 v = *(const float4*)&g_coef[(size_t)(hh * 256 + w) * 100 + q * 4];
        float* dst = ((hh & 1) ? coefO : coefE) + (hh >> 1) * 102 + q * 4;
        dst[0] = v.x; dst[1] = v.y; dst[2] = v.z; dst[3] = v.w;
    }
    for (int li = tid; li < 768; li += 128) {
        int k = li >> 8, hh = li & 255;
        tiltS[k * 257 + hh] = g_tilt[k * NPIX + hh * 256 + w];
    }
    __syncthreads();

    const int h1 = 2 * tid;
    float acc1[40], acc2[40];
#pragma unroll
    for (int p = 0; p < 40; p++) { acc1[p] = 0.f; acc2[p] = 0.f; }

#pragma unroll 2
    for (int ro = -32; ro <= 33; ro++) {
        int r = h1 + ro;
        r = (r < 0) ? -r : ((r > 255) ? 510 - r : r);
        int t1 = ro + 32, t2 = ro + 31;
        bool va = (t1 <= 64), vb = (t2 >= 0);
        int t1c = va ? t1 : 64, t2c = vb ? t2 : 0;
        const float* crow = ((r & 1) ? coefO : coefE) + (r >> 1) * 102;
        float s1[10], s2[10];
#pragma unroll
        for (int j = 0; j < 10; j++) { s1[j] = 0.f; s2[j] = 0.f; }
#pragma unroll
        for (int i = 0; i < 10; i++) {
            float L1 = va ? Lsm[t1c * 10 + i] : 0.f;
            float L2 = vb ? Lsm[t2c * 10 + i] : 0.f;
#pragma unroll
            for (int u = 0; u < 5; u++) {
                float2 cc = *(const float2*)&crow[i * 10 + 2 * u];
                s1[2 * u]     += L1 * cc.x;
                s1[2 * u + 1] += L1 * cc.y;
                s2[2 * u]     += L2 * cc.x;
                s2[2 * u + 1] += L2 * cc.y;
            }
        }
        float T0 = tiltS[r], T1 = tiltS[257 + r], T2 = tiltS[514 + r];
#pragma unroll
        for (int j = 0; j < 10; j++) {
            acc1[j]      += T0 * s1[j];
            acc1[10 + j] += T1 * s1[j];
            acc1[20 + j] += T2 * s1[j];
            acc1[30 + j] += s1[j];
            acc2[j]      += T0 * s2[j];
            acc2[10 + j] += T1 * s2[j];
            acc2[20 + j] += T2 * s2[j];
            acc2[30 + j] += s2[j];
        }
    }
#pragma unroll
    for (int p = 0; p < 40; p++) {
        g_A[p * NPIX + h1 * 256 + w] = acc1[p];
        g_A[p * NPIX + (h1 + 1) * 256 + w] = acc2[p];
    }
}

// ---------------- vertical mu pass ----------------
__global__ void k_vmu(const float* __restrict__ mu) {
    __shared__ float tiltS[3 * 257];
    __shared__ float Msm[650];
    int w = blockIdx.x, tid = threadIdx.x;
    for (int i = tid; i < 650; i += 256) Msm[i] = mu[i];
    for (int li = tid; li < 768; li += 256) {
        int k = li >> 8, hh = li & 255;
        tiltS[k * 257 + hh] = g_tilt[k * NPIX + hh * 256 + w];
    }
    __syncthreads();
    int h = tid;
    float acc[30];
#pragma unroll
    for (int q = 0; q < 30; q++) acc[q] = 0.f;
    for (int t = 0; t < 65; t++) {
        int r = h + t - 32;
        r = (r < 0) ? -r : ((r > 255) ? 510 - r : r);
        float t0 = tiltS[r], t1 = tiltS[257 + r], t2 = tiltS[514 + r];
#pragma unroll
        for (int m = 0; m < 10; m++) {
            float mv = Msm[t * 10 + m];
            acc[m] += mv * t0;
            acc[10 + m] += mv * t1;
            acc[20 + m] += mv * t2;
        }
    }
#pragma unroll
    for (int p = 0; p < 30; p++) g_Bmu[p * NPIX + h * 256 + w] = acc[p];
}

// ---------------- horizontal pass: 2 outputs (w, w+1) per thread ----------------
__global__ __launch_bounds__(128) void k_horiz(const float* __restrict__ basis_right,
                                               const float* __restrict__ mu,
                                               float* __restrict__ out) {
    extern __shared__ float smh[];
    float* P = smh;
    float* Rsm = P + 70 * 258;
    float* Msm = Rsm + 650;
    int h = blockIdx.x, tid = threadIdx.x;
    for (int i = tid; i < 650; i += 128) {
        Rsm[i] = basis_right[i];
        Msm[i] = mu[i];
    }
    for (int p = 0; p < 40; p++)
        for (int c = tid; c < 256; c += 128) P[p * 258 + c] = g_A[p * NPIX + h * 256 + c];
    for (int p = 0; p < 30; p++)
        for (int c = tid; c < 256; c += 128) P[(40 + p) * 258 + c] = g_Bmu[p * NPIX + h * 256 + c];
    __syncthreads();

    const int w0 = 2 * tid;
    float n0a = 0, n0b = 0, n1a = 0, n1b = 0, n2a = 0, n2b = 0, dna = 0, dnb = 0;

    for (int ke = 0; ke <= 64; ke += 2) {
        int c = w0 + ke - 32;
        bool fast = (c >= 0) && (c <= 254);
        int ca = (c < 0) ? -c : ((c > 255) ? 510 - c : c);
        int cd = c + 1;
        int cb = (cd < 0) ? -cd : ((cd > 255) ? 510 - cd : cd);

        float Rm[10], R0[10], Rp[10], Mm[10], M0[10], Mp[10];
#pragma unroll
        for (int j = 0; j < 10; j++) {
            R0[j] = Rsm[ke * 10 + j];
            M0[j] = Msm[ke * 10 + j];
            Rp[j] = (ke < 64) ? Rsm[(ke + 1) * 10 + j] : 0.f;
            Mp[j] = (ke < 64) ? Msm[(ke + 1) * 10 + j] : 0.f;
            Rm[j] = (ke > 0) ? Rsm[(ke - 1) * 10 + j] : 0.f;
            Mm[j] = (ke > 0) ? Msm[(ke - 1) * 10 + j] : 0.f;
        }
#pragma unroll
        for (int j = 0; j < 10; j++) {
            float2 g;
#define LOADP(p) (fast ? *(const float2*)&P[(p) * 258 + c] \
                       : make_float2(P[(p) * 258 + ca], P[(p) * 258 + cb]))
            g = LOADP(j);
            n0a += R0[j] * g.x + Rp[j] * g.y;  n0b += Rm[j] * g.x + R0[j] * g.y;
            g = LOADP(10 + j);
            n1a += R0[j] * g.x + Rp[j] * g.y;  n1b += Rm[j] * g.x + R0[j] * g.y;
            g = LOADP(20 + j);
            n2a += R0[j] * g.x + Rp[j] * g.y;  n2b += Rm[j] * g.x + R0[j] * g.y;
            g = LOADP(30 + j);
            dna += R0[j] * g.x + Rp[j] * g.y;  dnb += Rm[j] * g.x + R0[j] * g.y;
            g = LOADP(40 + j);
            n0a += M0[j] * g.x + Mp[j] * g.y;  n0b += Mm[j] * g.x + M0[j] * g.y;
            g = LOADP(50 + j);
            n1a += M0[j] * g.x + Mp[j] * g.y;  n1b += Mm[j] * g.x + M0[j] * g.y;
            g = LOADP(60 + j);
            n2a += M0[j] * g.x + Mp[j] * g.y;  n2b += Mm[j] * g.x + M0[j] * g.y;
#undef LOADP
        }
    }
    float dmu = g_denmu;
    dna += dmu;
    dnb += dmu;
    size_t base = (size_t)h * 256 + w0;
    *reinterpret_cast<float2*>(&out[0 * NPIX + base]) = make_float2(n0a / dna, n0b / dnb);
    *reinterpret_cast<float2*>(&out[1 * NPIX + base]) = make_float2(n1a / dna, n1b / dnb);
    *reinterpret_cast<float2*>(&out[2 * NPIX + base]) = make_float2(n2a / dna, n2b / dnb);
}

// ---------------- launcher ----------------
extern "C" void kernel_launch(void* const* d_in, const int* in_sizes, int n_in,
                              void* d_out, int out_size) {
    const float* img  = (const float*)d_in[0];
    const float* zern = (const float*)d_in[1];
    const float* fc1w = (const float*)d_in[2];
    const float* fc1b = (const float*)d_in[3];
    const float* fc2w = (const float*)d_in[4];
    const float* fc2b = (const float*)d_in[5];
    const float* fc3w = (const float*)d_in[6];
    const float* fc3b = (const float*)d_in[7];
    const float* bl   = (const float*)d_in[8];
    const float* br   = (const float*)d_in[9];
    const float* mu   = (const float*)d_in[10];
    float* out = (float*)d_out;

    auto l1 = k_mlp<200, 33, 35, 2, 1>;
    auto l2 = k_mlp<200, 200, 200, 0, 1>;
    auto l3 = k_mlp<100, 200, 200, 0, 0>;
    // smem: NP*KS*2B + NP*4B
    // l1: 200*56*2 + 800 = 23200
    // l2: 200*216*2 + 800 = 87200
    // l3: 104*216*2 + 416 = 45344
    cudaFuncSetAttribute(l1, cudaFuncAttributeMaxDynamicSharedMemorySize, 23200);
    cudaFuncSetAttribute(l2, cudaFuncAttributeMaxDynamicSharedMemorySize, 87200);
    cudaFuncSetAttribute(l3, cudaFuncAttributeMaxDynamicSharedMemorySize, 45344);
    cudaFuncSetAttribute(k_vert, cudaFuncAttributeMaxDynamicSharedMemorySize, 110132);
    cudaFuncSetAttribute(k_horiz, cudaFuncAttributeMaxDynamicSharedMemorySize, 77440);

    float *h1, *h2, *coef;
    cudaGetSymbolAddress((void**)&h1, g_h1);
    cudaGetSymbolAddress((void**)&h2, g_h2);
    cudaGetSymbolAddress((void**)&coef, g_coef);

    k_denmu<<<1, 64>>>(mu);
    k_gridsample<<<256, 256>>>(img, zern);
    l1<<<148, 512, 23200>>>(zern, fc1w, fc1b, h1);
    l2<<<148, 512, 87200>>>(h1, fc2w, fc2b, h2);
    l3<<<148, 512, 45344>>>(h2, fc3w, fc3b, coef);
    k_vert<<<256, 128, 110132>>>(bl);
    k_vmu<<<256, 256>>>(mu);
    k_horiz<<<256, 128, 77440>>>(br, mu, out);
}

// round 9
// speedup vs baseline: 1.1182x; 1.0369x over previous
#include <cuda_runtime.h>
#include <cuda_fp16.h>
#include <cstdint>

#define NPIX 65536

// ---------------- scratch (device globals; no allocation) ----------------
__device__ float g_tilt[3 * NPIX];
__device__ float g_h1[(size_t)NPIX * 200];
__device__ float g_h2[(size_t)NPIX * 200];
__device__ float g_coef[(size_t)NPIX * 100];
__device__ float g_A[40 * NPIX];
__device__ float g_Bmu[30 * NPIX];
__device__ float g_denmu;

// ---------------- warp-mma helpers ----------------
__device__ __forceinline__ void mma_f16(float* c, uint32_t a0, uint32_t a1, uint32_t a2,
                                        uint32_t a3, uint32_t b0, uint32_t b1) {
    asm volatile(
        "mma.sync.aligned.m16n8k16.row.col.f32.f16.f16.f32 "
        "{%0,%1,%2,%3}, {%4,%5,%6,%7}, {%8,%9}, {%0,%1,%2,%3};"
        : "+f"(c[0]), "+f"(c[1]), "+f"(c[2]), "+f"(c[3])
        : "r"(a0), "r"(a1), "r"(a2), "r"(a3), "r"(b0), "r"(b1));
}
__device__ __forceinline__ uint32_t pack_h2(float a, float b) {
    __half2 t;
    t.x = __float2half(a);
    t.y = __float2half(b);
    return *reinterpret_cast<uint32_t*>(&t);
}

// ---------------- per-warp MLP body over an N-subrange ----------------
// single-pass fp16: A converted in registers, W single fp16 copy in smem.
template <int NOUT, int K, int LDA, int AOFF, int ACT, int NTH>
__device__ __forceinline__ void mlp_body(const float* __restrict__ A, float* __restrict__ C,
                                         const __half* sh, const float* bias_s,
                                         int lane, int gp, int gstride, int noff) {
    constexpr int KC = (K + 15) / 16;
    constexpr int KP = KC * 16;
    constexpr int KS = KP + 8;   // conflict-free row stride
    constexpr bool VEC = (LDA % 2 == 0) && (AOFF % 2 == 0);
    const int k0 = (lane & 3) * 2;
    const int nrow = lane >> 2;

    for (int wt = gp; wt < 4096; wt += gstride) {
        int row0 = wt * 16 + nrow;
        int row1 = row0 + 8;
        const float* ar0 = A + (size_t)row0 * LDA + AOFF;
        const float* ar1 = A + (size_t)row1 * LDA + AOFF;

        float acc[NTH][4];
#pragma unroll
        for (int nt = 0; nt < NTH; nt++)
#pragma unroll
            for (int q = 0; q < 4; q++) acc[nt][q] = 0.0f;

#pragma unroll
        for (int kc = 0; kc < KC; kc++) {
            int kb = kc * 16 + k0;
            float x00, x01, x02, x03, x10, x11, x12, x13;
            if (VEC) {
                float2 p0 = (kb + 1 < K) ? *(const float2*)(ar0 + kb)
                                         : make_float2(kb < K ? ar0[kb] : 0.f, 0.f);
                float2 p1 = (kb + 1 < K) ? *(const float2*)(ar1 + kb)
                                         : make_float2(kb < K ? ar1[kb] : 0.f, 0.f);
                float2 p2 = (kb + 9 < K) ? *(const float2*)(ar0 + kb + 8)
                                         : make_float2(kb + 8 < K ? ar0[kb + 8] : 0.f, 0.f);
                float2 p3 = (kb + 9 < K) ? *(const float2*)(ar1 + kb + 8)
                                         : make_float2(kb + 8 < K ? ar1[kb + 8] : 0.f, 0.f);
                x00 = p0.x; x01 = p0.y; x10 = p1.x; x11 = p1.y;
                x02 = p2.x; x03 = p2.y; x12 = p3.x; x13 = p3.y;
            } else {
                x00 = (kb < K) ? ar0[kb] : 0.f;
                x01 = (kb + 1 < K) ? ar0[kb + 1] : 0.f;
                x10 = (kb < K) ? ar1[kb] : 0.f;
                x11 = (kb + 1 < K) ? ar1[kb + 1] : 0.f;
                x02 = (kb + 8 < K) ? ar0[kb + 8] : 0.f;
                x03 = (kb + 9 < K) ? ar0[kb + 9] : 0.f;
                x12 = (kb + 8 < K) ? ar1[kb + 8] : 0.f;
                x13 = (kb + 9 < K) ? ar1[kb + 9] : 0.f;
            }
            uint32_t ah0 = pack_h2(x00, x01);
            uint32_t ah1 = pack_h2(x10, x11);
            uint32_t ah2 = pack_h2(x02, x03);
            uint32_t ah3 = pack_h2(x12, x13);

#pragma unroll
            for (int nt = 0; nt < NTH; nt++) {
                int n = noff + nt * 8 + nrow;
                const __half* ph = sh + n * KS + kc * 16 + k0;
                uint32_t bh0 = *reinterpret_cast<const uint32_t*>(ph);
                uint32_t bh1 = *reinterpret_cast<const uint32_t*>(ph + 8);
                mma_f16(acc[nt], ah0, ah1, ah2, ah3, bh0, bh1);
            }
        }

        float* c0 = C + (size_t)row0 * NOUT;
        float* c1 = C + (size_t)row1 * NOUT;
#pragma unroll
        for (int nt = 0; nt < NTH; nt++) {
            int cc = noff + nt * 8 + k0;
            if (cc < NOUT) {
                float b0v = bias_s[cc], b1v = bias_s[cc + 1];
                float v0 = acc[nt][0] + b0v, v1 = acc[nt][1] + b1v;
                float v2 = acc[nt][2] + b0v, v3 = acc[nt][3] + b1v;
                if (ACT) {
                    v0 = v0 > 0.f ? v0 : 0.01f * v0;
                    v1 = v1 > 0.f ? v1 : 0.01f * v1;
                    v2 = v2 > 0.f ? v2 : 0.01f * v2;
                    v3 = v3 > 0.f ? v3 : 0.01f * v3;
                }
                *reinterpret_cast<float2*>(c0 + cc) = make_float2(v0, v1);
                *reinterpret_cast<float2*>(c1 + cc) = make_float2(v2, v3);
            }
        }
    }
}

// ================= single-pass fp16 warp-mma MLP layer =================
// 512 threads = 16 warps = 8 warp pairs; pair shares a 16-row M-tile, halves split N.
template <int NOUT, int K, int LDA, int AOFF, int ACT>
__global__ __launch_bounds__(512, 1) void k_mlp(const float* __restrict__ A,
                                                const float* __restrict__ W,
                                                const float* __restrict__ bias,
                                                float* __restrict__ C) {
    constexpr int NP = (NOUT + 7) & ~7;
    constexpr int NT = NP / 8;
    constexpr int NT0 = (NT + 1) / 2;
    constexpr int NT1 = NT - NT0;
    constexpr int KC = (K + 15) / 16;
    constexpr int KP = KC * 16;
    constexpr int KS = KP + 8;

    extern __shared__ char smraw[];
    __half* sh = reinterpret_cast<__half*>(smraw);
    float* bias_s = reinterpret_cast<float*>(sh + NP * KS);

    int tid = threadIdx.x;
    int lane = tid & 31, warp = tid >> 5;

    for (int idx = tid; idx < NP * KP; idx += 512) {
        int n = idx / KP, k = idx % KP;
        float v = (n < NOUT && k < K) ? W[n * K + k] : 0.0f;
        sh[n * KS + k] = __float2half(v);
    }
    for (int i = tid; i < NP; i += 512) bias_s[i] = (i < NOUT) ? bias[i] : 0.0f;
    __syncthreads();

    const int gp = blockIdx.x * 8 + (warp >> 1);
    const int gstride = gridDim.x * 8;
    if ((warp & 1) == 0)
        mlp_body<NOUT, K, LDA, AOFF, ACT, NT0>(A, C, sh, bias_s, lane, gp, gstride, 0);
    else
        mlp_body<NOUT, K, LDA, AOFF, ACT, NT1>(A, C, sh, bias_s, lane, gp, gstride, NT0 * 8);
}

// ---------------- denominator mu constant ----------------
__global__ void k_denmu(const float* __restrict__ mu) {
    int tid = threadIdx.x;
    __shared__ float S[10];
    if (tid < 10) {
        float s = 0.f;
        for (int t = 0; t < 65; t++) s += mu[t * 10 + tid];
        S[tid] = s * s;
    }
    __syncthreads();
    if (tid == 0) {
        float d = 0.f;
        for (int m = 0; m < 10; m++) d += S[m];
        g_denmu = d;
    }
}

// ---------------- bilinear grid sample ----------------
__global__ void k_gridsample(const float* __restrict__ img, const float* __restrict__ zern) {
    int p = blockIdx.x * blockDim.x + threadIdx.x;
    if (p >= NPIX) return;
    int y = p >> 8, x = p & 255;
    float px = zern[p * 35 + 0], py = zern[p * 35 + 1];
    float fx = 2.0f * ((float)x + px) / 255.0f - 1.0f;
    float fy = 2.0f * ((float)y + py) / 255.0f - 1.0f;
    float ix = ((fx + 1.0f) * 256.0f - 1.0f) * 0.5f;
    float iy = ((fy + 1.0f) * 256.0f - 1.0f) * 0.5f;
    ix = fminf(fmaxf(ix, 0.f), 255.f);
    iy = fminf(fmaxf(iy, 0.f), 255.f);
    float x0f = floorf(ix), y0f = floorf(iy);
    float wx = ix - x0f, wy = iy - y0f;
    int x0 = (int)x0f, y0 = (int)y0f;
    int x1 = min(x0 + 1, 255), y1 = min(y0 + 1, 255);
#pragma unroll
    for (int c = 0; c < 3; c++) {
        const float* im = img + c * NPIX;
        float g00 = im[y0 * 256 + x0], g01 = im[y0 * 256 + x1];
        float g10 = im[y1 * 256 + x0], g11 = im[y1 * 256 + x1];
        float top = g00 * (1.f - wx) + g01 * wx;
        float bot = g10 * (1.f - wx) + g11 * wx;
        g_tilt[c * NPIX + p] = top * (1.f - wy) + bot * wy;
    }
}

// ---------------- vertical pass: 2 outputs (h, h+1) per thread ----------------
__global__ __launch_bounds__(128) void k_vert(const float* __restrict__ basis_left) {
    extern __shared__ float smv[];
    float* coefE = smv;
    float* coefO = smv + 128 * 102;
    float* tiltS = coefO + 128 * 102;
    float* Lsm = tiltS + 3 * 257;
    int w = blockIdx.x, tid = threadIdx.x;
    for (int i = tid; i < 650; i += 128) Lsm[i] = basis_left[i];
    for (int li = tid; li < 6400; li += 128) {
        int hh = li / 25, q = li % 25;
        float4 v = *(const float4*)&g_coef[(size_t)(hh * 256 + w) * 100 + q * 4];
        float* dst = ((hh & 1) ? coefO : coefE) + (hh >> 1) * 102 + q * 4;
        dst[0] = v.x; dst[1] = v.y; dst[2] = v.z; dst[3] = v.w;
    }
    for (int li = tid; li < 768; li += 128) {
        int k = li >> 8, hh = li & 255;
        tiltS[k * 257 + hh] = g_tilt[k * NPIX + hh * 256 + w];
    }
    __syncthreads();

    const int h1 = 2 * tid;
    float acc1[40], acc2[40];
#pragma unroll
    for (int p = 0; p < 40; p++) { acc1[p] = 0.f; acc2[p] = 0.f; }

#pragma unroll 2
    for (int ro = -32; ro <= 33; ro++) {
        int r = h1 + ro;
        r = (r < 0) ? -r : ((r > 255) ? 510 - r : r);
        int t1 = ro + 32, t2 = ro + 31;
        bool va = (t1 <= 64), vb = (t2 >= 0);
        int t1c = va ? t1 : 64, t2c = vb ? t2 : 0;
        const float* crow = ((r & 1) ? coefO : coefE) + (r >> 1) * 102;
        float s1[10], s2[10];
#pragma unroll
        for (int j = 0; j < 10; j++) { s1[j] = 0.f; s2[j] = 0.f; }
#pragma unroll
        for (int i = 0; i < 10; i++) {
            float L1 = va ? Lsm[t1c * 10 + i] : 0.f;
            float L2 = vb ? Lsm[t2c * 10 + i] : 0.f;
#pragma unroll
            for (int u = 0; u < 5; u++) {
                float2 cc = *(const float2*)&crow[i * 10 + 2 * u];
                s1[2 * u]     += L1 * cc.x;
                s1[2 * u + 1] += L1 * cc.y;
                s2[2 * u]     += L2 * cc.x;
                s2[2 * u + 1] += L2 * cc.y;
            }
        }
        float T0 = tiltS[r], T1 = tiltS[257 + r], T2 = tiltS[514 + r];
#pragma unroll
        for (int j = 0; j < 10; j++) {
            acc1[j]      += T0 * s1[j];
            acc1[10 + j] += T1 * s1[j];
            acc1[20 + j] += T2 * s1[j];
            acc1[30 + j] += s1[j];
            acc2[j]      += T0 * s2[j];
            acc2[10 + j] += T1 * s2[j];
            acc2[20 + j] += T2 * s2[j];
            acc2[30 + j] += s2[j];
        }
    }
#pragma unroll
    for (int p = 0; p < 40; p++) {
        g_A[p * NPIX + h1 * 256 + w] = acc1[p];
        g_A[p * NPIX + (h1 + 1) * 256 + w] = acc2[p];
    }
}

// ---------------- vertical mu pass ----------------
__global__ void k_vmu(const float* __restrict__ mu) {
    __shared__ float tiltS[3 * 257];
    __shared__ float Msm[650];
    int w = blockIdx.x, tid = threadIdx.x;
    for (int i = tid; i < 650; i += 256) Msm[i] = mu[i];
    for (int li = tid; li < 768; li += 256) {
        int k = li >> 8, hh = li & 255;
        tiltS[k * 257 + hh] = g_tilt[k * NPIX + hh * 256 + w];
    }
    __syncthreads();
    int h = tid;
    float acc[30];
#pragma unroll
    for (int q = 0; q < 30; q++) acc[q] = 0.f;
    for (int t = 0; t < 65; t++) {
        int r = h + t - 32;
        r = (r < 0) ? -r : ((r > 255) ? 510 - r : r);
        float t0 = tiltS[r], t1 = tiltS[257 + r], t2 = tiltS[514 + r];
#pragma unroll
        for (int m = 0; m < 10; m++) {
            float mv = Msm[t * 10 + m];
            acc[m] += mv * t0;
            acc[10 + m] += mv * t1;
            acc[20 + m] += mv * t2;
        }
    }
#pragma unroll
    for (int p = 0; p < 30; p++) g_Bmu[p * NPIX + h * 256 + w] = acc[p];
}

// ---------------- horizontal pass: 2 outputs (w, w+1) per thread ----------------
__global__ __launch_bounds__(128) void k_horiz(const float* __restrict__ basis_right,
                                               const float* __restrict__ mu,
                                               float* __restrict__ out) {
    extern __shared__ float smh[];
    float* P = smh;
    float* Rsm = P + 70 * 258;
    float* Msm = Rsm + 650;
    int h = blockIdx.x, tid = threadIdx.x;
    for (int i = tid; i < 650; i += 128) {
        Rsm[i] = basis_right[i];
        Msm[i] = mu[i];
    }
    for (int p = 0; p < 40; p++)
        for (int c = tid; c < 256; c += 128) P[p * 258 + c] = g_A[p * NPIX + h * 256 + c];
    for (int p = 0; p < 30; p++)
        for (int c = tid; c < 256; c += 128) P[(40 + p) * 258 + c] = g_Bmu[p * NPIX + h * 256 + c];
    __syncthreads();

    const int w0 = 2 * tid;
    float n0a = 0, n0b = 0, n1a = 0, n1b = 0, n2a = 0, n2b = 0, dna = 0, dnb = 0;

    for (int ke = 0; ke <= 64; ke += 2) {
        int c = w0 + ke - 32;
        bool fast = (c >= 0) && (c <= 254);
        int ca = (c < 0) ? -c : ((c > 255) ? 510 - c : c);
        int cd = c + 1;
        int cb = (cd < 0) ? -cd : ((cd > 255) ? 510 - cd : cd);

        float Rm[10], R0[10], Rp[10], Mm[10], M0[10], Mp[10];
#pragma unroll
        for (int j = 0; j < 10; j++) {
            R0[j] = Rsm[ke * 10 + j];
            M0[j] = Msm[ke * 10 + j];
            Rp[j] = (ke < 64) ? Rsm[(ke + 1) * 10 + j] : 0.f;
            Mp[j] = (ke < 64) ? Msm[(ke + 1) * 10 + j] : 0.f;
            Rm[j] = (ke > 0) ? Rsm[(ke - 1) * 10 + j] : 0.f;
            Mm[j] = (ke > 0) ? Msm[(ke - 1) * 10 + j] : 0.f;
        }
#pragma unroll
        for (int j = 0; j < 10; j++) {
            float2 g;
#define LOADP(p) (fast ? *(const float2*)&P[(p) * 258 + c] \
                       : make_float2(P[(p) * 258 + ca], P[(p) * 258 + cb]))
            g = LOADP(j);
            n0a += R0[j] * g.x + Rp[j] * g.y;  n0b += Rm[j] * g.x + R0[j] * g.y;
            g = LOADP(10 + j);
            n1a += R0[j] * g.x + Rp[j] * g.y;  n1b += Rm[j] * g.x + R0[j] * g.y;
            g = LOADP(20 + j);
            n2a += R0[j] * g.x + Rp[j] * g.y;  n2b += Rm[j] * g.x + R0[j] * g.y;
            g = LOADP(30 + j);
            dna += R0[j] * g.x + Rp[j] * g.y;  dnb += Rm[j] * g.x + R0[j] * g.y;
            g = LOADP(40 + j);
            n0a += M0[j] * g.x + Mp[j] * g.y;  n0b += Mm[j] * g.x + M0[j] * g.y;
            g = LOADP(50 + j);
            n1a += M0[j] * g.x + Mp[j] * g.y;  n1b += Mm[j] * g.x + M0[j] * g.y;
            g = LOADP(60 + j);
            n2a += M0[j] * g.x + Mp[j] * g.y;  n2b += Mm[j] * g.x + M0[j] * g.y;
#undef LOADP
        }
    }
    float dmu = g_denmu;
    dna += dmu;
    dnb += dmu;
    size_t base = (size_t)h * 256 + w0;
    *reinterpret_cast<float2*>(&out[0 * NPIX + base]) = make_float2(n0a / dna, n0b / dnb);
    *reinterpret_cast<float2*>(&out[1 * NPIX + base]) = make_float2(n1a / dna, n1b / dnb);
    *reinterpret_cast<float2*>(&out[2 * NPIX + base]) = make_float2(n2a / dna, n2b / dnb);
}

// ---------------- launcher ----------------
extern "C" void kernel_launch(void* const* d_in, const int* in_sizes, int n_in,
                              void* d_out, int out_size) {
    const float* img  = (const float*)d_in[0];
    const float* zern = (const float*)d_in[1];
    const float* fc1w = (const float*)d_in[2];
    const float* fc1b = (const float*)d_in[3];
    const float* fc2w = (const float*)d_in[4];
    const float* fc2b = (const float*)d_in[5];
    const float* fc3w = (const float*)d_in[6];
    const float* fc3b = (const float*)d_in[7];
    const float* bl   = (const float*)d_in[8];
    const float* br   = (const float*)d_in[9];
    const float* mu   = (const float*)d_in[10];
    float* out = (float*)d_out;

    auto l1 = k_mlp<200, 33, 35, 2, 1>;
    auto l2 = k_mlp<200, 200, 200, 0, 1>;
    auto l3 = k_mlp<100, 200, 200, 0, 0>;
    cudaFuncSetAttribute(l1, cudaFuncAttributeMaxDynamicSharedMemorySize, 23200);
    cudaFuncSetAttribute(l2, cudaFuncAttributeMaxDynamicSharedMemorySize, 87200);
    cudaFuncSetAttribute(l3, cudaFuncAttributeMaxDynamicSharedMemorySize, 45344);
    cudaFuncSetAttribute(k_vert, cudaFuncAttributeMaxDynamicSharedMemorySize, 110132);
    cudaFuncSetAttribute(k_horiz, cudaFuncAttributeMaxDynamicSharedMemorySize, 77440);

    float *h1, *h2, *coef;
    cudaGetSymbolAddress((void**)&h1, g_h1);
    cudaGetSymbolAddress((void**)&h2, g_h2);
    cudaGetSymbolAddress((void**)&coef, g_coef);

    k_denmu<<<1, 64>>>(mu);
    k_gridsample<<<256, 256>>>(img, zern);
    l1<<<148, 512, 23200>>>(zern, fc1w, fc1b, h1);
    l2<<<148, 512, 87200>>>(h1, fc2w, fc2b, h2);
    l3<<<148, 512, 45344>>>(h2, fc3w, fc3b, coef);
    k_vert<<<256, 128, 110132>>>(bl);
    k_vmu<<<256, 256>>>(mu);
    k_horiz<<<256, 128, 77440>>>(br, mu, out);
}

// round 10
// speedup vs baseline: 1.3351x; 1.1939x over previous
#include <cuda_runtime.h>
#include <cuda_fp16.h>
#include <cstdint>

#define NPIX 65536

// ---------------- scratch (device globals; no allocation) ----------------
__device__ float g_tilt[3 * NPIX];
__device__ float g_coef[(size_t)NPIX * 100];
__device__ float g_A[40 * NPIX];
__device__ float g_Bmu[30 * NPIX];
__device__ float g_denmu;

// ---------------- warp-mma helpers ----------------
__device__ __forceinline__ void mma_f16(float* c, uint32_t a0, uint32_t a1, uint32_t a2,
                                        uint32_t a3, uint32_t b0, uint32_t b1) {
    asm volatile(
        "mma.sync.aligned.m16n8k16.row.col.f32.f16.f16.f32 "
        "{%0,%1,%2,%3}, {%4,%5,%6,%7}, {%8,%9}, {%0,%1,%2,%3};"
        : "+f"(c[0]), "+f"(c[1]), "+f"(c[2]), "+f"(c[3])
        : "r"(a0), "r"(a1), "r"(a2), "r"(a3), "r"(b0), "r"(b1));
}
__device__ __forceinline__ uint32_t pack_h2(float a, float b) {
    __half2 t;
    t.x = __float2half(a);
    t.y = __float2half(b);
    return *reinterpret_cast<uint32_t*>(&t);
}
__device__ __forceinline__ float lrelu(float v) { return v > 0.f ? v : 0.01f * v; }

// ================= fused 3-layer MLP, fragment-chained =================
// zern[p,2:35] -> h1(200,lrelu) -> h2(200,lrelu) -> coef(100)
// D-fragment of layer L IS the A-fragment of layer L+1 (no data movement).
// 256 threads = 8 warps; each warp owns 16-row M-tiles strided across the grid.
__global__ __launch_bounds__(256, 1) void k_mlp_fused(
    const float* __restrict__ zern,
    const float* __restrict__ w1, const float* __restrict__ b1,
    const float* __restrict__ w2, const float* __restrict__ b2,
    const float* __restrict__ w3, const float* __restrict__ b3,
    float* __restrict__ coef) {
    constexpr int KS1 = 56;    // l1: K=33, KP=48
    constexpr int KS2 = 216;   // l2/l3: K=200, KP=208
    constexpr int O1 = 0;                  // halves
    constexpr int O2 = O1 + 200 * KS1;
    constexpr int O3 = O2 + 200 * KS2;
    constexpr int OEND = O3 + 104 * KS2;

    extern __shared__ char smraw[];
    __half* sw = reinterpret_cast<__half*>(smraw);
    float* bias_s = reinterpret_cast<float*>(sw + OEND);  // b1[200] b2[200] b3[104]

    int tid = threadIdx.x;
    int lane = tid & 31, warp = tid >> 5;

    // ---- stage weights (fp16) + biases ----
    for (int idx = tid; idx < 200 * 48; idx += 256) {
        int n = idx / 48, k = idx % 48;
        sw[O1 + n * KS1 + k] = __float2half((k < 33) ? w1[n * 33 + k] : 0.0f);
    }
    for (int idx = tid; idx < 200 * 208; idx += 256) {
        int n = idx / 208, k = idx % 208;
        sw[O2 + n * KS2 + k] = __float2half((k < 200) ? w2[n * 200 + k] : 0.0f);
    }
    for (int idx = tid; idx < 104 * 208; idx += 256) {
        int n = idx / 208, k = idx % 208;
        sw[O3 + n * KS2 + k] = __float2half((n < 100 && k < 200) ? w3[n * 200 + k] : 0.0f);
    }
    for (int i = tid; i < 200; i += 256) {
        bias_s[i] = b1[i];
        bias_s[200 + i] = b2[i];
    }
    for (int i = tid; i < 104; i += 256) bias_s[400 + i] = (i < 100) ? b3[i] : 0.0f;
    __syncthreads();

    const int k0 = (lane & 3) * 2;
    const int nrow = lane >> 2;
    const int gw = blockIdx.x * 8 + warp;
    const int gstride = gridDim.x * 8;

    for (int wt = gw; wt < 4096; wt += gstride) {
        const int row0 = wt * 16 + nrow;
        const int row1 = row0 + 8;
        const float* z0 = zern + (size_t)row0 * 35 + 2;
        const float* z1 = zern + (size_t)row1 * 35 + 2;

        float acc[25][4];
#pragma unroll
        for (int nt = 0; nt < 25; nt++)
#pragma unroll
            for (int q = 0; q < 4; q++) acc[nt][q] = 0.0f;

        // ================= layer 1: K=33 (3 chunks), N=200 =================
#pragma unroll
        for (int kc = 0; kc < 3; kc++) {
            int kb = kc * 16 + k0;
            float x00 = (kb < 33) ? z0[kb] : 0.f;
            float x01 = (kb + 1 < 33) ? z0[kb + 1] : 0.f;
            float x10 = (kb < 33) ? z1[kb] : 0.f;
            float x11 = (kb + 1 < 33) ? z1[kb + 1] : 0.f;
            float x02 = (kb + 8 < 33) ? z0[kb + 8] : 0.f;
            float x03 = (kb + 9 < 33) ? z0[kb + 9] : 0.f;
            float x12 = (kb + 8 < 33) ? z1[kb + 8] : 0.f;
            float x13 = (kb + 9 < 33) ? z1[kb + 9] : 0.f;
            uint32_t ah0 = pack_h2(x00, x01);
            uint32_t ah1 = pack_h2(x10, x11);
            uint32_t ah2 = pack_h2(x02, x03);
            uint32_t ah3 = pack_h2(x12, x13);
#pragma unroll
            for (int nt = 0; nt < 25; nt++) {
                const __half* ph = sw + O1 + (nt * 8 + nrow) * KS1 + kc * 16 + k0;
                uint32_t bh0 = *reinterpret_cast<const uint32_t*>(ph);
                uint32_t bh1 = *reinterpret_cast<const uint32_t*>(ph + 8);
                mma_f16(acc[nt], ah0, ah1, ah2, ah3, bh0, bh1);
            }
        }

        // ---- bias + leaky + pack D->A fragments for layer 2 ----
        uint32_t af[13][4];
#pragma unroll
        for (int kc = 0; kc < 13; kc++) {
            {
                int cc = kc * 16 + k0;  // nt = 2kc
                float bv0 = bias_s[cc], bv1 = bias_s[cc + 1];
                af[kc][0] = pack_h2(lrelu(acc[2 * kc][0] + bv0), lrelu(acc[2 * kc][1] + bv1));
                af[kc][1] = pack_h2(lrelu(acc[2 * kc][2] + bv0), lrelu(acc[2 * kc][3] + bv1));
            }
            if (kc < 12) {  // nt = 2kc+1 (kc=12 -> cols 200..207 = 0)
                int cc = kc * 16 + 8 + k0;
                float bv0 = bias_s[cc], bv1 = bias_s[cc + 1];
                af[kc][2] = pack_h2(lrelu(acc[2 * kc + 1][0] + bv0), lrelu(acc[2 * kc + 1][1] + bv1));
                af[kc][3] = pack_h2(lrelu(acc[2 * kc + 1][2] + bv0), lrelu(acc[2 * kc + 1][3] + bv1));
            } else {
                af[kc][2] = 0u;
                af[kc][3] = 0u;
            }
        }

        // ================= layer 2: K=200 (13 chunks), N=200 =================
#pragma unroll
        for (int nt = 0; nt < 25; nt++)
#pragma unroll
            for (int q = 0; q < 4; q++) acc[nt][q] = 0.0f;
#pragma unroll
        for (int kc = 0; kc < 13; kc++) {
            uint32_t ah0 = af[kc][0], ah1 = af[kc][1], ah2 = af[kc][2], ah3 = af[kc][3];
#pragma unroll
            for (int nt = 0; nt < 25; nt++) {
                const __half* ph = sw + O2 + (nt * 8 + nrow) * KS2 + kc * 16 + k0;
                uint32_t bh0 = *reinterpret_cast<const uint32_t*>(ph);
                uint32_t bh1 = *reinterpret_cast<const uint32_t*>(ph + 8);
                mma_f16(acc[nt], ah0, ah1, ah2, ah3, bh0, bh1);
            }
        }

        // ---- bias + leaky + pack for layer 3 ----
#pragma unroll
        for (int kc = 0; kc < 13; kc++) {
            {
                int cc = kc * 16 + k0;
                float bv0 = bias_s[200 + cc], bv1 = bias_s[200 + cc + 1];
                af[kc][0] = pack_h2(lrelu(acc[2 * kc][0] + bv0), lrelu(acc[2 * kc][1] + bv1));
                af[kc][1] = pack_h2(lrelu(acc[2 * kc][2] + bv0), lrelu(acc[2 * kc][3] + bv1));
            }
            if (kc < 12) {
                int cc = kc * 16 + 8 + k0;
                float bv0 = bias_s[200 + cc], bv1 = bias_s[200 + cc + 1];
                af[kc][2] = pack_h2(lrelu(acc[2 * kc + 1][0] + bv0), lrelu(acc[2 * kc + 1][1] + bv1));
                af[kc][3] = pack_h2(lrelu(acc[2 * kc + 1][2] + bv0), lrelu(acc[2 * kc + 1][3] + bv1));
            } else {
                af[kc][2] = 0u;
                af[kc][3] = 0u;
            }
        }

        // ================= layer 3: K=200 (13 chunks), N=100 =================
        float acc3[13][4];
#pragma unroll
        for (int nt = 0; nt < 13; nt++)
#pragma unroll
            for (int q = 0; q < 4; q++) acc3[nt][q] = 0.0f;
#pragma unroll
        for (int kc = 0; kc < 13; kc++) {
            uint32_t ah0 = af[kc][0], ah1 = af[kc][1], ah2 = af[kc][2], ah3 = af[kc][3];
#pragma unroll
            for (int nt = 0; nt < 13; nt++) {
                const __half* ph = sw + O3 + (nt * 8 + nrow) * KS2 + kc * 16 + k0;
                uint32_t bh0 = *reinterpret_cast<const uint32_t*>(ph);
                uint32_t bh1 = *reinterpret_cast<const uint32_t*>(ph + 8);
                mma_f16(acc3[nt], ah0, ah1, ah2, ah3, bh0, bh1);
            }
        }

        // ---- epilogue: bias + store coef (100 cols, fp32) ----
        float* c0 = coef + (size_t)row0 * 100;
        float* c1 = coef + (size_t)row1 * 100;
#pragma unroll
        for (int nt = 0; nt < 13; nt++) {
            int cc = nt * 8 + k0;
            if (cc < 100) {
                float bv0 = bias_s[400 + cc], bv1 = bias_s[400 + cc + 1];
                *reinterpret_cast<float2*>(c0 + cc) =
                    make_float2(acc3[nt][0] + bv0, acc3[nt][1] + bv1);
                *reinterpret_cast<float2*>(c1 + cc) =
                    make_float2(acc3[nt][2] + bv0, acc3[nt][3] + bv1);
            }
        }
    }
}

// ---------------- denominator mu constant ----------------
__global__ void k_denmu(const float* __restrict__ mu) {
    int tid = threadIdx.x;
    __shared__ float S[10];
    if (tid < 10) {
        float s = 0.f;
        for (int t = 0; t < 65; t++) s += mu[t * 10 + tid];
        S[tid] = s * s;
    }
    __syncthreads();
    if (tid == 0) {
        float d = 0.f;
        for (int m = 0; m < 10; m++) d += S[m];
        g_denmu = d;
    }
}

// ---------------- bilinear grid sample ----------------
__global__ void k_gridsample(const float* __restrict__ img, const float* __restrict__ zern) {
    int p = blockIdx.x * blockDim.x + threadIdx.x;
    if (p >= NPIX) return;
    int y = p >> 8, x = p & 255;
    float px = zern[p * 35 + 0], py = zern[p * 35 + 1];
    float fx = 2.0f * ((float)x + px) / 255.0f - 1.0f;
    float fy = 2.0f * ((float)y + py) / 255.0f - 1.0f;
    float ix = ((fx + 1.0f) * 256.0f - 1.0f) * 0.5f;
    float iy = ((fy + 1.0f) * 256.0f - 1.0f) * 0.5f;
    ix = fminf(fmaxf(ix, 0.f), 255.f);
    iy = fminf(fmaxf(iy, 0.f), 255.f);
    float x0f = floorf(ix), y0f = floorf(iy);
    float wx = ix - x0f, wy = iy - y0f;
    int x0 = (int)x0f, y0 = (int)y0f;
    int x1 = min(x0 + 1, 255), y1 = min(y0 + 1, 255);
#pragma unroll
    for (int c = 0; c < 3; c++) {
        const float* im = img + c * NPIX;
        float g00 = im[y0 * 256 + x0], g01 = im[y0 * 256 + x1];
        float g10 = im[y1 * 256 + x0], g11 = im[y1 * 256 + x1];
        float top = g00 * (1.f - wx) + g01 * wx;
        float bot = g10 * (1.f - wx) + g11 * wx;
        g_tilt[c * NPIX + p] = top * (1.f - wy) + bot * wy;
    }
}

// ---------------- vertical pass: 2 outputs (h, h+1) per thread ----------------
__global__ __launch_bounds__(128) void k_vert(const float* __restrict__ basis_left) {
    extern __shared__ float smv[];
    float* coefE = smv;
    float* coefO = smv + 128 * 102;
    float* tiltS = coefO + 128 * 102;
    float* Lsm = tiltS + 3 * 257;
    int w = blockIdx.x, tid = threadIdx.x;
    for (int i = tid; i < 650; i += 128) Lsm[i] = basis_left[i];
    for (int li = tid; li < 6400; li += 128) {
        int hh = li / 25, q = li % 25;
        float4 v = *(const float4*)&g_coef[(size_t)(hh * 256 + w) * 100 + q * 4];
        float* dst = ((hh & 1) ? coefO : coefE) + (hh >> 1) * 102 + q * 4;
        dst[0] = v.x; dst[1] = v.y; dst[2] = v.z; dst[3] = v.w;
    }
    for (int li = tid; li < 768; li += 128) {
        int k = li >> 8, hh = li & 255;
        tiltS[k * 257 + hh] = g_tilt[k * NPIX + hh * 256 + w];
    }
    __syncthreads();

    const int h1 = 2 * tid;
    float acc1[40], acc2[40];
#pragma unroll
    for (int p = 0; p < 40; p++) { acc1[p] = 0.f; acc2[p] = 0.f; }

#pragma unroll 2
    for (int ro = -32; ro <= 33; ro++) {
        int r = h1 + ro;
        r = (r < 0) ? -r : ((r > 255) ? 510 - r : r);
        int t1 = ro + 32, t2 = ro + 31;
        bool va = (t1 <= 64), vb = (t2 >= 0);
        int t1c = va ? t1 : 64, t2c = vb ? t2 : 0;
        const float* crow = ((r & 1) ? coefO : coefE) + (r >> 1) * 102;
        float s1[10], s2[10];
#pragma unroll
        for (int j = 0; j < 10; j++) { s1[j] = 0.f; s2[j] = 0.f; }
#pragma unroll
        for (int i = 0; i < 10; i++) {
            float L1 = va ? Lsm[t1c * 10 + i] : 0.f;
            float L2 = vb ? Lsm[t2c * 10 + i] : 0.f;
#pragma unroll
            for (int u = 0; u < 5; u++) {
                float2 cc = *(const float2*)&crow[i * 10 + 2 * u];
                s1[2 * u]     += L1 * cc.x;
                s1[2 * u + 1] += L1 * cc.y;
                s2[2 * u]     += L2 * cc.x;
                s2[2 * u + 1] += L2 * cc.y;
            }
        }
        float T0 = tiltS[r], T1 = tiltS[257 + r], T2 = tiltS[514 + r];
#pragma unroll
        for (int j = 0; j < 10; j++) {
            acc1[j]      += T0 * s1[j];
            acc1[10 + j] += T1 * s1[j];
            acc1[20 + j] += T2 * s1[j];
            acc1[30 + j] += s1[j];
            acc2[j]      += T0 * s2[j];
            acc2[10 + j] += T1 * s2[j];
            acc2[20 + j] += T2 * s2[j];
            acc2[30 + j] += s2[j];
        }
    }
#pragma unroll
    for (int p = 0; p < 40; p++) {
        g_A[p * NPIX + h1 * 256 + w] = acc1[p];
        g_A[p * NPIX + (h1 + 1) * 256 + w] = acc2[p];
    }
}

// ---------------- vertical mu pass ----------------
__global__ void k_vmu(const float* __restrict__ mu) {
    __shared__ float tiltS[3 * 257];
    __shared__ float Msm[650];
    int w = blockIdx.x, tid = threadIdx.x;
    for (int i = tid; i < 650; i += 256) Msm[i] = mu[i];
    for (int li = tid; li < 768; li += 256) {
        int k = li >> 8, hh = li & 255;
        tiltS[k * 257 + hh] = g_tilt[k * NPIX + hh * 256 + w];
    }
    __syncthreads();
    int h = tid;
    float acc[30];
#pragma unroll
    for (int q = 0; q < 30; q++) acc[q] = 0.f;
    for (int t = 0; t < 65; t++) {
        int r = h + t - 32;
        r = (r < 0) ? -r : ((r > 255) ? 510 - r : r);
        float t0 = tiltS[r], t1 = tiltS[257 + r], t2 = tiltS[514 + r];
#pragma unroll
        for (int m = 0; m < 10; m++) {
            float mv = Msm[t * 10 + m];
            acc[m] += mv * t0;
            acc[10 + m] += mv * t1;
            acc[20 + m] += mv * t2;
        }
    }
#pragma unroll
    for (int p = 0; p < 30; p++) g_Bmu[p * NPIX + h * 256 + w] = acc[p];
}

// ---------------- horizontal pass: 2 outputs (w, w+1) per thread ----------------
__global__ __launch_bounds__(128) void k_horiz(const float* __restrict__ basis_right,
                                               const float* __restrict__ mu,
                                               float* __restrict__ out) {
    extern __shared__ float smh[];
    float* P = smh;
    float* Rsm = P + 70 * 258;
    float* Msm = Rsm + 650;
    int h = blockIdx.x, tid = threadIdx.x;
    for (int i = tid; i < 650; i += 128) {
        Rsm[i] = basis_right[i];
        Msm[i] = mu[i];
    }
    for (int p = 0; p < 40; p++)
        for (int c = tid; c < 256; c += 128) P[p * 258 + c] = g_A[p * NPIX + h * 256 + c];
    for (int p = 0; p < 30; p++)
        for (int c = tid; c < 256; c += 128) P[(40 + p) * 258 + c] = g_Bmu[p * NPIX + h * 256 + c];
    __syncthreads();

    const int w0 = 2 * tid;
    float n0a = 0, n0b = 0, n1a = 0, n1b = 0, n2a = 0, n2b = 0, dna = 0, dnb = 0;

    for (int ke = 0; ke <= 64; ke += 2) {
        int c = w0 + ke - 32;
        bool fast = (c >= 0) && (c <= 254);
        int ca = (c < 0) ? -c : ((c > 255) ? 510 - c : c);
        int cd = c + 1;
        int cb = (cd < 0) ? -cd : ((cd > 255) ? 510 - cd : cd);

        float Rm[10], R0[10], Rp[10], Mm[10], M0[10], Mp[10];
#pragma unroll
        for (int j = 0; j < 10; j++) {
            R0[j] = Rsm[ke * 10 + j];
            M0[j] = Msm[ke * 10 + j];
            Rp[j] = (ke < 64) ? Rsm[(ke + 1) * 10 + j] : 0.f;
            Mp[j] = (ke < 64) ? Msm[(ke + 1) * 10 + j] : 0.f;
            Rm[j] = (ke > 0) ? Rsm[(ke - 1) * 10 + j] : 0.f;
            Mm[j] = (ke > 0) ? Msm[(ke - 1) * 10 + j] : 0.f;
        }
#pragma unroll
        for (int j = 0; j < 10; j++) {
            float2 g;
#define LOADP(p) (fast ? *(const float2*)&P[(p) * 258 + c] \
                       : make_float2(P[(p) * 258 + ca], P[(p) * 258 + cb]))
            g = LOADP(j);
            n0a += R0[j] * g.x + Rp[j] * g.y;  n0b += Rm[j] * g.x + R0[j] * g.y;
            g = LOADP(10 + j);
            n1a += R0[j] * g.x + Rp[j] * g.y;  n1b += Rm[j] * g.x + R0[j] * g.y;
            g = LOADP(20 + j);
            n2a += R0[j] * g.x + Rp[j] * g.y;  n2b += Rm[j] * g.x + R0[j] * g.y;
            g = LOADP(30 + j);
            dna += R0[j] * g.x + Rp[j] * g.y;  dnb += Rm[j] * g.x + R0[j] * g.y;
            g = LOADP(40 + j);
            n0a += M0[j] * g.x + Mp[j] * g.y;  n0b += Mm[j] * g.x + M0[j] * g.y;
            g = LOADP(50 + j);
            n1a += M0[j] * g.x + Mp[j] * g.y;  n1b += Mm[j] * g.x + M0[j] * g.y;
            g = LOADP(60 + j);
            n2a += M0[j] * g.x + Mp[j] * g.y;  n2b += Mm[j] * g.x + M0[j] * g.y;
#undef LOADP
        }
    }
    float dmu = g_denmu;
    dna += dmu;
    dnb += dmu;
    size_t base = (size_t)h * 256 + w0;
    *reinterpret_cast<float2*>(&out[0 * NPIX + base]) = make_float2(n0a / dna, n0b / dnb);
    *reinterpret_cast<float2*>(&out[1 * NPIX + base]) = make_float2(n1a / dna, n1b / dnb);
    *reinterpret_cast<float2*>(&out[2 * NPIX + base]) = make_float2(n2a / dna, n2b / dnb);
}

// ---------------- launcher ----------------
extern "C" void kernel_launch(void* const* d_in, const int* in_sizes, int n_in,
                              void* d_out, int out_size) {
    const float* img  = (const float*)d_in[0];
    const float* zern = (const float*)d_in[1];
    const float* fc1w = (const float*)d_in[2];
    const float* fc1b = (const float*)d_in[3];
    const float* fc2w = (const float*)d_in[4];
    const float* fc2b = (const float*)d_in[5];
    const float* fc3w = (const float*)d_in[6];
    const float* fc3b = (const float*)d_in[7];
    const float* bl   = (const float*)d_in[8];
    const float* br   = (const float*)d_in[9];
    const float* mu   = (const float*)d_in[10];
    float* out = (float*)d_out;

    // fused MLP smem: (200*56 + 200*216 + 104*216)*2B + 504*4B = 153728 + 2016 = 155744
    cudaFuncSetAttribute(k_mlp_fused, cudaFuncAttributeMaxDynamicSharedMemorySize, 155744);
    cudaFuncSetAttribute(k_vert, cudaFuncAttributeMaxDynamicSharedMemorySize, 110132);
    cudaFuncSetAttribute(k_horiz, cudaFuncAttributeMaxDynamicSharedMemorySize, 77440);

    float* coef;
    cudaGetSymbolAddress((void**)&coef, g_coef);

    k_denmu<<<1, 64>>>(mu);
    k_gridsample<<<256, 256>>>(img, zern);
    k_mlp_fused<<<148, 256, 155744>>>(zern, fc1w, fc1b, fc2w, fc2b, fc3w, fc3b, coef);
    k_vert<<<256, 128, 110132>>>(bl);
    k_vmu<<<256, 256>>>(mu);
    k_horiz<<<256, 128, 77440>>>(br, mu, out);
}

// round 11
// speedup vs baseline: 1.3584x; 1.0174x over previous
#include <cuda_runtime.h>
#include <cuda_fp16.h>
#include <cstdint>

#define NPIX 65536

typedef unsigned long long u64;

// ---------------- scratch (device globals; no allocation) ----------------
__device__ float g_tilt[3 * NPIX];
__device__ float g_coef[(size_t)NPIX * 100];
__device__ float g_A[40 * NPIX];
__device__ float g_Bmu[30 * NPIX];
__device__ float g_denmu;

// ---------------- packed f32x2 helpers (Blackwell) ----------------
__device__ __forceinline__ void fma2(u64& d, u64 a, u64 b) {
    asm("fma.rn.f32x2 %0, %1, %2, %0;" : "+l"(d) : "l"(a), "l"(b));
}
__device__ __forceinline__ u64 dup2(float x) {
    u64 d;
    asm("mov.b64 %0, {%1, %2};" : "=l"(d) : "f"(x), "f"(x));
    return d;
}
__device__ __forceinline__ float2 unpk(u64 v) {
    float2 r;
    asm("mov.b64 {%0, %1}, %2;" : "=f"(r.x), "=f"(r.y) : "l"(v));
    return r;
}

// ---------------- warp-mma helpers ----------------
__device__ __forceinline__ void mma_f16(float* c, uint32_t a0, uint32_t a1, uint32_t a2,
                                        uint32_t a3, uint32_t b0, uint32_t b1) {
    asm volatile(
        "mma.sync.aligned.m16n8k16.row.col.f32.f16.f16.f32 "
        "{%0,%1,%2,%3}, {%4,%5,%6,%7}, {%8,%9}, {%0,%1,%2,%3};"
        : "+f"(c[0]), "+f"(c[1]), "+f"(c[2]), "+f"(c[3])
        : "r"(a0), "r"(a1), "r"(a2), "r"(a3), "r"(b0), "r"(b1));
}
__device__ __forceinline__ uint32_t pack_h2(float a, float b) {
    __half2 t;
    t.x = __float2half(a);
    t.y = __float2half(b);
    return *reinterpret_cast<uint32_t*>(&t);
}
__device__ __forceinline__ float lrelu(float v) { return v > 0.f ? v : 0.01f * v; }

// ================= fused 3-layer MLP, fragment-chained =================
__global__ __launch_bounds__(256, 1) void k_mlp_fused(
    const float* __restrict__ zern,
    const float* __restrict__ w1, const float* __restrict__ b1,
    const float* __restrict__ w2, const float* __restrict__ b2,
    const float* __restrict__ w3, const float* __restrict__ b3,
    float* __restrict__ coef) {
    constexpr int KS1 = 56;
    constexpr int KS2 = 216;
    constexpr int O1 = 0;
    constexpr int O2 = O1 + 200 * KS1;
    constexpr int O3 = O2 + 200 * KS2;
    constexpr int OEND = O3 + 104 * KS2;

    extern __shared__ char smraw[];
    __half* sw = reinterpret_cast<__half*>(smraw);
    float* bias_s = reinterpret_cast<float*>(sw + OEND);

    int tid = threadIdx.x;
    int lane = tid & 31, warp = tid >> 5;

    for (int idx = tid; idx < 200 * 48; idx += 256) {
        int n = idx / 48, k = idx % 48;
        sw[O1 + n * KS1 + k] = __float2half((k < 33) ? w1[n * 33 + k] : 0.0f);
    }
    for (int idx = tid; idx < 200 * 208; idx += 256) {
        int n = idx / 208, k = idx % 208;
        sw[O2 + n * KS2 + k] = __float2half((k < 200) ? w2[n * 200 + k] : 0.0f);
    }
    for (int idx = tid; idx < 104 * 208; idx += 256) {
        int n = idx / 208, k = idx % 208;
        sw[O3 + n * KS2 + k] = __float2half((n < 100 && k < 200) ? w3[n * 200 + k] : 0.0f);
    }
    for (int i = tid; i < 200; i += 256) {
        bias_s[i] = b1[i];
        bias_s[200 + i] = b2[i];
    }
    for (int i = tid; i < 104; i += 256) bias_s[400 + i] = (i < 100) ? b3[i] : 0.0f;
    __syncthreads();

    const int k0 = (lane & 3) * 2;
    const int nrow = lane >> 2;
    const int gw = blockIdx.x * 8 + warp;
    const int gstride = gridDim.x * 8;

    for (int wt = gw; wt < 4096; wt += gstride) {
        const int row0 = wt * 16 + nrow;
        const int row1 = row0 + 8;
        const float* z0 = zern + (size_t)row0 * 35 + 2;
        const float* z1 = zern + (size_t)row1 * 35 + 2;

        float acc[25][4];
#pragma unroll
        for (int nt = 0; nt < 25; nt++)
#pragma unroll
            for (int q = 0; q < 4; q++) acc[nt][q] = 0.0f;

        // layer 1: K=33
#pragma unroll
        for (int kc = 0; kc < 3; kc++) {
            int kb = kc * 16 + k0;
            float x00 = (kb < 33) ? z0[kb] : 0.f;
            float x01 = (kb + 1 < 33) ? z0[kb + 1] : 0.f;
            float x10 = (kb < 33) ? z1[kb] : 0.f;
            float x11 = (kb + 1 < 33) ? z1[kb + 1] : 0.f;
            float x02 = (kb + 8 < 33) ? z0[kb + 8] : 0.f;
            float x03 = (kb + 9 < 33) ? z0[kb + 9] : 0.f;
            float x12 = (kb + 8 < 33) ? z1[kb + 8] : 0.f;
            float x13 = (kb + 9 < 33) ? z1[kb + 9] : 0.f;
            uint32_t ah0 = pack_h2(x00, x01);
            uint32_t ah1 = pack_h2(x10, x11);
            uint32_t ah2 = pack_h2(x02, x03);
            uint32_t ah3 = pack_h2(x12, x13);
#pragma unroll
            for (int nt = 0; nt < 25; nt++) {
                const __half* ph = sw + O1 + (nt * 8 + nrow) * KS1 + kc * 16 + k0;
                uint32_t bh0 = *reinterpret_cast<const uint32_t*>(ph);
                uint32_t bh1 = *reinterpret_cast<const uint32_t*>(ph + 8);
                mma_f16(acc[nt], ah0, ah1, ah2, ah3, bh0, bh1);
            }
        }

        uint32_t af[13][4];
#pragma unroll
        for (int kc = 0; kc < 13; kc++) {
            {
                int cc = kc * 16 + k0;
                float bv0 = bias_s[cc], bv1 = bias_s[cc + 1];
                af[kc][0] = pack_h2(lrelu(acc[2 * kc][0] + bv0), lrelu(acc[2 * kc][1] + bv1));
                af[kc][1] = pack_h2(lrelu(acc[2 * kc][2] + bv0), lrelu(acc[2 * kc][3] + bv1));
            }
            if (kc < 12) {
                int cc = kc * 16 + 8 + k0;
                float bv0 = bias_s[cc], bv1 = bias_s[cc + 1];
                af[kc][2] = pack_h2(lrelu(acc[2 * kc + 1][0] + bv0), lrelu(acc[2 * kc + 1][1] + bv1));
                af[kc][3] = pack_h2(lrelu(acc[2 * kc + 1][2] + bv0), lrelu(acc[2 * kc + 1][3] + bv1));
            } else {
                af[kc][2] = 0u;
                af[kc][3] = 0u;
            }
        }

        // layer 2
#pragma unroll
        for (int nt = 0; nt < 25; nt++)
#pragma unroll
            for (int q = 0; q < 4; q++) acc[nt][q] = 0.0f;
#pragma unroll
        for (int kc = 0; kc < 13; kc++) {
            uint32_t ah0 = af[kc][0], ah1 = af[kc][1], ah2 = af[kc][2], ah3 = af[kc][3];
#pragma unroll
            for (int nt = 0; nt < 25; nt++) {
                const __half* ph = sw + O2 + (nt * 8 + nrow) * KS2 + kc * 16 + k0;
                uint32_t bh0 = *reinterpret_cast<const uint32_t*>(ph);
                uint32_t bh1 = *reinterpret_cast<const uint32_t*>(ph + 8);
                mma_f16(acc[nt], ah0, ah1, ah2, ah3, bh0, bh1);
            }
        }

#pragma unroll
        for (int kc = 0; kc < 13; kc++) {
            {
                int cc = kc * 16 + k0;
                float bv0 = bias_s[200 + cc], bv1 = bias_s[200 + cc + 1];
                af[kc][0] = pack_h2(lrelu(acc[2 * kc][0] + bv0), lrelu(acc[2 * kc][1] + bv1));
                af[kc][1] = pack_h2(lrelu(acc[2 * kc][2] + bv0), lrelu(acc[2 * kc][3] + bv1));
            }
            if (kc < 12) {
                int cc = kc * 16 + 8 + k0;
                float bv0 = bias_s[200 + cc], bv1 = bias_s[200 + cc + 1];
                af[kc][2] = pack_h2(lrelu(acc[2 * kc + 1][0] + bv0), lrelu(acc[2 * kc + 1][1] + bv1));
                af[kc][3] = pack_h2(lrelu(acc[2 * kc + 1][2] + bv0), lrelu(acc[2 * kc + 1][3] + bv1));
            } else {
                af[kc][2] = 0u;
                af[kc][3] = 0u;
            }
        }

        // layer 3
        float acc3[13][4];
#pragma unroll
        for (int nt = 0; nt < 13; nt++)
#pragma unroll
            for (int q = 0; q < 4; q++) acc3[nt][q] = 0.0f;
#pragma unroll
        for (int kc = 0; kc < 13; kc++) {
            uint32_t ah0 = af[kc][0], ah1 = af[kc][1], ah2 = af[kc][2], ah3 = af[kc][3];
#pragma unroll
            for (int nt = 0; nt < 13; nt++) {
                const __half* ph = sw + O3 + (nt * 8 + nrow) * KS2 + kc * 16 + k0;
                uint32_t bh0 = *reinterpret_cast<const uint32_t*>(ph);
                uint32_t bh1 = *reinterpret_cast<const uint32_t*>(ph + 8);
                mma_f16(acc3[nt], ah0, ah1, ah2, ah3, bh0, bh1);
            }
        }

        float* c0 = coef + (size_t)row0 * 100;
        float* c1 = coef + (size_t)row1 * 100;
#pragma unroll
        for (int nt = 0; nt < 13; nt++) {
            int cc = nt * 8 + k0;
            if (cc < 100) {
                float bv0 = bias_s[400 + cc], bv1 = bias_s[400 + cc + 1];
                *reinterpret_cast<float2*>(c0 + cc) =
                    make_float2(acc3[nt][0] + bv0, acc3[nt][1] + bv1);
                *reinterpret_cast<float2*>(c1 + cc) =
                    make_float2(acc3[nt][2] + bv0, acc3[nt][3] + bv1);
            }
        }
    }
}

// ---------------- denominator mu constant ----------------
__global__ void k_denmu(const float* __restrict__ mu) {
    int tid = threadIdx.x;
    __shared__ float S[10];
    if (tid < 10) {
        float s = 0.f;
        for (int t = 0; t < 65; t++) s += mu[t * 10 + tid];
        S[tid] = s * s;
    }
    __syncthreads();
    if (tid == 0) {
        float d = 0.f;
        for (int m = 0; m < 10; m++) d += S[m];
        g_denmu = d;
    }
}

// ---------------- bilinear grid sample ----------------
__global__ void k_gridsample(const float* __restrict__ img, const float* __restrict__ zern) {
    int p = blockIdx.x * blockDim.x + threadIdx.x;
    if (p >= NPIX) return;
    int y = p >> 8, x = p & 255;
    float px = zern[p * 35 + 0], py = zern[p * 35 + 1];
    float fx = 2.0f * ((float)x + px) / 255.0f - 1.0f;
    float fy = 2.0f * ((float)y + py) / 255.0f - 1.0f;
    float ix = ((fx + 1.0f) * 256.0f - 1.0f) * 0.5f;
    float iy = ((fy + 1.0f) * 256.0f - 1.0f) * 0.5f;
    ix = fminf(fmaxf(ix, 0.f), 255.f);
    iy = fminf(fmaxf(iy, 0.f), 255.f);
    float x0f = floorf(ix), y0f = floorf(iy);
    float wx = ix - x0f, wy = iy - y0f;
    int x0 = (int)x0f, y0 = (int)y0f;
    int x1 = min(x0 + 1, 255), y1 = min(y0 + 1, 255);
#pragma unroll
    for (int c = 0; c < 3; c++) {
        const float* im = img + c * NPIX;
        float g00 = im[y0 * 256 + x0], g01 = im[y0 * 256 + x1];
        float g10 = im[y1 * 256 + x0], g11 = im[y1 * 256 + x1];
        float top = g00 * (1.f - wx) + g01 * wx;
        float bot = g10 * (1.f - wx) + g11 * wx;
        g_tilt[c * NPIX + p] = top * (1.f - wy) + bot * wy;
    }
}

// ---------------- vertical pass: 2 outputs/thread, packed f32x2 math ----------------
__global__ __launch_bounds__(128) void k_vert(const float* __restrict__ basis_left) {
    extern __shared__ float smv[];
    float* coefE = smv;
    float* coefO = smv + 128 * 102;
    float* tiltS = coefO + 128 * 102;
    float* Lsm = tiltS + 3 * 257;
    int w = blockIdx.x, tid = threadIdx.x;
    for (int i = tid; i < 650; i += 128) Lsm[i] = basis_left[i];
    for (int li = tid; li < 6400; li += 128) {
        int hh = li / 25, q = li % 25;
        float4 v = *(const float4*)&g_coef[(size_t)(hh * 256 + w) * 100 + q * 4];
        float* dst = ((hh & 1) ? coefO : coefE) + (hh >> 1) * 102 + q * 4;
        dst[0] = v.x; dst[1] = v.y; dst[2] = v.z; dst[3] = v.w;
    }
    for (int li = tid; li < 768; li += 128) {
        int k = li >> 8, hh = li & 255;
        tiltS[k * 257 + hh] = g_tilt[k * NPIX + hh * 256 + w];
    }
    __syncthreads();

    const int h1 = 2 * tid;
    const u64 ONEd = dup2(1.0f);
    u64 acc1p[20], acc2p[20];   // [img(4)][u(5)] j-pairs (2u, 2u+1)
#pragma unroll
    for (int p = 0; p < 20; p++) { acc1p[p] = 0ull; acc2p[p] = 0ull; }

#pragma unroll 2
    for (int ro = -32; ro <= 33; ro++) {
        int r = h1 + ro;
        r = (r < 0) ? -r : ((r > 255) ? 510 - r : r);
        int t1 = ro + 32, t2 = ro + 31;
        bool va = (t1 <= 64), vb = (t2 >= 0);
        int t1c = va ? t1 : 64, t2c = vb ? t2 : 0;
        const u64* crow = reinterpret_cast<const u64*>(
            (((r & 1) ? coefO : coefE) + (r >> 1) * 102));
        u64 s1[5], s2[5];
#pragma unroll
        for (int u = 0; u < 5; u++) { s1[u] = 0ull; s2[u] = 0ull; }
#pragma unroll
        for (int i = 0; i < 10; i++) {
            float L1 = va ? Lsm[t1c * 10 + i] : 0.f;
            float L2 = vb ? Lsm[t2c * 10 + i] : 0.f;
            u64 L1d = dup2(L1), L2d = dup2(L2);
#pragma unroll
            for (int u = 0; u < 5; u++) {
                u64 cw = crow[i * 5 + u];
                fma2(s1[u], L1d, cw);
                fma2(s2[u], L2d, cw);
            }
        }
        u64 T0d = dup2(tiltS[r]), T1d = dup2(tiltS[257 + r]), T2d = dup2(tiltS[514 + r]);
#pragma unroll
        for (int u = 0; u < 5; u++) {
            fma2(acc1p[u], T0d, s1[u]);
            fma2(acc1p[5 + u], T1d, s1[u]);
            fma2(acc1p[10 + u], T2d, s1[u]);
            fma2(acc1p[15 + u], ONEd, s1[u]);
            fma2(acc2p[u], T0d, s2[u]);
            fma2(acc2p[5 + u], T1d, s2[u]);
            fma2(acc2p[10 + u], T2d, s2[u]);
            fma2(acc2p[15 + u], ONEd, s2[u]);
        }
    }
#pragma unroll
    for (int img = 0; img < 4; img++) {
#pragma unroll
        for (int u = 0; u < 5; u++) {
            float2 v1 = unpk(acc1p[img * 5 + u]);
            float2 v2 = unpk(acc2p[img * 5 + u]);
            int p = img * 10 + 2 * u;
            g_A[p * NPIX + h1 * 256 + w] = v1.x;
            g_A[(p + 1) * NPIX + h1 * 256 + w] = v1.y;
            g_A[p * NPIX + (h1 + 1) * 256 + w] = v2.x;
            g_A[(p + 1) * NPIX + (h1 + 1) * 256 + w] = v2.y;
        }
    }
}

// ---------------- vertical mu pass (packed f32x2) ----------------
__global__ void k_vmu(const float* __restrict__ mu) {
    __shared__ __align__(16) float tiltS[3 * 257];
    __shared__ __align__(16) float Msm[650];
    int w = blockIdx.x, tid = threadIdx.x;
    for (int i = tid; i < 650; i += 256) Msm[i] = mu[i];
    for (int li = tid; li < 768; li += 256) {
        int k = li >> 8, hh = li & 255;
        tiltS[k * 257 + hh] = g_tilt[k * NPIX + hh * 256 + w];
    }
    __syncthreads();
    int h = tid;
    u64 accp[15];   // [img(3)][u(5)]
#pragma unroll
    for (int q = 0; q < 15; q++) accp[q] = 0ull;
    for (int t = 0; t < 65; t++) {
        int r = h + t - 32;
        r = (r < 0) ? -r : ((r > 255) ? 510 - r : r);
        u64 T0d = dup2(tiltS[r]), T1d = dup2(tiltS[257 + r]), T2d = dup2(tiltS[514 + r]);
        const u64* mrow = reinterpret_cast<const u64*>(Msm + t * 10);
#pragma unroll
        for (int u = 0; u < 5; u++) {
            u64 mw = mrow[u];
            fma2(accp[u], T0d, mw);
            fma2(accp[5 + u], T1d, mw);
            fma2(accp[10 + u], T2d, mw);
        }
    }
#pragma unroll
    for (int img = 0; img < 3; img++) {
#pragma unroll
        for (int u = 0; u < 5; u++) {
            float2 v = unpk(accp[img * 5 + u]);
            int p = img * 10 + 2 * u;
            g_Bmu[p * NPIX + h * 256 + w] = v.x;
            g_Bmu[(p + 1) * NPIX + h * 256 + w] = v.y;
        }
    }
}

// ---------------- horizontal pass: 2 outputs (w, w+1) per thread ----------------
__global__ __launch_bounds__(128) void k_horiz(const float* __restrict__ basis_right,
                                               const float* __restrict__ mu,
                                               float* __restrict__ out) {
    extern __shared__ float smh[];
    float* P = smh;
    float* Rsm = P + 70 * 258;
    float* Msm = Rsm + 650;
    int h = blockIdx.x, tid = threadIdx.x;
    for (int i = tid; i < 650; i += 128) {
        Rsm[i] = basis_right[i];
        Msm[i] = mu[i];
    }
    for (int p = 0; p < 40; p++)
        for (int c = tid; c < 256; c += 128) P[p * 258 + c] = g_A[p * NPIX + h * 256 + c];
    for (int p = 0; p < 30; p++)
        for (int c = tid; c < 256; c += 128) P[(40 + p) * 258 + c] = g_Bmu[p * NPIX + h * 256 + c];
    __syncthreads();

    const int w0 = 2 * tid;
    float n0a = 0, n0b = 0, n1a = 0, n1b = 0, n2a = 0, n2b = 0, dna = 0, dnb = 0;

    for (int ke = 0; ke <= 64; ke += 2) {
        int c = w0 + ke - 32;
        bool fast = (c >= 0) && (c <= 254);
        int ca = (c < 0) ? -c : ((c > 255) ? 510 - c : c);
        int cd = c + 1;
        int cb = (cd < 0) ? -cd : ((cd > 255) ? 510 - cd : cd);

        float Rm[10], R0[10], Rp[10], Mm[10], M0[10], Mp[10];
#pragma unroll
        for (int j = 0; j < 10; j++) {
            R0[j] = Rsm[ke * 10 + j];
            M0[j] = Msm[ke * 10 + j];
            Rp[j] = (ke < 64) ? Rsm[(ke + 1) * 10 + j] : 0.f;
            Mp[j] = (ke < 64) ? Msm[(ke + 1) * 10 + j] : 0.f;
            Rm[j] = (ke > 0) ? Rsm[(ke - 1) * 10 + j] : 0.f;
            Mm[j] = (ke > 0) ? Msm[(ke - 1) * 10 + j] : 0.f;
        }
#pragma unroll
        for (int j = 0; j < 10; j++) {
            float2 g;
#define LOADP(p) (fast ? *(const float2*)&P[(p) * 258 + c] \
                       : make_float2(P[(p) * 258 + ca], P[(p) * 258 + cb]))
            g = LOADP(j);
            n0a += R0[j] * g.x + Rp[j] * g.y;  n0b += Rm[j] * g.x + R0[j] * g.y;
            g = LOADP(10 + j);
            n1a += R0[j] * g.x + Rp[j] * g.y;  n1b += Rm[j] * g.x + R0[j] * g.y;
            g = LOADP(20 + j);
            n2a += R0[j] * g.x + Rp[j] * g.y;  n2b += Rm[j] * g.x + R0[j] * g.y;
            g = LOADP(30 + j);
            dna += R0[j] * g.x + Rp[j] * g.y;  dnb += Rm[j] * g.x + R0[j] * g.y;
            g = LOADP(40 + j);
            n0a += M0[j] * g.x + Mp[j] * g.y;  n0b += Mm[j] * g.x + M0[j] * g.y;
            g = LOADP(50 + j);
            n1a += M0[j] * g.x + Mp[j] * g.y;  n1b += Mm[j] * g.x + M0[j] * g.y;
            g = LOADP(60 + j);
            n2a += M0[j] * g.x + Mp[j] * g.y;  n2b += Mm[j] * g.x + M0[j] * g.y;
#undef LOADP
        }
    }
    float dmu = g_denmu;
    dna += dmu;
    dnb += dmu;
    size_t base = (size_t)h * 256 + w0;
    *reinterpret_cast<float2*>(&out[0 * NPIX + base]) = make_float2(n0a / dna, n0b / dnb);
    *reinterpret_cast<float2*>(&out[1 * NPIX + base]) = make_float2(n1a / dna, n1b / dnb);
    *reinterpret_cast<float2*>(&out[2 * NPIX + base]) = make_float2(n2a / dna, n2b / dnb);
}

// ---------------- launcher ----------------
extern "C" void kernel_launch(void* const* d_in, const int* in_sizes, int n_in,
                              void* d_out, int out_size) {
    const float* img  = (const float*)d_in[0];
    const float* zern = (const float*)d_in[1];
    const float* fc1w = (const float*)d_in[2];
    const float* fc1b = (const float*)d_in[3];
    const float* fc2w = (const float*)d_in[4];
    const float* fc2b = (const float*)d_in[5];
    const float* fc3w = (const float*)d_in[6];
    const float* fc3b = (const float*)d_in[7];
    const float* bl   = (const float*)d_in[8];
    const float* br   = (const float*)d_in[9];
    const float* mu   = (const float*)d_in[10];
    float* out = (float*)d_out;

    cudaFuncSetAttribute(k_mlp_fused, cudaFuncAttributeMaxDynamicSharedMemorySize, 155744);
    cudaFuncSetAttribute(k_vert, cudaFuncAttributeMaxDynamicSharedMemorySize, 110132);
    cudaFuncSetAttribute(k_horiz, cudaFuncAttributeMaxDynamicSharedMemorySize, 77440);

    float* coef;
    cudaGetSymbolAddress((void**)&coef, g_coef);

    k_denmu<<<1, 64>>>(mu);
    k_gridsample<<<256, 256>>>(img, zern);
    k_mlp_fused<<<148, 256, 155744>>>(zern, fc1w, fc1b, fc2w, fc2b, fc3w, fc3b, coef);
    k_vert<<<256, 128, 110132>>>(bl);
    k_vmu<<<256, 256>>>(mu);
    k_horiz<<<256, 128, 77440>>>(br, mu, out);
}

// round 12
// speedup vs baseline: 1.5397x; 1.1335x over previous
#include <cuda_runtime.h>
#include <cuda_fp16.h>
#include <cstdint>

#define NPIX 65536

typedef unsigned long long u64;

// ---------------- scratch (device globals; no allocation) ----------------
__device__ float g_tilt[3 * NPIX];
__device__ float g_coef[(size_t)NPIX * 100];
__device__ float g_A[40 * NPIX];
__device__ float g_Bmu[30 * NPIX];
__device__ float g_denmu;

// ---------------- packed f32x2 helpers (Blackwell) ----------------
__device__ __forceinline__ void fma2(u64& d, u64 a, u64 b) {
    asm("fma.rn.f32x2 %0, %1, %2, %0;" : "+l"(d) : "l"(a), "l"(b));
}
__device__ __forceinline__ void add2(u64& d, u64 a) {
    asm("add.rn.f32x2 %0, %0, %1;" : "+l"(d) : "l"(a));
}
__device__ __forceinline__ u64 dup2(float x) {
    u64 d;
    asm("mov.b64 %0, {%1, %2};" : "=l"(d) : "f"(x), "f"(x));
    return d;
}
__device__ __forceinline__ float2 unpk(u64 v) {
    float2 r;
    asm("mov.b64 {%0, %1}, %2;" : "=f"(r.x), "=f"(r.y) : "l"(v));
    return r;
}

// ---------------- warp-mma helpers ----------------
__device__ __forceinline__ void mma_f16(float* c, uint32_t a0, uint32_t a1, uint32_t a2,
                                        uint32_t a3, uint32_t b0, uint32_t b1) {
    asm volatile(
        "mma.sync.aligned.m16n8k16.row.col.f32.f16.f16.f32 "
        "{%0,%1,%2,%3}, {%4,%5,%6,%7}, {%8,%9}, {%0,%1,%2,%3};"
        : "+f"(c[0]), "+f"(c[1]), "+f"(c[2]), "+f"(c[3])
        : "r"(a0), "r"(a1), "r"(a2), "r"(a3), "r"(b0), "r"(b1));
}
__device__ __forceinline__ uint32_t pack_h2(float a, float b) {
    __half2 t;
    t.x = __float2half(a);
    t.y = __float2half(b);
    return *reinterpret_cast<uint32_t*>(&t);
}
__device__ __forceinline__ float lrelu(float v) { return v > 0.f ? v : 0.01f * v; }

// ================= fused 3-layer MLP, fragment-chained =================
__global__ __launch_bounds__(256, 1) void k_mlp_fused(
    const float* __restrict__ zern,
    const float* __restrict__ w1, const float* __restrict__ b1,
    const float* __restrict__ w2, const float* __restrict__ b2,
    const float* __restrict__ w3, const float* __restrict__ b3,
    float* __restrict__ coef) {
    constexpr int KS1 = 56;
    constexpr int KS2 = 216;
    constexpr int O1 = 0;
    constexpr int O2 = O1 + 200 * KS1;
    constexpr int O3 = O2 + 200 * KS2;
    constexpr int OEND = O3 + 104 * KS2;

    extern __shared__ char smraw[];
    __half* sw = reinterpret_cast<__half*>(smraw);
    float* bias_s = reinterpret_cast<float*>(sw + OEND);

    int tid = threadIdx.x;
    int lane = tid & 31, warp = tid >> 5;

    for (int idx = tid; idx < 200 * 48; idx += 256) {
        int n = idx / 48, k = idx % 48;
        sw[O1 + n * KS1 + k] = __float2half((k < 33) ? w1[n * 33 + k] : 0.0f);
    }
    for (int idx = tid; idx < 200 * 208; idx += 256) {
        int n = idx / 208, k = idx % 208;
        sw[O2 + n * KS2 + k] = __float2half((k < 200) ? w2[n * 200 + k] : 0.0f);
    }
    for (int idx = tid; idx < 104 * 208; idx += 256) {
        int n = idx / 208, k = idx % 208;
        sw[O3 + n * KS2 + k] = __float2half((n < 100 && k < 200) ? w3[n * 200 + k] : 0.0f);
    }
    for (int i = tid; i < 200; i += 256) {
        bias_s[i] = b1[i];
        bias_s[200 + i] = b2[i];
    }
    for (int i = tid; i < 104; i += 256) bias_s[400 + i] = (i < 100) ? b3[i] : 0.0f;
    __syncthreads();

    const int k0 = (lane & 3) * 2;
    const int nrow = lane >> 2;
    const int gw = blockIdx.x * 8 + warp;
    const int gstride = gridDim.x * 8;

    for (int wt = gw; wt < 4096; wt += gstride) {
        const int row0 = wt * 16 + nrow;
        const int row1 = row0 + 8;
        const float* z0 = zern + (size_t)row0 * 35 + 2;
        const float* z1 = zern + (size_t)row1 * 35 + 2;

        float acc[25][4];
#pragma unroll
        for (int nt = 0; nt < 25; nt++)
#pragma unroll
            for (int q = 0; q < 4; q++) acc[nt][q] = 0.0f;

        // layer 1: K=33
#pragma unroll
        for (int kc = 0; kc < 3; kc++) {
            int kb = kc * 16 + k0;
            float x00 = (kb < 33) ? z0[kb] : 0.f;
            float x01 = (kb + 1 < 33) ? z0[kb + 1] : 0.f;
            float x10 = (kb < 33) ? z1[kb] : 0.f;
            float x11 = (kb + 1 < 33) ? z1[kb + 1] : 0.f;
            float x02 = (kb + 8 < 33) ? z0[kb + 8] : 0.f;
            float x03 = (kb + 9 < 33) ? z0[kb + 9] : 0.f;
            float x12 = (kb + 8 < 33) ? z1[kb + 8] : 0.f;
            float x13 = (kb + 9 < 33) ? z1[kb + 9] : 0.f;
            uint32_t ah0 = pack_h2(x00, x01);
            uint32_t ah1 = pack_h2(x10, x11);
            uint32_t ah2 = pack_h2(x02, x03);
            uint32_t ah3 = pack_h2(x12, x13);
#pragma unroll
            for (int nt = 0; nt < 25; nt++) {
                const __half* ph = sw + O1 + (nt * 8 + nrow) * KS1 + kc * 16 + k0;
                uint32_t bh0 = *reinterpret_cast<const uint32_t*>(ph);
                uint32_t bh1 = *reinterpret_cast<const uint32_t*>(ph + 8);
                mma_f16(acc[nt], ah0, ah1, ah2, ah3, bh0, bh1);
            }
        }

        uint32_t af[13][4];
#pragma unroll
        for (int kc = 0; kc < 13; kc++) {
            {
                int cc = kc * 16 + k0;
                float bv0 = bias_s[cc], bv1 = bias_s[cc + 1];
                af[kc][0] = pack_h2(lrelu(acc[2 * kc][0] + bv0), lrelu(acc[2 * kc][1] + bv1));
                af[kc][1] = pack_h2(lrelu(acc[2 * kc][2] + bv0), lrelu(acc[2 * kc][3] + bv1));
            }
            if (kc < 12) {
                int cc = kc * 16 + 8 + k0;
                float bv0 = bias_s[cc], bv1 = bias_s[cc + 1];
                af[kc][2] = pack_h2(lrelu(acc[2 * kc + 1][0] + bv0), lrelu(acc[2 * kc + 1][1] + bv1));
                af[kc][3] = pack_h2(lrelu(acc[2 * kc + 1][2] + bv0), lrelu(acc[2 * kc + 1][3] + bv1));
            } else {
                af[kc][2] = 0u;
                af[kc][3] = 0u;
            }
        }

        // layer 2
#pragma unroll
        for (int nt = 0; nt < 25; nt++)
#pragma unroll
            for (int q = 0; q < 4; q++) acc[nt][q] = 0.0f;
#pragma unroll
        for (int kc = 0; kc < 13; kc++) {
            uint32_t ah0 = af[kc][0], ah1 = af[kc][1], ah2 = af[kc][2], ah3 = af[kc][3];
#pragma unroll
            for (int nt = 0; nt < 25; nt++) {
                const __half* ph = sw + O2 + (nt * 8 + nrow) * KS2 + kc * 16 + k0;
                uint32_t bh0 = *reinterpret_cast<const uint32_t*>(ph);
                uint32_t bh1 = *reinterpret_cast<const uint32_t*>(ph + 8);
                mma_f16(acc[nt], ah0, ah1, ah2, ah3, bh0, bh1);
            }
        }

#pragma unroll
        for (int kc = 0; kc < 13; kc++) {
            {
                int cc = kc * 16 + k0;
                float bv0 = bias_s[200 + cc], bv1 = bias_s[200 + cc + 1];
                af[kc][0] = pack_h2(lrelu(acc[2 * kc][0] + bv0), lrelu(acc[2 * kc][1] + bv1));
                af[kc][1] = pack_h2(lrelu(acc[2 * kc][2] + bv0), lrelu(acc[2 * kc][3] + bv1));
            }
            if (kc < 12) {
                int cc = kc * 16 + 8 + k0;
                float bv0 = bias_s[200 + cc], bv1 = bias_s[200 + cc + 1];
                af[kc][2] = pack_h2(lrelu(acc[2 * kc + 1][0] + bv0), lrelu(acc[2 * kc + 1][1] + bv1));
                af[kc][3] = pack_h2(lrelu(acc[2 * kc + 1][2] + bv0), lrelu(acc[2 * kc + 1][3] + bv1));
            } else {
                af[kc][2] = 0u;
                af[kc][3] = 0u;
            }
        }

        // layer 3
        float acc3[13][4];
#pragma unroll
        for (int nt = 0; nt < 13; nt++)
#pragma unroll
            for (int q = 0; q < 4; q++) acc3[nt][q] = 0.0f;
#pragma unroll
        for (int kc = 0; kc < 13; kc++) {
            uint32_t ah0 = af[kc][0], ah1 = af[kc][1], ah2 = af[kc][2], ah3 = af[kc][3];
#pragma unroll
            for (int nt = 0; nt < 13; nt++) {
                const __half* ph = sw + O3 + (nt * 8 + nrow) * KS2 + kc * 16 + k0;
                uint32_t bh0 = *reinterpret_cast<const uint32_t*>(ph);
                uint32_t bh1 = *reinterpret_cast<const uint32_t*>(ph + 8);
                mma_f16(acc3[nt], ah0, ah1, ah2, ah3, bh0, bh1);
            }
        }

        float* c0 = coef + (size_t)row0 * 100;
        float* c1 = coef + (size_t)row1 * 100;
#pragma unroll
        for (int nt = 0; nt < 13; nt++) {
            int cc = nt * 8 + k0;
            if (cc < 100) {
                float bv0 = bias_s[400 + cc], bv1 = bias_s[400 + cc + 1];
                *reinterpret_cast<float2*>(c0 + cc) =
                    make_float2(acc3[nt][0] + bv0, acc3[nt][1] + bv1);
                *reinterpret_cast<float2*>(c1 + cc) =
                    make_float2(acc3[nt][2] + bv0, acc3[nt][3] + bv1);
            }
        }
    }
}

// ---------------- denominator mu constant ----------------
__global__ void k_denmu(const float* __restrict__ mu) {
    int tid = threadIdx.x;
    __shared__ float S[10];
    if (tid < 10) {
        float s = 0.f;
        for (int t = 0; t < 65; t++) s += mu[t * 10 + tid];
        S[tid] = s * s;
    }
    __syncthreads();
    if (tid == 0) {
        float d = 0.f;
        for (int m = 0; m < 10; m++) d += S[m];
        g_denmu = d;
    }
}

// ---------------- bilinear grid sample ----------------
__global__ void k_gridsample(const float* __restrict__ img, const float* __restrict__ zern) {
    int p = blockIdx.x * blockDim.x + threadIdx.x;
    if (p >= NPIX) return;
    int y = p >> 8, x = p & 255;
    float px = zern[p * 35 + 0], py = zern[p * 35 + 1];
    float fx = 2.0f * ((float)x + px) / 255.0f - 1.0f;
    float fy = 2.0f * ((float)y + py) / 255.0f - 1.0f;
    float ix = ((fx + 1.0f) * 256.0f - 1.0f) * 0.5f;
    float iy = ((fy + 1.0f) * 256.0f - 1.0f) * 0.5f;
    ix = fminf(fmaxf(ix, 0.f), 255.f);
    iy = fminf(fmaxf(iy, 0.f), 255.f);
    float x0f = floorf(ix), y0f = floorf(iy);
    float wx = ix - x0f, wy = iy - y0f;
    int x0 = (int)x0f, y0 = (int)y0f;
    int x1 = min(x0 + 1, 255), y1 = min(y0 + 1, 255);
#pragma unroll
    for (int c = 0; c < 3; c++) {
        const float* im = img + c * NPIX;
        float g00 = im[y0 * 256 + x0], g01 = im[y0 * 256 + x1];
        float g10 = im[y1 * 256 + x0], g11 = im[y1 * 256 + x1];
        float top = g00 * (1.f - wx) + g01 * wx;
        float bot = g10 * (1.f - wx) + g11 * wx;
        g_tilt[c * NPIX + p] = top * (1.f - wy) + bot * wy;
    }
}

// ---------------- vertical pass: 256 threads, tap-split x2, f32x2 math ----------------
// pid = tid&127 owns outputs (2*pid, 2*pid+1); grp = tid>>7 takes half the 66 window
// positions. Partials reduced through the coef smem region (reused as scratch).
__global__ __launch_bounds__(256, 2) void k_vert(const float* __restrict__ basis_left) {
    extern __shared__ float smv[];
    float* coefE = smv;
    float* coefO = smv + 128 * 102;
    float* tiltS = coefO + 128 * 102;
    float* Lsm = tiltS + 3 * 257;
    int w = blockIdx.x, tid = threadIdx.x;
    int pid = tid & 127, grp = tid >> 7;
    for (int i = tid; i < 650; i += 256) Lsm[i] = basis_left[i];
    for (int li = tid; li < 6400; li += 256) {
        int hh = li / 25, q = li % 25;
        float4 v = *(const float4*)&g_coef[(size_t)(hh * 256 + w) * 100 + q * 4];
        float* dst = ((hh & 1) ? coefO : coefE) + (hh >> 1) * 102 + q * 4;
        dst[0] = v.x; dst[1] = v.y; dst[2] = v.z; dst[3] = v.w;
    }
    for (int li = tid; li < 768; li += 256) {
        int k = li >> 8, hh = li & 255;
        tiltS[k * 257 + hh] = g_tilt[k * NPIX + hh * 256 + w];
    }
    __syncthreads();

    const int h1 = 2 * pid;
    const u64 ONEd = dup2(1.0f);
    u64 acc1p[20], acc2p[20];
#pragma unroll
    for (int p = 0; p < 20; p++) { acc1p[p] = 0ull; acc2p[p] = 0ull; }

    const int ro0 = grp * 33 - 32;  // grp0: [-32..0], grp1: [1..33]
#pragma unroll 2
    for (int it = 0; it < 33; it++) {
        int ro = ro0 + it;
        int r = h1 + ro;
        r = (r < 0) ? -r : ((r > 255) ? 510 - r : r);
        int t1 = ro + 32, t2 = ro + 31;
        bool va = (t1 <= 64), vb = (t2 >= 0);
        int t1c = va ? t1 : 64, t2c = vb ? t2 : 0;
        const u64* crow = reinterpret_cast<const u64*>(
            (((r & 1) ? coefO : coefE) + (r >> 1) * 102));
        u64 s1[5], s2[5];
#pragma unroll
        for (int u = 0; u < 5; u++) { s1[u] = 0ull; s2[u] = 0ull; }
#pragma unroll
        for (int i = 0; i < 10; i++) {
            float L1 = va ? Lsm[t1c * 10 + i] : 0.f;
            float L2 = vb ? Lsm[t2c * 10 + i] : 0.f;
            u64 L1d = dup2(L1), L2d = dup2(L2);
#pragma unroll
            for (int u = 0; u < 5; u++) {
                u64 cw = crow[i * 5 + u];
                fma2(s1[u], L1d, cw);
                fma2(s2[u], L2d, cw);
            }
        }
        u64 T0d = dup2(tiltS[r]), T1d = dup2(tiltS[257 + r]), T2d = dup2(tiltS[514 + r]);
#pragma unroll
        for (int u = 0; u < 5; u++) {
            fma2(acc1p[u], T0d, s1[u]);
            fma2(acc1p[5 + u], T1d, s1[u]);
            fma2(acc1p[10 + u], T2d, s1[u]);
            fma2(acc1p[15 + u], ONEd, s1[u]);
            fma2(acc2p[u], T0d, s2[u]);
            fma2(acc2p[5 + u], T1d, s2[u]);
            fma2(acc2p[10 + u], T2d, s2[u]);
            fma2(acc2p[15 + u], ONEd, s2[u]);
        }
    }

    // ---- cross-group reduction through coef smem (no longer needed) ----
    __syncthreads();
    u64* scr = reinterpret_cast<u64*>(smv);  // 40*128 u64 = 41KB <= coefE region
    if (grp == 1) {
#pragma unroll
        for (int q = 0; q < 20; q++) scr[q * 128 + pid] = acc1p[q];
#pragma unroll
        for (int q = 0; q < 20; q++) scr[(20 + q) * 128 + pid] = acc2p[q];
    }
    __syncthreads();
    if (grp == 0) {
#pragma unroll
        for (int q = 0; q < 20; q++) add2(acc1p[q], scr[q * 128 + pid]);
#pragma unroll
        for (int q = 0; q < 20; q++) add2(acc2p[q], scr[(20 + q) * 128 + pid]);
#pragma unroll
        for (int img = 0; img < 4; img++) {
#pragma unroll
            for (int u = 0; u < 5; u++) {
                float2 v1 = unpk(acc1p[img * 5 + u]);
                float2 v2 = unpk(acc2p[img * 5 + u]);
                int p = img * 10 + 2 * u;
                g_A[p * NPIX + h1 * 256 + w] = v1.x;
                g_A[(p + 1) * NPIX + h1 * 256 + w] = v1.y;
                g_A[p * NPIX + (h1 + 1) * 256 + w] = v2.x;
                g_A[(p + 1) * NPIX + (h1 + 1) * 256 + w] = v2.y;
            }
        }
    }
}

// ---------------- vertical mu pass (packed f32x2) ----------------
__global__ void k_vmu(const float* __restrict__ mu) {
    __shared__ __align__(16) float tiltS[3 * 257];
    __shared__ __align__(16) float Msm[650];
    int w = blockIdx.x, tid = threadIdx.x;
    for (int i = tid; i < 650; i += 256) Msm[i] = mu[i];
    for (int li = tid; li < 768; li += 256) {
        int k = li >> 8, hh = li & 255;
        tiltS[k * 257 + hh] = g_tilt[k * NPIX + hh * 256 + w];
    }
    __syncthreads();
    int h = tid;
    u64 accp[15];
#pragma unroll
    for (int q = 0; q < 15; q++) accp[q] = 0ull;
    for (int t = 0; t < 65; t++) {
        int r = h + t - 32;
        r = (r < 0) ? -r : ((r > 255) ? 510 - r : r);
        u64 T0d = dup2(tiltS[r]), T1d = dup2(tiltS[257 + r]), T2d = dup2(tiltS[514 + r]);
        const u64* mrow = reinterpret_cast<const u64*>(Msm + t * 10);
#pragma unroll
        for (int u = 0; u < 5; u++) {
            u64 mw = mrow[u];
            fma2(accp[u], T0d, mw);
            fma2(accp[5 + u], T1d, mw);
            fma2(accp[10 + u], T2d, mw);
        }
    }
#pragma unroll
    for (int img = 0; img < 3; img++) {
#pragma unroll
        for (int u = 0; u < 5; u++) {
            float2 v = unpk(accp[img * 5 + u]);
            int p = img * 10 + 2 * u;
            g_Bmu[p * NPIX + h * 256 + w] = v.x;
            g_Bmu[(p + 1) * NPIX + h * 256 + w] = v.y;
        }
    }
}

// ---------------- horizontal pass: 256 threads, ke-split x2 ----------------
__global__ __launch_bounds__(256) void k_horiz(const float* __restrict__ basis_right,
                                               const float* __restrict__ mu,
                                               float* __restrict__ out) {
    extern __shared__ float smh[];
    float* P = smh;
    float* Rsm = P + 70 * 258;
    float* Msm = Rsm + 650;
    int h = blockIdx.x, tid = threadIdx.x;
    int pid = tid & 127, grp = tid >> 7;
    for (int i = tid; i < 650; i += 256) {
        Rsm[i] = basis_right[i];
        Msm[i] = mu[i];
    }
    for (int p = 0; p < 40; p++)
        for (int c = tid; c < 256; c += 256) P[p * 258 + c] = g_A[p * NPIX + h * 256 + c];
    for (int p = 0; p < 30; p++)
        for (int c = tid; c < 256; c += 256) P[(40 + p) * 258 + c] = g_Bmu[p * NPIX + h * 256 + c];
    __syncthreads();

    const int w0 = 2 * pid;
    float n0a = 0, n0b = 0, n1a = 0, n1b = 0, n2a = 0, n2b = 0, dna = 0, dnb = 0;

    const int nke = grp ? 16 : 17;            // grp0: ke=0,2..32; grp1: ke=34,36..64
    for (int kk = 0; kk < nke; kk++) {
        int ke = grp ? (34 + 2 * kk) : (2 * kk);
        int c = w0 + ke - 32;
        bool fast = (c >= 0) && (c <= 254);
        int ca = (c < 0) ? -c : ((c > 255) ? 510 - c : c);
        int cd = c + 1;
        int cb = (cd < 0) ? -cd : ((cd > 255) ? 510 - cd : cd);

        float Rm[10], R0[10], Rp[10], Mm[10], M0[10], Mp[10];
#pragma unroll
        for (int j = 0; j < 10; j++) {
            R0[j] = Rsm[ke * 10 + j];
            M0[j] = Msm[ke * 10 + j];
            Rp[j] = (ke < 64) ? Rsm[(ke + 1) * 10 + j] : 0.f;
            Mp[j] = (ke < 64) ? Msm[(ke + 1) * 10 + j] : 0.f;
            Rm[j] = (ke > 0) ? Rsm[(ke - 1) * 10 + j] : 0.f;
            Mm[j] = (ke > 0) ? Msm[(ke - 1) * 10 + j] : 0.f;
        }
#pragma unroll
        for (int j = 0; j < 10; j++) {
            float2 g;
#define LOADP(p) (fast ? *(const float2*)&P[(p) * 258 + c] \
                       : make_float2(P[(p) * 258 + ca], P[(p) * 258 + cb]))
            g = LOADP(j);
            n0a += R0[j] * g.x + Rp[j] * g.y;  n0b += Rm[j] * g.x + R0[j] * g.y;
            g = LOADP(10 + j);
            n1a += R0[j] * g.x + Rp[j] * g.y;  n1b += Rm[j] * g.x + R0[j] * g.y;
            g = LOADP(20 + j);
            n2a += R0[j] * g.x + Rp[j] * g.y;  n2b += Rm[j] * g.x + R0[j] * g.y;
            g = LOADP(30 + j);
            dna += R0[j] * g.x + Rp[j] * g.y;  dnb += Rm[j] * g.x + R0[j] * g.y;
            g = LOADP(40 + j);
            n0a += M0[j] * g.x + Mp[j] * g.y;  n0b += Mm[j] * g.x + M0[j] * g.y;
            g = LOADP(50 + j);
            n1a += M0[j] * g.x + Mp[j] * g.y;  n1b += Mm[j] * g.x + M0[j] * g.y;
            g = LOADP(60 + j);
            n2a += M0[j] * g.x + Mp[j] * g.y;  n2b += Mm[j] * g.x + M0[j] * g.y;
#undef LOADP
        }
    }

    // ---- cross-group reduction through Rsm/Msm region (1300 floats >= 1024) ----
    __syncthreads();
    float* scr = Rsm;
    if (grp == 1) {
        scr[0 * 128 + pid] = n0a; scr[1 * 128 + pid] = n0b;
        scr[2 * 128 + pid] = n1a; scr[3 * 128 + pid] = n1b;
        scr[4 * 128 + pid] = n2a; scr[5 * 128 + pid] = n2b;
        scr[6 * 128 + pid] = dna; scr[7 * 128 + pid] = dnb;
    }
    __syncthreads();
    if (grp == 0) {
        n0a += scr[0 * 128 + pid]; n0b += scr[1 * 128 + pid];
        n1a += scr[2 * 128 + pid]; n1b += scr[3 * 128 + pid];
        n2a += scr[4 * 128 + pid]; n2b += scr[5 * 128 + pid];
        dna += scr[6 * 128 + pid]; dnb += scr[7 * 128 + pid];
        float dmu = g_denmu;
        dna += dmu;
        dnb += dmu;
        size_t base = (size_t)h * 256 + w0;
        *reinterpret_cast<float2*>(&out[0 * NPIX + base]) = make_float2(n0a / dna, n0b / dnb);
        *reinterpret_cast<float2*>(&out[1 * NPIX + base]) = make_float2(n1a / dna, n1b / dnb);
        *reinterpret_cast<float2*>(&out[2 * NPIX + base]) = make_float2(n2a / dna, n2b / dnb);
    }
}

// ---------------- launcher ----------------
extern "C" void kernel_launch(void* const* d_in, const int* in_sizes, int n_in,
                              void* d_out, int out_size) {
    const float* img  = (const float*)d_in[0];
    const float* zern = (const float*)d_in[1];
    const float* fc1w = (const float*)d_in[2];
    const float* fc1b = (const float*)d_in[3];
    const float* fc2w = (const float*)d_in[4];
    const float* fc2b = (const float*)d_in[5];
    const float* fc3w = (const float*)d_in[6];
    const float* fc3b = (const float*)d_in[7];
    const float* bl   = (const float*)d_in[8];
    const float* br   = (const float*)d_in[9];
    const float* mu   = (const float*)d_in[10];
    float* out = (float*)d_out;

    cudaFuncSetAttribute(k_mlp_fused, cudaFuncAttributeMaxDynamicSharedMemorySize, 155744);
    cudaFuncSetAttribute(k_vert, cudaFuncAttributeMaxDynamicSharedMemorySize, 110132);
    cudaFuncSetAttribute(k_horiz, cudaFuncAttributeMaxDynamicSharedMemorySize, 77440);

    float* coef;
    cudaGetSymbolAddress((void**)&coef, g_coef);

    k_denmu<<<1, 64>>>(mu);
    k_gridsample<<<256, 256>>>(img, zern);
    k_mlp_fused<<<148, 256, 155744>>>(zern, fc1w, fc1b, fc2w, fc2b, fc3w, fc3b, coef);
    k_vert<<<256, 256, 110132>>>(bl);
    k_vmu<<<256, 256>>>(mu);
    k_horiz<<<256, 256, 77440>>>(br, mu, out);
}

// round 13
// speedup vs baseline: 1.5808x; 1.0267x over previous
#include <cuda_runtime.h>
#include <cuda_fp16.h>
#include <cstdint>

#define NPIX 65536

typedef unsigned long long u64;

// ---------------- scratch (device globals; no allocation) ----------------
__device__ float g_tilt[3 * NPIX];
__device__ uint32_t g_coefh[(size_t)NPIX * 50];   // coef as half2 pairs (j even/odd)
__device__ float g_A[40 * NPIX];
__device__ float g_Bmu[30 * NPIX];
__device__ float g_denmu;

// ---------------- packed f32x2 helpers (Blackwell) ----------------
__device__ __forceinline__ void fma2(u64& d, u64 a, u64 b) {
    asm("fma.rn.f32x2 %0, %1, %2, %0;" : "+l"(d) : "l"(a), "l"(b));
}
__device__ __forceinline__ void add2(u64& d, u64 a) {
    asm("add.rn.f32x2 %0, %0, %1;" : "+l"(d) : "l"(a));
}
__device__ __forceinline__ u64 dup2(float x) {
    u64 d;
    asm("mov.b64 %0, {%1, %2};" : "=l"(d) : "f"(x), "f"(x));
    return d;
}
__device__ __forceinline__ u64 pk2(float x, float y) {
    u64 d;
    asm("mov.b64 %0, {%1, %2};" : "=l"(d) : "f"(x), "f"(y));
    return d;
}
__device__ __forceinline__ float2 unpk(u64 v) {
    float2 r;
    asm("mov.b64 {%0, %1}, %2;" : "=f"(r.x), "=f"(r.y) : "l"(v));
    return r;
}

// ---------------- warp-mma helpers ----------------
__device__ __forceinline__ void mma_f16(float* c, uint32_t a0, uint32_t a1, uint32_t a2,
                                        uint32_t a3, uint32_t b0, uint32_t b1) {
    asm volatile(
        "mma.sync.aligned.m16n8k16.row.col.f32.f16.f16.f32 "
        "{%0,%1,%2,%3}, {%4,%5,%6,%7}, {%8,%9}, {%0,%1,%2,%3};"
        : "+f"(c[0]), "+f"(c[1]), "+f"(c[2]), "+f"(c[3])
        : "r"(a0), "r"(a1), "r"(a2), "r"(a3), "r"(b0), "r"(b1));
}
__device__ __forceinline__ uint32_t pack_h2(float a, float b) {
    __half2 t;
    t.x = __float2half(a);
    t.y = __float2half(b);
    return *reinterpret_cast<uint32_t*>(&t);
}
__device__ __forceinline__ float lrelu(float v) { return v > 0.f ? v : 0.01f * v; }

// ================= fused 3-layer MLP, fragment-chained =================
__global__ __launch_bounds__(256, 1) void k_mlp_fused(
    const float* __restrict__ zern,
    const float* __restrict__ w1, const float* __restrict__ b1,
    const float* __restrict__ w2, const float* __restrict__ b2,
    const float* __restrict__ w3, const float* __restrict__ b3,
    uint32_t* __restrict__ coefh) {
    constexpr int KS1 = 56;
    constexpr int KS2 = 216;
    constexpr int O1 = 0;
    constexpr int O2 = O1 + 200 * KS1;
    constexpr int O3 = O2 + 200 * KS2;
    constexpr int OEND = O3 + 104 * KS2;

    extern __shared__ char smraw[];
    __half* sw = reinterpret_cast<__half*>(smraw);
    float* bias_s = reinterpret_cast<float*>(sw + OEND);

    int tid = threadIdx.x;
    int lane = tid & 31, warp = tid >> 5;

    for (int idx = tid; idx < 200 * 48; idx += 256) {
        int n = idx / 48, k = idx % 48;
        sw[O1 + n * KS1 + k] = __float2half((k < 33) ? w1[n * 33 + k] : 0.0f);
    }
    for (int idx = tid; idx < 200 * 208; idx += 256) {
        int n = idx / 208, k = idx % 208;
        sw[O2 + n * KS2 + k] = __float2half((k < 200) ? w2[n * 200 + k] : 0.0f);
    }
    for (int idx = tid; idx < 104 * 208; idx += 256) {
        int n = idx / 208, k = idx % 208;
        sw[O3 + n * KS2 + k] = __float2half((n < 100 && k < 200) ? w3[n * 200 + k] : 0.0f);
    }
    for (int i = tid; i < 200; i += 256) {
        bias_s[i] = b1[i];
        bias_s[200 + i] = b2[i];
    }
    for (int i = tid; i < 104; i += 256) bias_s[400 + i] = (i < 100) ? b3[i] : 0.0f;
    __syncthreads();

    const int k0 = (lane & 3) * 2;
    const int nrow = lane >> 2;
    const int gw = blockIdx.x * 8 + warp;
    const int gstride = gridDim.x * 8;

    for (int wt = gw; wt < 4096; wt += gstride) {
        const int row0 = wt * 16 + nrow;
        const int row1 = row0 + 8;
        const float* z0 = zern + (size_t)row0 * 35 + 2;
        const float* z1 = zern + (size_t)row1 * 35 + 2;

        float acc[25][4];
#pragma unroll
        for (int nt = 0; nt < 25; nt++)
#pragma unroll
            for (int q = 0; q < 4; q++) acc[nt][q] = 0.0f;

        // layer 1: K=33
#pragma unroll
        for (int kc = 0; kc < 3; kc++) {
            int kb = kc * 16 + k0;
            float x00 = (kb < 33) ? z0[kb] : 0.f;
            float x01 = (kb + 1 < 33) ? z0[kb + 1] : 0.f;
            float x10 = (kb < 33) ? z1[kb] : 0.f;
            float x11 = (kb + 1 < 33) ? z1[kb + 1] : 0.f;
            float x02 = (kb + 8 < 33) ? z0[kb + 8] : 0.f;
            float x03 = (kb + 9 < 33) ? z0[kb + 9] : 0.f;
            float x12 = (kb + 8 < 33) ? z1[kb + 8] : 0.f;
            float x13 = (kb + 9 < 33) ? z1[kb + 9] : 0.f;
            uint32_t ah0 = pack_h2(x00, x01);
            uint32_t ah1 = pack_h2(x10, x11);
            uint32_t ah2 = pack_h2(x02, x03);
            uint32_t ah3 = pack_h2(x12, x13);
#pragma unroll
            for (int nt = 0; nt < 25; nt++) {
                const __half* ph = sw + O1 + (nt * 8 + nrow) * KS1 + kc * 16 + k0;
                uint32_t bh0 = *reinterpret_cast<const uint32_t*>(ph);
                uint32_t bh1 = *reinterpret_cast<const uint32_t*>(ph + 8);
                mma_f16(acc[nt], ah0, ah1, ah2, ah3, bh0, bh1);
            }
        }

        uint32_t af[13][4];
#pragma unroll
        for (int kc = 0; kc < 13; kc++) {
            {
                int cc = kc * 16 + k0;
                float bv0 = bias_s[cc], bv1 = bias_s[cc + 1];
                af[kc][0] = pack_h2(lrelu(acc[2 * kc][0] + bv0), lrelu(acc[2 * kc][1] + bv1));
                af[kc][1] = pack_h2(lrelu(acc[2 * kc][2] + bv0), lrelu(acc[2 * kc][3] + bv1));
            }
            if (kc < 12) {
                int cc = kc * 16 + 8 + k0;
                float bv0 = bias_s[cc], bv1 = bias_s[cc + 1];
                af[kc][2] = pack_h2(lrelu(acc[2 * kc + 1][0] + bv0), lrelu(acc[2 * kc + 1][1] + bv1));
                af[kc][3] = pack_h2(lrelu(acc[2 * kc + 1][2] + bv0), lrelu(acc[2 * kc + 1][3] + bv1));
            } else {
                af[kc][2] = 0u;
                af[kc][3] = 0u;
            }
        }

        // layer 2
#pragma unroll
        for (int nt = 0; nt < 25; nt++)
#pragma unroll
            for (int q = 0; q < 4; q++) acc[nt][q] = 0.0f;
#pragma unroll
        for (int kc = 0; kc < 13; kc++) {
            uint32_t ah0 = af[kc][0], ah1 = af[kc][1], ah2 = af[kc][2], ah3 = af[kc][3];
#pragma unroll
            for (int nt = 0; nt < 25; nt++) {
                const __half* ph = sw + O2 + (nt * 8 + nrow) * KS2 + kc * 16 + k0;
                uint32_t bh0 = *reinterpret_cast<const uint32_t*>(ph);
                uint32_t bh1 = *reinterpret_cast<const uint32_t*>(ph + 8);
                mma_f16(acc[nt], ah0, ah1, ah2, ah3, bh0, bh1);
            }
        }

#pragma unroll
        for (int kc = 0; kc < 13; kc++) {
            {
                int cc = kc * 16 + k0;
                float bv0 = bias_s[200 + cc], bv1 = bias_s[200 + cc + 1];
                af[kc][0] = pack_h2(lrelu(acc[2 * kc][0] + bv0), lrelu(acc[2 * kc][1] + bv1));
                af[kc][1] = pack_h2(lrelu(acc[2 * kc][2] + bv0), lrelu(acc[2 * kc][3] + bv1));
            }
            if (kc < 12) {
                int cc = kc * 16 + 8 + k0;
                float bv0 = bias_s[200 + cc], bv1 = bias_s[200 + cc + 1];
                af[kc][2] = pack_h2(lrelu(acc[2 * kc + 1][0] + bv0), lrelu(acc[2 * kc + 1][1] + bv1));
                af[kc][3] = pack_h2(lrelu(acc[2 * kc + 1][2] + bv0), lrelu(acc[2 * kc + 1][3] + bv1));
            } else {
                af[kc][2] = 0u;
                af[kc][3] = 0u;
            }
        }

        // layer 3
        float acc3[13][4];
#pragma unroll
        for (int nt = 0; nt < 13; nt++)
#pragma unroll
            for (int q = 0; q < 4; q++) acc3[nt][q] = 0.0f;
#pragma unroll
        for (int kc = 0; kc < 13; kc++) {
            uint32_t ah0 = af[kc][0], ah1 = af[kc][1], ah2 = af[kc][2], ah3 = af[kc][3];
#pragma unroll
            for (int nt = 0; nt < 13; nt++) {
                const __half* ph = sw + O3 + (nt * 8 + nrow) * KS2 + kc * 16 + k0;
                uint32_t bh0 = *reinterpret_cast<const uint32_t*>(ph);
                uint32_t bh1 = *reinterpret_cast<const uint32_t*>(ph + 8);
                mma_f16(acc3[nt], ah0, ah1, ah2, ah3, bh0, bh1);
            }
        }

        // ---- epilogue: bias + pack to half2, store coef ----
        uint32_t* c0 = coefh + (size_t)row0 * 50;
        uint32_t* c1 = coefh + (size_t)row1 * 50;
#pragma unroll
        for (int nt = 0; nt < 13; nt++) {
            int cc = nt * 8 + k0;
            if (cc < 100) {
                float bv0 = bias_s[400 + cc], bv1 = bias_s[400 + cc + 1];
                c0[cc >> 1] = pack_h2(acc3[nt][0] + bv0, acc3[nt][1] + bv1);
                c1[cc >> 1] = pack_h2(acc3[nt][2] + bv0, acc3[nt][3] + bv1);
            }
        }
    }
}

// ---------------- denominator mu constant ----------------
__global__ void k_denmu(const float* __restrict__ mu) {
    int tid = threadIdx.x;
    __shared__ float S[10];
    if (tid < 10) {
        float s = 0.f;
        for (int t = 0; t < 65; t++) s += mu[t * 10 + tid];
        S[tid] = s * s;
    }
    __syncthreads();
    if (tid == 0) {
        float d = 0.f;
        for (int m = 0; m < 10; m++) d += S[m];
        g_denmu = d;
    }
}

// ---------------- bilinear grid sample ----------------
__global__ void k_gridsample(const float* __restrict__ img, const float* __restrict__ zern) {
    int p = blockIdx.x * blockDim.x + threadIdx.x;
    if (p >= NPIX) return;
    int y = p >> 8, x = p & 255;
    float px = zern[p * 35 + 0], py = zern[p * 35 + 1];
    float fx = 2.0f * ((float)x + px) / 255.0f - 1.0f;
    float fy = 2.0f * ((float)y + py) / 255.0f - 1.0f;
    float ix = ((fx + 1.0f) * 256.0f - 1.0f) * 0.5f;
    float iy = ((fy + 1.0f) * 256.0f - 1.0f) * 0.5f;
    ix = fminf(fmaxf(ix, 0.f), 255.f);
    iy = fminf(fmaxf(iy, 0.f), 255.f);
    float x0f = floorf(ix), y0f = floorf(iy);
    float wx = ix - x0f, wy = iy - y0f;
    int x0 = (int)x0f, y0 = (int)y0f;
    int x1 = min(x0 + 1, 255), y1 = min(y0 + 1, 255);
#pragma unroll
    for (int c = 0; c < 3; c++) {
        const float* im = img + c * NPIX;
        float g00 = im[y0 * 256 + x0], g01 = im[y0 * 256 + x1];
        float g10 = im[y1 * 256 + x0], g11 = im[y1 * 256 + x1];
        float top = g00 * (1.f - wx) + g01 * wx;
        float bot = g10 * (1.f - wx) + g11 * wx;
        g_tilt[c * NPIX + p] = top * (1.f - wy) + bot * wy;
    }
}

// ---------------- vertical pass: fp16 coef in smem, tap-split x2, f32x2 math ----------------
// coef staged as half2 words, parity-split (E/O), row stride 51 words (odd -> conflict-free).
__global__ __launch_bounds__(256, 2) void k_vert(const float* __restrict__ basis_left) {
    extern __shared__ uint32_t smw[];
    uint32_t* cE = smw;                       // 128*51 words
    uint32_t* cO = smw + 128 * 51;            // 128*51 words
    float* tiltS = reinterpret_cast<float*>(smw + 2 * 128 * 51);  // 3*257
    float* Lsm = tiltS + 3 * 257;                                 // 650
    int w = blockIdx.x, tid = threadIdx.x;
    int pid = tid & 127, grp = tid >> 7;
    for (int i = tid; i < 650; i += 256) Lsm[i] = basis_left[i];
    for (int li = tid; li < 12800; li += 256) {
        int hh = li / 50, q = li % 50;
        uint32_t v = g_coefh[(size_t)(hh * 256 + w) * 50 + q];
        ((hh & 1) ? cO : cE)[(hh >> 1) * 51 + q] = v;
    }
    for (int li = tid; li < 768; li += 256) {
        int k = li >> 8, hh = li & 255;
        tiltS[k * 257 + hh] = g_tilt[k * NPIX + hh * 256 + w];
    }
    __syncthreads();

    const int h1 = 2 * pid;
    const u64 ONEd = dup2(1.0f);
    u64 acc1p[20], acc2p[20];
#pragma unroll
    for (int p = 0; p < 20; p++) { acc1p[p] = 0ull; acc2p[p] = 0ull; }

    const int ro0 = grp * 33 - 32;  // grp0: [-32..0], grp1: [1..33]
#pragma unroll 2
    for (int it = 0; it < 33; it++) {
        int ro = ro0 + it;
        int r = h1 + ro;
        r = (r < 0) ? -r : ((r > 255) ? 510 - r : r);
        int t1 = ro + 32, t2 = ro + 31;
        bool va = (t1 <= 64), vb = (t2 >= 0);
        int t1c = va ? t1 : 64, t2c = vb ? t2 : 0;
        const uint32_t* crow = ((r & 1) ? cO : cE) + (r >> 1) * 51;
        u64 s1[5], s2[5];
#pragma unroll
        for (int u = 0; u < 5; u++) { s1[u] = 0ull; s2[u] = 0ull; }
#pragma unroll
        for (int i = 0; i < 10; i++) {
            float L1 = va ? Lsm[t1c * 10 + i] : 0.f;
            float L2 = vb ? Lsm[t2c * 10 + i] : 0.f;
            u64 L1d = dup2(L1), L2d = dup2(L2);
#pragma unroll
            for (int u = 0; u < 5; u++) {
                uint32_t hv = crow[i * 5 + u];
                float2 cf = __half22float2(*reinterpret_cast<const __half2*>(&hv));
                u64 cw = pk2(cf.x, cf.y);
                fma2(s1[u], L1d, cw);
                fma2(s2[u], L2d, cw);
            }
        }
        u64 T0d = dup2(tiltS[r]), T1d = dup2(tiltS[257 + r]), T2d = dup2(tiltS[514 + r]);
#pragma unroll
        for (int u = 0; u < 5; u++) {
            fma2(acc1p[u], T0d, s1[u]);
            fma2(acc1p[5 + u], T1d, s1[u]);
            fma2(acc1p[10 + u], T2d, s1[u]);
            fma2(acc1p[15 + u], ONEd, s1[u]);
            fma2(acc2p[u], T0d, s2[u]);
            fma2(acc2p[5 + u], T1d, s2[u]);
            fma2(acc2p[10 + u], T2d, s2[u]);
            fma2(acc2p[15 + u], ONEd, s2[u]);
        }
    }

    // ---- cross-group reduction through the coef smem region (no longer needed) ----
    __syncthreads();
    u64* scr = reinterpret_cast<u64*>(smw);   // 40*128 u64 = 40960B <= 52224B coef region
    if (grp == 1) {
#pragma unroll
        for (int q = 0; q < 20; q++) scr[q * 128 + pid] = acc1p[q];
#pragma unroll
        for (int q = 0; q < 20; q++) scr[(20 + q) * 128 + pid] = acc2p[q];
    }
    __syncthreads();
    if (grp == 0) {
#pragma unroll
        for (int q = 0; q < 20; q++) add2(acc1p[q], scr[q * 128 + pid]);
#pragma unroll
        for (int q = 0; q < 20; q++) add2(acc2p[q], scr[(20 + q) * 128 + pid]);
#pragma unroll
        for (int img = 0; img < 4; img++) {
#pragma unroll
            for (int u = 0; u < 5; u++) {
                float2 v1 = unpk(acc1p[img * 5 + u]);
                float2 v2 = unpk(acc2p[img * 5 + u]);
                int p = img * 10 + 2 * u;
                g_A[p * NPIX + h1 * 256 + w] = v1.x;
                g_A[(p + 1) * NPIX + h1 * 256 + w] = v1.y;
                g_A[p * NPIX + (h1 + 1) * 256 + w] = v2.x;
                g_A[(p + 1) * NPIX + (h1 + 1) * 256 + w] = v2.y;
            }
        }
    }
}

// ---------------- vertical mu pass (packed f32x2) ----------------
__global__ void k_vmu(const float* __restrict__ mu) {
    __shared__ __align__(16) float tiltS[3 * 257];
    __shared__ __align__(16) float Msm[650];
    int w = blockIdx.x, tid = threadIdx.x;
    for (int i = tid; i < 650; i += 256) Msm[i] = mu[i];
    for (int li = tid; li < 768; li += 256) {
        int k = li >> 8, hh = li & 255;
        tiltS[k * 257 + hh] = g_tilt[k * NPIX + hh * 256 + w];
    }
    __syncthreads();
    int h = tid;
    u64 accp[15];
#pragma unroll
    for (int q = 0; q < 15; q++) accp[q] = 0ull;
    for (int t = 0; t < 65; t++) {
        int r = h + t - 32;
        r = (r < 0) ? -r : ((r > 255) ? 510 - r : r);
        u64 T0d = dup2(tiltS[r]), T1d = dup2(tiltS[257 + r]), T2d = dup2(tiltS[514 + r]);
        const u64* mrow = reinterpret_cast<const u64*>(Msm + t * 10);
#pragma unroll
        for (int u = 0; u < 5; u++) {
            u64 mw = mrow[u];
            fma2(accp[u], T0d, mw);
            fma2(accp[5 + u], T1d, mw);
            fma2(accp[10 + u], T2d, mw);
        }
    }
#pragma unroll
    for (int img = 0; img < 3; img++) {
#pragma unroll
        for (int u = 0; u < 5; u++) {
            float2 v = unpk(accp[img * 5 + u]);
            int p = img * 10 + 2 * u;
            g_Bmu[p * NPIX + h * 256 + w] = v.x;
            g_Bmu[(p + 1) * NPIX + h * 256 + w] = v.y;
        }
    }
}

// ---------------- horizontal pass: 256 threads, ke-split x2 ----------------
__global__ __launch_bounds__(256) void k_horiz(const float* __restrict__ basis_right,
                                               const float* __restrict__ mu,
                                               float* __restrict__ out) {
    extern __shared__ float smh[];
    float* P = smh;
    float* Rsm = P + 70 * 258;
    float* Msm = Rsm + 650;
    int h = blockIdx.x, tid = threadIdx.x;
    int pid = tid & 127, grp = tid >> 7;
    for (int i = tid; i < 650; i += 256) {
        Rsm[i] = basis_right[i];
        Msm[i] = mu[i];
    }
    for (int p = 0; p < 40; p++)
        for (int c = tid; c < 256; c += 256) P[p * 258 + c] = g_A[p * NPIX + h * 256 + c];
    for (int p = 0; p < 30; p++)
        for (int c = tid; c < 256; c += 256) P[(40 + p) * 258 + c] = g_Bmu[p * NPIX + h * 256 + c];
    __syncthreads();

    const int w0 = 2 * pid;
    float n0a = 0, n0b = 0, n1a = 0, n1b = 0, n2a = 0, n2b = 0, dna = 0, dnb = 0;

    const int nke = grp ? 16 : 17;
    for (int kk = 0; kk < nke; kk++) {
        int ke = grp ? (34 + 2 * kk) : (2 * kk);
        int c = w0 + ke - 32;
        bool fast = (c >= 0) && (c <= 254);
        int ca = (c < 0) ? -c : ((c > 255) ? 510 - c : c);
        int cd = c + 1;
        int cb = (cd < 0) ? -cd : ((cd > 255) ? 510 - cd : cd);

        float Rm[10], R0[10], Rp[10], Mm[10], M0[10], Mp[10];
#pragma unroll
        for (int j = 0; j < 10; j++) {
            R0[j] = Rsm[ke * 10 + j];
            M0[j] = Msm[ke * 10 + j];
            Rp[j] = (ke < 64) ? Rsm[(ke + 1) * 10 + j] : 0.f;
            Mp[j] = (ke < 64) ? Msm[(ke + 1) * 10 + j] : 0.f;
            Rm[j] = (ke > 0) ? Rsm[(ke - 1) * 10 + j] : 0.f;
            Mm[j] = (ke > 0) ? Msm[(ke - 1) * 10 + j] : 0.f;
        }
#pragma unroll
        for (int j = 0; j < 10; j++) {
            float2 g;
#define LOADP(p) (fast ? *(const float2*)&P[(p) * 258 + c] \
                       : make_float2(P[(p) * 258 + ca], P[(p) * 258 + cb]))
            g = LOADP(j);
            n0a += R0[j] * g.x + Rp[j] * g.y;  n0b += Rm[j] * g.x + R0[j] * g.y;
            g = LOADP(10 + j);
            n1a += R0[j] * g.x + Rp[j] * g.y;  n1b += Rm[j] * g.x + R0[j] * g.y;
            g = LOADP(20 + j);
            n2a += R0[j] * g.x + Rp[j] * g.y;  n2b += Rm[j] * g.x + R0[j] * g.y;
            g = LOADP(30 + j);
            dna += R0[j] * g.x + Rp[j] * g.y;  dnb += Rm[j] * g.x + R0[j] * g.y;
            g = LOADP(40 + j);
            n0a += M0[j] * g.x + Mp[j] * g.y;  n0b += Mm[j] * g.x + M0[j] * g.y;
            g = LOADP(50 + j);
            n1a += M0[j] * g.x + Mp[j] * g.y;  n1b += Mm[j] * g.x + M0[j] * g.y;
            g = LOADP(60 + j);
            n2a += M0[j] * g.x + Mp[j] * g.y;  n2b += Mm[j] * g.x + M0[j] * g.y;
#undef LOADP
        }
    }

    __syncthreads();
    float* scr = Rsm;
    if (grp == 1) {
        scr[0 * 128 + pid] = n0a; scr[1 * 128 + pid] = n0b;
        scr[2 * 128 + pid] = n1a; scr[3 * 128 + pid] = n1b;
        scr[4 * 128 + pid] = n2a; scr[5 * 128 + pid] = n2b;
        scr[6 * 128 + pid] = dna; scr[7 * 128 + pid] = dnb;
    }
    __syncthreads();
    if (grp == 0) {
        n0a += scr[0 * 128 + pid]; n0b += scr[1 * 128 + pid];
        n1a += scr[2 * 128 + pid]; n1b += scr[3 * 128 + pid];
        n2a += scr[4 * 128 + pid]; n2b += scr[5 * 128 + pid];
        dna += scr[6 * 128 + pid]; dnb += scr[7 * 128 + pid];
        float dmu = g_denmu;
        dna += dmu;
        dnb += dmu;
        size_t base = (size_t)h * 256 + w0;
        *reinterpret_cast<float2*>(&out[0 * NPIX + base]) = make_float2(n0a / dna, n0b / dnb);
        *reinterpret_cast<float2*>(&out[1 * NPIX + base]) = make_float2(n1a / dna, n1b / dnb);
        *reinterpret_cast<float2*>(&out[2 * NPIX + base]) = make_float2(n2a / dna, n2b / dnb);
    }
}

// ---------------- launcher ----------------
extern "C" void kernel_launch(void* const* d_in, const int* in_sizes, int n_in,
                              void* d_out, int out_size) {
    const float* img  = (const float*)d_in[0];
    const float* zern = (const float*)d_in[1];
    const float* fc1w = (const float*)d_in[2];
    const float* fc1b = (const float*)d_in[3];
    const float* fc2w = (const float*)d_in[4];
    const float* fc2b = (const float*)d_in[5];
    const float* fc3w = (const float*)d_in[6];
    const float* fc3b = (const float*)d_in[7];
    const float* bl   = (const float*)d_in[8];
    const float* br   = (const float*)d_in[9];
    const float* mu   = (const float*)d_in[10];
    float* out = (float*)d_out;

    // k_vert smem: 2*128*51*4 + (3*257 + 650)*4 = 52224 + 5684 = 57908
    cudaFuncSetAttribute(k_mlp_fused, cudaFuncAttributeMaxDynamicSharedMemorySize, 155744);
    cudaFuncSetAttribute(k_vert, cudaFuncAttributeMaxDynamicSharedMemorySize, 57908);
    cudaFuncSetAttribute(k_horiz, cudaFuncAttributeMaxDynamicSharedMemorySize, 77440);

    uint32_t* coefh;
    cudaGetSymbolAddress((void**)&coefh, g_coefh);

    k_denmu<<<1, 64>>>(mu);
    k_gridsample<<<256, 256>>>(img, zern);
    k_mlp_fused<<<148, 256, 155744>>>(zern, fc1w, fc1b, fc2w, fc2b, fc3w, fc3b, coefh);
    k_vert<<<256, 256, 57908>>>(bl);
    k_vmu<<<256, 256>>>(mu);
    k_horiz<<<256, 256, 77440>>>(br, mu, out);
}

// round 14
// speedup vs baseline: 1.6923x; 1.0706x over previous
#include <cuda_runtime.h>
#include <cuda_fp16.h>
#include <cstdint>

#define NPIX 65536

typedef unsigned long long u64;

// ---------------- scratch (device globals; no allocation) ----------------
__device__ float g_tilt[3 * NPIX];
__device__ uint32_t g_coefh[(size_t)NPIX * 50];   // coef as half2 pairs (j even/odd)
__device__ float g_A[40 * NPIX];
__device__ float g_Bmu[30 * NPIX];
__device__ float g_denmu;

// ---------------- packed f32x2 helpers (Blackwell) ----------------
__device__ __forceinline__ void fma2(u64& d, u64 a, u64 b) {
    asm("fma.rn.f32x2 %0, %1, %2, %0;" : "+l"(d) : "l"(a), "l"(b));
}
__device__ __forceinline__ void add2(u64& d, u64 a) {
    asm("add.rn.f32x2 %0, %0, %1;" : "+l"(d) : "l"(a));
}
__device__ __forceinline__ u64 dup2(float x) {
    u64 d;
    asm("mov.b64 %0, {%1, %2};" : "=l"(d) : "f"(x), "f"(x));
    return d;
}
__device__ __forceinline__ u64 pk2(float x, float y) {
    u64 d;
    asm("mov.b64 %0, {%1, %2};" : "=l"(d) : "f"(x), "f"(y));
    return d;
}
__device__ __forceinline__ float2 unpk(u64 v) {
    float2 r;
    asm("mov.b64 {%0, %1}, %2;" : "=f"(r.x), "=f"(r.y) : "l"(v));
    return r;
}

// ---------------- warp-mma helpers ----------------
__device__ __forceinline__ void mma_f16(float* c, uint32_t a0, uint32_t a1, uint32_t a2,
                                        uint32_t a3, uint32_t b0, uint32_t b1) {
    asm volatile(
        "mma.sync.aligned.m16n8k16.row.col.f32.f16.f16.f32 "
        "{%0,%1,%2,%3}, {%4,%5,%6,%7}, {%8,%9}, {%0,%1,%2,%3};"
        : "+f"(c[0]), "+f"(c[1]), "+f"(c[2]), "+f"(c[3])
        : "r"(a0), "r"(a1), "r"(a2), "r"(a3), "r"(b0), "r"(b1));
}
__device__ __forceinline__ uint32_t pack_h2(float a, float b) {
    __half2 t;
    t.x = __float2half(a);
    t.y = __float2half(b);
    return *reinterpret_cast<uint32_t*>(&t);
}
__device__ __forceinline__ float lrelu(float v) { return v > 0.f ? v : 0.01f * v; }

// ================= fused 3-layer MLP, fragment-chained =================
__global__ __launch_bounds__(256, 1) void k_mlp_fused(
    const float* __restrict__ zern,
    const float* __restrict__ w1, const float* __restrict__ b1,
    const float* __restrict__ w2, const float* __restrict__ b2,
    const float* __restrict__ w3, const float* __restrict__ b3,
    uint32_t* __restrict__ coefh) {
    constexpr int KS1 = 56;
    constexpr int KS2 = 216;
    constexpr int O1 = 0;
    constexpr int O2 = O1 + 200 * KS1;
    constexpr int O3 = O2 + 200 * KS2;
    constexpr int OEND = O3 + 104 * KS2;

    extern __shared__ char smraw[];
    __half* sw = reinterpret_cast<__half*>(smraw);
    float* bias_s = reinterpret_cast<float*>(sw + OEND);

    int tid = threadIdx.x;
    int lane = tid & 31, warp = tid >> 5;

    for (int idx = tid; idx < 200 * 48; idx += 256) {
        int n = idx / 48, k = idx % 48;
        sw[O1 + n * KS1 + k] = __float2half((k < 33) ? w1[n * 33 + k] : 0.0f);
    }
    for (int idx = tid; idx < 200 * 208; idx += 256) {
        int n = idx / 208, k = idx % 208;
        sw[O2 + n * KS2 + k] = __float2half((k < 200) ? w2[n * 200 + k] : 0.0f);
    }
    for (int idx = tid; idx < 104 * 208; idx += 256) {
        int n = idx / 208, k = idx % 208;
        sw[O3 + n * KS2 + k] = __float2half((n < 100 && k < 200) ? w3[n * 200 + k] : 0.0f);
    }
    for (int i = tid; i < 200; i += 256) {
        bias_s[i] = b1[i];
        bias_s[200 + i] = b2[i];
    }
    for (int i = tid; i < 104; i += 256) bias_s[400 + i] = (i < 100) ? b3[i] : 0.0f;
    __syncthreads();

    const int k0 = (lane & 3) * 2;
    const int nrow = lane >> 2;
    const int gw = blockIdx.x * 8 + warp;
    const int gstride = gridDim.x * 8;

    for (int wt = gw; wt < 4096; wt += gstride) {
        const int row0 = wt * 16 + nrow;
        const int row1 = row0 + 8;
        const float* z0 = zern + (size_t)row0 * 35 + 2;
        const float* z1 = zern + (size_t)row1 * 35 + 2;

        float acc[25][4];
#pragma unroll
        for (int nt = 0; nt < 25; nt++)
#pragma unroll
            for (int q = 0; q < 4; q++) acc[nt][q] = 0.0f;

        // layer 1: K=33
#pragma unroll
        for (int kc = 0; kc < 3; kc++) {
            int kb = kc * 16 + k0;
            float x00 = (kb < 33) ? z0[kb] : 0.f;
            float x01 = (kb + 1 < 33) ? z0[kb + 1] : 0.f;
            float x10 = (kb < 33) ? z1[kb] : 0.f;
            float x11 = (kb + 1 < 33) ? z1[kb + 1] : 0.f;
            float x02 = (kb + 8 < 33) ? z0[kb + 8] : 0.f;
            float x03 = (kb + 9 < 33) ? z0[kb + 9] : 0.f;
            float x12 = (kb + 8 < 33) ? z1[kb + 8] : 0.f;
            float x13 = (kb + 9 < 33) ? z1[kb + 9] : 0.f;
            uint32_t ah0 = pack_h2(x00, x01);
            uint32_t ah1 = pack_h2(x10, x11);
            uint32_t ah2 = pack_h2(x02, x03);
            uint32_t ah3 = pack_h2(x12, x13);
#pragma unroll
            for (int nt = 0; nt < 25; nt++) {
                const __half* ph = sw + O1 + (nt * 8 + nrow) * KS1 + kc * 16 + k0;
                uint32_t bh0 = *reinterpret_cast<const uint32_t*>(ph);
                uint32_t bh1 = *reinterpret_cast<const uint32_t*>(ph + 8);
                mma_f16(acc[nt], ah0, ah1, ah2, ah3, bh0, bh1);
            }
        }

        uint32_t af[13][4];
#pragma unroll
        for (int kc = 0; kc < 13; kc++) {
            {
                int cc = kc * 16 + k0;
                float bv0 = bias_s[cc], bv1 = bias_s[cc + 1];
                af[kc][0] = pack_h2(lrelu(acc[2 * kc][0] + bv0), lrelu(acc[2 * kc][1] + bv1));
                af[kc][1] = pack_h2(lrelu(acc[2 * kc][2] + bv0), lrelu(acc[2 * kc][3] + bv1));
            }
            if (kc < 12) {
                int cc = kc * 16 + 8 + k0;
                float bv0 = bias_s[cc], bv1 = bias_s[cc + 1];
                af[kc][2] = pack_h2(lrelu(acc[2 * kc + 1][0] + bv0), lrelu(acc[2 * kc + 1][1] + bv1));
                af[kc][3] = pack_h2(lrelu(acc[2 * kc + 1][2] + bv0), lrelu(acc[2 * kc + 1][3] + bv1));
            } else {
                af[kc][2] = 0u;
                af[kc][3] = 0u;
            }
        }

        // layer 2
#pragma unroll
        for (int nt = 0; nt < 25; nt++)
#pragma unroll
            for (int q = 0; q < 4; q++) acc[nt][q] = 0.0f;
#pragma unroll
        for (int kc = 0; kc < 13; kc++) {
            uint32_t ah0 = af[kc][0], ah1 = af[kc][1], ah2 = af[kc][2], ah3 = af[kc][3];
#pragma unroll
            for (int nt = 0; nt < 25; nt++) {
                const __half* ph = sw + O2 + (nt * 8 + nrow) * KS2 + kc * 16 + k0;
                uint32_t bh0 = *reinterpret_cast<const uint32_t*>(ph);
                uint32_t bh1 = *reinterpret_cast<const uint32_t*>(ph + 8);
                mma_f16(acc[nt], ah0, ah1, ah2, ah3, bh0, bh1);
            }
        }

#pragma unroll
        for (int kc = 0; kc < 13; kc++) {
            {
                int cc = kc * 16 + k0;
                float bv0 = bias_s[200 + cc], bv1 = bias_s[200 + cc + 1];
                af[kc][0] = pack_h2(lrelu(acc[2 * kc][0] + bv0), lrelu(acc[2 * kc][1] + bv1));
                af[kc][1] = pack_h2(lrelu(acc[2 * kc][2] + bv0), lrelu(acc[2 * kc][3] + bv1));
            }
            if (kc < 12) {
                int cc = kc * 16 + 8 + k0;
                float bv0 = bias_s[200 + cc], bv1 = bias_s[200 + cc + 1];
                af[kc][2] = pack_h2(lrelu(acc[2 * kc + 1][0] + bv0), lrelu(acc[2 * kc + 1][1] + bv1));
                af[kc][3] = pack_h2(lrelu(acc[2 * kc + 1][2] + bv0), lrelu(acc[2 * kc + 1][3] + bv1));
            } else {
                af[kc][2] = 0u;
                af[kc][3] = 0u;
            }
        }

        // layer 3
        float acc3[13][4];
#pragma unroll
        for (int nt = 0; nt < 13; nt++)
#pragma unroll
            for (int q = 0; q < 4; q++) acc3[nt][q] = 0.0f;
#pragma unroll
        for (int kc = 0; kc < 13; kc++) {
            uint32_t ah0 = af[kc][0], ah1 = af[kc][1], ah2 = af[kc][2], ah3 = af[kc][3];
#pragma unroll
            for (int nt = 0; nt < 13; nt++) {
                const __half* ph = sw + O3 + (nt * 8 + nrow) * KS2 + kc * 16 + k0;
                uint32_t bh0 = *reinterpret_cast<const uint32_t*>(ph);
                uint32_t bh1 = *reinterpret_cast<const uint32_t*>(ph + 8);
                mma_f16(acc3[nt], ah0, ah1, ah2, ah3, bh0, bh1);
            }
        }

        // ---- epilogue: bias + pack to half2, store coef ----
        uint32_t* c0 = coefh + (size_t)row0 * 50;
        uint32_t* c1 = coefh + (size_t)row1 * 50;
#pragma unroll
        for (int nt = 0; nt < 13; nt++) {
            int cc = nt * 8 + k0;
            if (cc < 100) {
                float bv0 = bias_s[400 + cc], bv1 = bias_s[400 + cc + 1];
                c0[cc >> 1] = pack_h2(acc3[nt][0] + bv0, acc3[nt][1] + bv1);
                c1[cc >> 1] = pack_h2(acc3[nt][2] + bv0, acc3[nt][3] + bv1);
            }
        }
    }
}

// ---------------- denominator mu constant ----------------
__global__ void k_denmu(const float* __restrict__ mu) {
    int tid = threadIdx.x;
    __shared__ float S[10];
    if (tid < 10) {
        float s = 0.f;
        for (int t = 0; t < 65; t++) s += mu[t * 10 + tid];
        S[tid] = s * s;
    }
    __syncthreads();
    if (tid == 0) {
        float d = 0.f;
        for (int m = 0; m < 10; m++) d += S[m];
        g_denmu = d;
    }
}

// ---------------- bilinear grid sample ----------------
__global__ void k_gridsample(const float* __restrict__ img, const float* __restrict__ zern) {
    int p = blockIdx.x * blockDim.x + threadIdx.x;
    if (p >= NPIX) return;
    int y = p >> 8, x = p & 255;
    float px = zern[p * 35 + 0], py = zern[p * 35 + 1];
    float fx = 2.0f * ((float)x + px) / 255.0f - 1.0f;
    float fy = 2.0f * ((float)y + py) / 255.0f - 1.0f;
    float ix = ((fx + 1.0f) * 256.0f - 1.0f) * 0.5f;
    float iy = ((fy + 1.0f) * 256.0f - 1.0f) * 0.5f;
    ix = fminf(fmaxf(ix, 0.f), 255.f);
    iy = fminf(fmaxf(iy, 0.f), 255.f);
    float x0f = floorf(ix), y0f = floorf(iy);
    float wx = ix - x0f, wy = iy - y0f;
    int x0 = (int)x0f, y0 = (int)y0f;
    int x1 = min(x0 + 1, 255), y1 = min(y0 + 1, 255);
#pragma unroll
    for (int c = 0; c < 3; c++) {
        const float* im = img + c * NPIX;
        float g00 = im[y0 * 256 + x0], g01 = im[y0 * 256 + x1];
        float g10 = im[y1 * 256 + x0], g11 = im[y1 * 256 + x1];
        float top = g00 * (1.f - wx) + g01 * wx;
        float bot = g10 * (1.f - wx) + g11 * wx;
        g_tilt[c * NPIX + p] = top * (1.f - wy) + bot * wy;
    }
}

// ---------------- vertical pass: fp16 coef + HFMA2 s-stage, tap-split x2 ----------------
// s_j(r,t) = sum_i L[t,i]*coef_ij(r) computed in half2 (j-pairs); accumulators fp32x2.
__global__ __launch_bounds__(256, 2) void k_vert(const float* __restrict__ basis_left) {
    extern __shared__ uint32_t smw[];
    uint32_t* cE = smw;                       // 128*51 words (half2 coef, even rows)
    uint32_t* cO = smw + 128 * 51;            // odd rows
    float* tiltS = reinterpret_cast<float*>(smw + 2 * 128 * 51);  // 3*257
    uint32_t* Lh = reinterpret_cast<uint32_t*>(tiltS + 3 * 257);  // 650 half2-dup
    int w = blockIdx.x, tid = threadIdx.x;
    int pid = tid & 127, grp = tid >> 7;
    for (int i = tid; i < 650; i += 256) {
        __half hv = __float2half(basis_left[i]);
        __half2 d2; d2.x = hv; d2.y = hv;
        Lh[i] = *reinterpret_cast<uint32_t*>(&d2);
    }
    for (int li = tid; li < 12800; li += 256) {
        int hh = li / 50, q = li % 50;
        uint32_t v = g_coefh[(size_t)(hh * 256 + w) * 50 + q];
        ((hh & 1) ? cO : cE)[(hh >> 1) * 51 + q] = v;
    }
    for (int li = tid; li < 768; li += 256) {
        int k = li >> 8, hh = li & 255;
        tiltS[k * 257 + hh] = g_tilt[k * NPIX + hh * 256 + w];
    }
    __syncthreads();

    const int h1 = 2 * pid;
    const u64 ONEd = dup2(1.0f);
    const __half2 HZERO = __float2half2_rn(0.0f);
    u64 acc1p[20], acc2p[20];
#pragma unroll
    for (int p = 0; p < 20; p++) { acc1p[p] = 0ull; acc2p[p] = 0ull; }

    const int ro0 = grp * 33 - 32;  // grp0: [-32..0], grp1: [1..33]
#pragma unroll 2
    for (int it = 0; it < 33; it++) {
        int ro = ro0 + it;
        int r = h1 + ro;
        r = (r < 0) ? -r : ((r > 255) ? 510 - r : r);
        int t1 = ro + 32, t2 = ro + 31;
        bool va = (t1 <= 64), vb = (t2 >= 0);
        int t1c = va ? t1 : 64, t2c = vb ? t2 : 0;
        const uint32_t* crow = ((r & 1) ? cO : cE) + (r >> 1) * 51;
        __half2 s1h[5], s2h[5];
#pragma unroll
        for (int u = 0; u < 5; u++) { s1h[u] = HZERO; s2h[u] = HZERO; }
#pragma unroll
        for (int i = 0; i < 10; i++) {
            uint32_t l1w = Lh[t1c * 10 + i];
            uint32_t l2w = Lh[t2c * 10 + i];
            __half2 L1 = va ? *reinterpret_cast<__half2*>(&l1w) : HZERO;
            __half2 L2 = vb ? *reinterpret_cast<__half2*>(&l2w) : HZERO;
#pragma unroll
            for (int u = 0; u < 5; u++) {
                uint32_t cwu = crow[i * 5 + u];
                __half2 cw = *reinterpret_cast<__half2*>(&cwu);
                s1h[u] = __hfma2(L1, cw, s1h[u]);
                s2h[u] = __hfma2(L2, cw, s2h[u]);
            }
        }
        u64 T0d = dup2(tiltS[r]), T1d = dup2(tiltS[257 + r]), T2d = dup2(tiltS[514 + r]);
#pragma unroll
        for (int u = 0; u < 5; u++) {
            float2 f1 = __half22float2(s1h[u]);
            float2 f2 = __half22float2(s2h[u]);
            u64 s1w = pk2(f1.x, f1.y);
            u64 s2w = pk2(f2.x, f2.y);
            fma2(acc1p[u], T0d, s1w);
            fma2(acc1p[5 + u], T1d, s1w);
            fma2(acc1p[10 + u], T2d, s1w);
            fma2(acc1p[15 + u], ONEd, s1w);
            fma2(acc2p[u], T0d, s2w);
            fma2(acc2p[5 + u], T1d, s2w);
            fma2(acc2p[10 + u], T2d, s2w);
            fma2(acc2p[15 + u], ONEd, s2w);
        }
    }

    // ---- cross-group reduction through the coef smem region (no longer needed) ----
    __syncthreads();
    u64* scr = reinterpret_cast<u64*>(smw);   // 40*128 u64 = 40960B <= coef region
    if (grp == 1) {
#pragma unroll
        for (int q = 0; q < 20; q++) scr[q * 128 + pid] = acc1p[q];
#pragma unroll
        for (int q = 0; q < 20; q++) scr[(20 + q) * 128 + pid] = acc2p[q];
    }
    __syncthreads();
    if (grp == 0) {
#pragma unroll
        for (int q = 0; q < 20; q++) add2(acc1p[q], scr[q * 128 + pid]);
#pragma unroll
        for (int q = 0; q < 20; q++) add2(acc2p[q], scr[(20 + q) * 128 + pid]);
#pragma unroll
        for (int img = 0; img < 4; img++) {
#pragma unroll
            for (int u = 0; u < 5; u++) {
                float2 v1 = unpk(acc1p[img * 5 + u]);
                float2 v2 = unpk(acc2p[img * 5 + u]);
                int p = img * 10 + 2 * u;
                g_A[p * NPIX + h1 * 256 + w] = v1.x;
                g_A[(p + 1) * NPIX + h1 * 256 + w] = v1.y;
                g_A[p * NPIX + (h1 + 1) * 256 + w] = v2.x;
                g_A[(p + 1) * NPIX + (h1 + 1) * 256 + w] = v2.y;
            }
        }
    }
}

// ---------------- vertical mu pass (packed f32x2) ----------------
__global__ void k_vmu(const float* __restrict__ mu) {
    __shared__ __align__(16) float tiltS[3 * 257];
    __shared__ __align__(16) float Msm[650];
    int w = blockIdx.x, tid = threadIdx.x;
    for (int i = tid; i < 650; i += 256) Msm[i] = mu[i];
    for (int li = tid; li < 768; li += 256) {
        int k = li >> 8, hh = li & 255;
        tiltS[k * 257 + hh] = g_tilt[k * NPIX + hh * 256 + w];
    }
    __syncthreads();
    int h = tid;
    u64 accp[15];
#pragma unroll
    for (int q = 0; q < 15; q++) accp[q] = 0ull;
    for (int t = 0; t < 65; t++) {
        int r = h + t - 32;
        r = (r < 0) ? -r : ((r > 255) ? 510 - r : r);
        u64 T0d = dup2(tiltS[r]), T1d = dup2(tiltS[257 + r]), T2d = dup2(tiltS[514 + r]);
        const u64* mrow = reinterpret_cast<const u64*>(Msm + t * 10);
#pragma unroll
        for (int u = 0; u < 5; u++) {
            u64 mw = mrow[u];
            fma2(accp[u], T0d, mw);
            fma2(accp[5 + u], T1d, mw);
            fma2(accp[10 + u], T2d, mw);
        }
    }
#pragma unroll
    for (int img = 0; img < 3; img++) {
#pragma unroll
        for (int u = 0; u < 5; u++) {
            float2 v = unpk(accp[img * 5 + u]);
            int p = img * 10 + 2 * u;
            g_Bmu[p * NPIX + h * 256 + w] = v.x;
            g_Bmu[(p + 1) * NPIX + h * 256 + w] = v.y;
        }
    }
}

// ---------------- horizontal pass: 256 threads, ke-split x2 ----------------
__global__ __launch_bounds__(256) void k_horiz(const float* __restrict__ basis_right,
                                               const float* __restrict__ mu,
                                               float* __restrict__ out) {
    extern __shared__ float smh[];
    float* P = smh;
    float* Rsm = P + 70 * 258;
    float* Msm = Rsm + 650;
    int h = blockIdx.x, tid = threadIdx.x;
    int pid = tid & 127, grp = tid >> 7;
    for (int i = tid; i < 650; i += 256) {
        Rsm[i] = basis_right[i];
        Msm[i] = mu[i];
    }
    for (int p = 0; p < 40; p++)
        for (int c = tid; c < 256; c += 256) P[p * 258 + c] = g_A[p * NPIX + h * 256 + c];
    for (int p = 0; p < 30; p++)
        for (int c = tid; c < 256; c += 256) P[(40 + p) * 258 + c] = g_Bmu[p * NPIX + h * 256 + c];
    __syncthreads();

    const int w0 = 2 * pid;
    float n0a = 0, n0b = 0, n1a = 0, n1b = 0, n2a = 0, n2b = 0, dna = 0, dnb = 0;

    const int nke = grp ? 16 : 17;
    for (int kk = 0; kk < nke; kk++) {
        int ke = grp ? (34 + 2 * kk) : (2 * kk);
        int c = w0 + ke - 32;
        bool fast = (c >= 0) && (c <= 254);
        int ca = (c < 0) ? -c : ((c > 255) ? 510 - c : c);
        int cd = c + 1;
        int cb = (cd < 0) ? -cd : ((cd > 255) ? 510 - cd : cd);

        float Rm[10], R0[10], Rp[10], Mm[10], M0[10], Mp[10];
#pragma unroll
        for (int j = 0; j < 10; j++) {
            R0[j] = Rsm[ke * 10 + j];
            M0[j] = Msm[ke * 10 + j];
            Rp[j] = (ke < 64) ? Rsm[(ke + 1) * 10 + j] : 0.f;
            Mp[j] = (ke < 64) ? Msm[(ke + 1) * 10 + j] : 0.f;
            Rm[j] = (ke > 0) ? Rsm[(ke - 1) * 10 + j] : 0.f;
            Mm[j] = (ke > 0) ? Msm[(ke - 1) * 10 + j] : 0.f;
        }
#pragma unroll
        for (int j = 0; j < 10; j++) {
            float2 g;
#define LOADP(p) (fast ? *(const float2*)&P[(p) * 258 + c] \
                       : make_float2(P[(p) * 258 + ca], P[(p) * 258 + cb]))
            g = LOADP(j);
            n0a += R0[j] * g.x + Rp[j] * g.y;  n0b += Rm[j] * g.x + R0[j] * g.y;
            g = LOADP(10 + j);
            n1a += R0[j] * g.x + Rp[j] * g.y;  n1b += Rm[j] * g.x + R0[j] * g.y;
            g = LOADP(20 + j);
            n2a += R0[j] * g.x + Rp[j] * g.y;  n2b += Rm[j] * g.x + R0[j] * g.y;
            g = LOADP(30 + j);
            dna += R0[j] * g.x + Rp[j] * g.y;  dnb += Rm[j] * g.x + R0[j] * g.y;
            g = LOADP(40 + j);
            n0a += M0[j] * g.x + Mp[j] * g.y;  n0b += Mm[j] * g.x + M0[j] * g.y;
            g = LOADP(50 + j);
            n1a += M0[j] * g.x + Mp[j] * g.y;  n1b += Mm[j] * g.x + M0[j] * g.y;
            g = LOADP(60 + j);
            n2a += M0[j] * g.x + Mp[j] * g.y;  n2b += Mm[j] * g.x + M0[j] * g.y;
#undef LOADP
        }
    }

    __syncthreads();
    float* scr = Rsm;
    if (grp == 1) {
        scr[0 * 128 + pid] = n0a; scr[1 * 128 + pid] = n0b;
        scr[2 * 128 + pid] = n1a; scr[3 * 128 + pid] = n1b;
        scr[4 * 128 + pid] = n2a; scr[5 * 128 + pid] = n2b;
        scr[6 * 128 + pid] = dna; scr[7 * 128 + pid] = dnb;
    }
    __syncthreads();
    if (grp == 0) {
        n0a += scr[0 * 128 + pid]; n0b += scr[1 * 128 + pid];
        n1a += scr[2 * 128 + pid]; n1b += scr[3 * 128 + pid];
        n2a += scr[4 * 128 + pid]; n2b += scr[5 * 128 + pid];
        dna += scr[6 * 128 + pid]; dnb += scr[7 * 128 + pid];
        float dmu = g_denmu;
        dna += dmu;
        dnb += dmu;
        size_t base = (size_t)h * 256 + w0;
        *reinterpret_cast<float2*>(&out[0 * NPIX + base]) = make_float2(n0a / dna, n0b / dnb);
        *reinterpret_cast<float2*>(&out[1 * NPIX + base]) = make_float2(n1a / dna, n1b / dnb);
        *reinterpret_cast<float2*>(&out[2 * NPIX + base]) = make_float2(n2a / dna, n2b / dnb);
    }
}

// ---------------- launcher ----------------
extern "C" void kernel_launch(void* const* d_in, const int* in_sizes, int n_in,
                              void* d_out, int out_size) {
    const float* img  = (const float*)d_in[0];
    const float* zern = (const float*)d_in[1];
    const float* fc1w = (const float*)d_in[2];
    const float* fc1b = (const float*)d_in[3];
    const float* fc2w = (const float*)d_in[4];
    const float* fc2b = (const float*)d_in[5];
    const float* fc3w = (const float*)d_in[6];
    const float* fc3b = (const float*)d_in[7];
    const float* bl   = (const float*)d_in[8];
    const float* br   = (const float*)d_in[9];
    const float* mu   = (const float*)d_in[10];
    float* out = (float*)d_out;

    // k_vert smem: 2*128*51*4 + 3*257*4 + 650*4 = 52224 + 3084 + 2600 = 57908
    cudaFuncSetAttribute(k_mlp_fused, cudaFuncAttributeMaxDynamicSharedMemorySize, 155744);
    cudaFuncSetAttribute(k_vert, cudaFuncAttributeMaxDynamicSharedMemorySize, 57908);
    cudaFuncSetAttribute(k_horiz, cudaFuncAttributeMaxDynamicSharedMemorySize, 77440);

    uint32_t* coefh;
    cudaGetSymbolAddress((void**)&coefh, g_coefh);

    k_denmu<<<1, 64>>>(mu);
    k_gridsample<<<256, 256>>>(img, zern);
    k_mlp_fused<<<148, 256, 155744>>>(zern, fc1w, fc1b, fc2w, fc2b, fc3w, fc3b, coefh);
    k_vert<<<256, 256, 57908>>>(bl);
    k_vmu<<<256, 256>>>(mu);
    k_horiz<<<256, 256, 77440>>>(br, mu, out);
}

// round 15
// speedup vs baseline: 1.7130x; 1.0122x over previous
#include <cuda_runtime.h>
#include <cuda_fp16.h>
#include <cstdint>

#define NPIX 65536

typedef unsigned long long u64;

// ---------------- scratch (device globals; no allocation) ----------------
__device__ float g_tilt[3 * NPIX];
__device__ uint32_t g_coefh[(size_t)NPIX * 50];   // coef as half2 pairs (j even/odd)
__device__ float g_A[40 * NPIX];
__device__ float g_Bmu[30 * NPIX];
__device__ float g_denmu;

// ---------------- packed f32x2 helpers (Blackwell) ----------------
__device__ __forceinline__ void fma2(u64& d, u64 a, u64 b) {
    asm("fma.rn.f32x2 %0, %1, %2, %0;" : "+l"(d) : "l"(a), "l"(b));
}
__device__ __forceinline__ void add2(u64& d, u64 a) {
    asm("add.rn.f32x2 %0, %0, %1;" : "+l"(d) : "l"(a));
}
__device__ __forceinline__ u64 dup2(float x) {
    u64 d;
    asm("mov.b64 %0, {%1, %2};" : "=l"(d) : "f"(x), "f"(x));
    return d;
}
__device__ __forceinline__ u64 pk2(float x, float y) {
    u64 d;
    asm("mov.b64 %0, {%1, %2};" : "=l"(d) : "f"(x), "f"(y));
    return d;
}
__device__ __forceinline__ float2 unpk(u64 v) {
    float2 r;
    asm("mov.b64 {%0, %1}, %2;" : "=f"(r.x), "=f"(r.y) : "l"(v));
    return r;
}

// ---------------- warp-mma helpers ----------------
__device__ __forceinline__ void mma_f16(float* c, uint32_t a0, uint32_t a1, uint32_t a2,
                                        uint32_t a3, uint32_t b0, uint32_t b1) {
    asm volatile(
        "mma.sync.aligned.m16n8k16.row.col.f32.f16.f16.f32 "
        "{%0,%1,%2,%3}, {%4,%5,%6,%7}, {%8,%9}, {%0,%1,%2,%3};"
        : "+f"(c[0]), "+f"(c[1]), "+f"(c[2]), "+f"(c[3])
        : "r"(a0), "r"(a1), "r"(a2), "r"(a3), "r"(b0), "r"(b1));
}
__device__ __forceinline__ uint32_t pack_h2(float a, float b) {
    __half2 t;
    t.x = __float2half(a);
    t.y = __float2half(b);
    return *reinterpret_cast<uint32_t*>(&t);
}
__device__ __forceinline__ float lrelu(float v) { return v > 0.f ? v : 0.01f * v; }

// ================= fused 3-layer MLP, fragment-chained =================
__global__ __launch_bounds__(256, 1) void k_mlp_fused(
    const float* __restrict__ zern,
    const float* __restrict__ w1, const float* __restrict__ b1,
    const float* __restrict__ w2, const float* __restrict__ b2,
    const float* __restrict__ w3, const float* __restrict__ b3,
    uint32_t* __restrict__ coefh) {
    constexpr int KS1 = 56;
    constexpr int KS2 = 216;
    constexpr int O1 = 0;
    constexpr int O2 = O1 + 200 * KS1;
    constexpr int O3 = O2 + 200 * KS2;
    constexpr int OEND = O3 + 104 * KS2;

    extern __shared__ char smraw[];
    __half* sw = reinterpret_cast<__half*>(smraw);
    float* bias_s = reinterpret_cast<float*>(sw + OEND);

    int tid = threadIdx.x;
    int lane = tid & 31, warp = tid >> 5;

    for (int idx = tid; idx < 200 * 48; idx += 256) {
        int n = idx / 48, k = idx % 48;
        sw[O1 + n * KS1 + k] = __float2half((k < 33) ? w1[n * 33 + k] : 0.0f);
    }
    for (int idx = tid; idx < 200 * 208; idx += 256) {
        int n = idx / 208, k = idx % 208;
        sw[O2 + n * KS2 + k] = __float2half((k < 200) ? w2[n * 200 + k] : 0.0f);
    }
    for (int idx = tid; idx < 104 * 208; idx += 256) {
        int n = idx / 208, k = idx % 208;
        sw[O3 + n * KS2 + k] = __float2half((n < 100 && k < 200) ? w3[n * 200 + k] : 0.0f);
    }
    for (int i = tid; i < 200; i += 256) {
        bias_s[i] = b1[i];
        bias_s[200 + i] = b2[i];
    }
    for (int i = tid; i < 104; i += 256) bias_s[400 + i] = (i < 100) ? b3[i] : 0.0f;
    __syncthreads();

    const int k0 = (lane & 3) * 2;
    const int nrow = lane >> 2;
    const int gw = blockIdx.x * 8 + warp;
    const int gstride = gridDim.x * 8;

    for (int wt = gw; wt < 4096; wt += gstride) {
        const int row0 = wt * 16 + nrow;
        const int row1 = row0 + 8;
        const float* z0 = zern + (size_t)row0 * 35 + 2;
        const float* z1 = zern + (size_t)row1 * 35 + 2;

        float acc[25][4];
#pragma unroll
        for (int nt = 0; nt < 25; nt++)
#pragma unroll
            for (int q = 0; q < 4; q++) acc[nt][q] = 0.0f;

        // layer 1: K=33
#pragma unroll
        for (int kc = 0; kc < 3; kc++) {
            int kb = kc * 16 + k0;
            float x00 = (kb < 33) ? z0[kb] : 0.f;
            float x01 = (kb + 1 < 33) ? z0[kb + 1] : 0.f;
            float x10 = (kb < 33) ? z1[kb] : 0.f;
            float x11 = (kb + 1 < 33) ? z1[kb + 1] : 0.f;
            float x02 = (kb + 8 < 33) ? z0[kb + 8] : 0.f;
            float x03 = (kb + 9 < 33) ? z0[kb + 9] : 0.f;
            float x12 = (kb + 8 < 33) ? z1[kb + 8] : 0.f;
            float x13 = (kb + 9 < 33) ? z1[kb + 9] : 0.f;
            uint32_t ah0 = pack_h2(x00, x01);
            uint32_t ah1 = pack_h2(x10, x11);
            uint32_t ah2 = pack_h2(x02, x03);
            uint32_t ah3 = pack_h2(x12, x13);
#pragma unroll
            for (int nt = 0; nt < 25; nt++) {
                const __half* ph = sw + O1 + (nt * 8 + nrow) * KS1 + kc * 16 + k0;
                uint32_t bh0 = *reinterpret_cast<const uint32_t*>(ph);
                uint32_t bh1 = *reinterpret_cast<const uint32_t*>(ph + 8);
                mma_f16(acc[nt], ah0, ah1, ah2, ah3, bh0, bh1);
            }
        }

        uint32_t af[13][4];
#pragma unroll
        for (int kc = 0; kc < 13; kc++) {
            {
                int cc = kc * 16 + k0;
                float bv0 = bias_s[cc], bv1 = bias_s[cc + 1];
                af[kc][0] = pack_h2(lrelu(acc[2 * kc][0] + bv0), lrelu(acc[2 * kc][1] + bv1));
                af[kc][1] = pack_h2(lrelu(acc[2 * kc][2] + bv0), lrelu(acc[2 * kc][3] + bv1));
            }
            if (kc < 12) {
                int cc = kc * 16 + 8 + k0;
                float bv0 = bias_s[cc], bv1 = bias_s[cc + 1];
                af[kc][2] = pack_h2(lrelu(acc[2 * kc + 1][0] + bv0), lrelu(acc[2 * kc + 1][1] + bv1));
                af[kc][3] = pack_h2(lrelu(acc[2 * kc + 1][2] + bv0), lrelu(acc[2 * kc + 1][3] + bv1));
            } else {
                af[kc][2] = 0u;
                af[kc][3] = 0u;
            }
        }

        // layer 2
#pragma unroll
        for (int nt = 0; nt < 25; nt++)
#pragma unroll
            for (int q = 0; q < 4; q++) acc[nt][q] = 0.0f;
#pragma unroll
        for (int kc = 0; kc < 13; kc++) {
            uint32_t ah0 = af[kc][0], ah1 = af[kc][1], ah2 = af[kc][2], ah3 = af[kc][3];
#pragma unroll
            for (int nt = 0; nt < 25; nt++) {
                const __half* ph = sw + O2 + (nt * 8 + nrow) * KS2 + kc * 16 + k0;
                uint32_t bh0 = *reinterpret_cast<const uint32_t*>(ph);
                uint32_t bh1 = *reinterpret_cast<const uint32_t*>(ph + 8);
                mma_f16(acc[nt], ah0, ah1, ah2, ah3, bh0, bh1);
            }
        }

#pragma unroll
        for (int kc = 0; kc < 13; kc++) {
            {
                int cc = kc * 16 + k0;
                float bv0 = bias_s[200 + cc], bv1 = bias_s[200 + cc + 1];
                af[kc][0] = pack_h2(lrelu(acc[2 * kc][0] + bv0), lrelu(acc[2 * kc][1] + bv1));
                af[kc][1] = pack_h2(lrelu(acc[2 * kc][2] + bv0), lrelu(acc[2 * kc][3] + bv1));
            }
            if (kc < 12) {
                int cc = kc * 16 + 8 + k0;
                float bv0 = bias_s[200 + cc], bv1 = bias_s[200 + cc + 1];
                af[kc][2] = pack_h2(lrelu(acc[2 * kc + 1][0] + bv0), lrelu(acc[2 * kc + 1][1] + bv1));
                af[kc][3] = pack_h2(lrelu(acc[2 * kc + 1][2] + bv0), lrelu(acc[2 * kc + 1][3] + bv1));
            } else {
                af[kc][2] = 0u;
                af[kc][3] = 0u;
            }
        }

        // layer 3
        float acc3[13][4];
#pragma unroll
        for (int nt = 0; nt < 13; nt++)
#pragma unroll
            for (int q = 0; q < 4; q++) acc3[nt][q] = 0.0f;
#pragma unroll
        for (int kc = 0; kc < 13; kc++) {
            uint32_t ah0 = af[kc][0], ah1 = af[kc][1], ah2 = af[kc][2], ah3 = af[kc][3];
#pragma unroll
            for (int nt = 0; nt < 13; nt++) {
                const __half* ph = sw + O3 + (nt * 8 + nrow) * KS2 + kc * 16 + k0;
                uint32_t bh0 = *reinterpret_cast<const uint32_t*>(ph);
                uint32_t bh1 = *reinterpret_cast<const uint32_t*>(ph + 8);
                mma_f16(acc3[nt], ah0, ah1, ah2, ah3, bh0, bh1);
            }
        }

        // ---- epilogue: bias + pack to half2, store coef ----
        uint32_t* c0 = coefh + (size_t)row0 * 50;
        uint32_t* c1 = coefh + (size_t)row1 * 50;
#pragma unroll
        for (int nt = 0; nt < 13; nt++) {
            int cc = nt * 8 + k0;
            if (cc < 100) {
                float bv0 = bias_s[400 + cc], bv1 = bias_s[400 + cc + 1];
                c0[cc >> 1] = pack_h2(acc3[nt][0] + bv0, acc3[nt][1] + bv1);
                c1[cc >> 1] = pack_h2(acc3[nt][2] + bv0, acc3[nt][3] + bv1);
            }
        }
    }
}

// ---------------- bilinear grid sample ----------------
__global__ void k_gridsample(const float* __restrict__ img, const float* __restrict__ zern) {
    int p = blockIdx.x * blockDim.x + threadIdx.x;
    if (p >= NPIX) return;
    int y = p >> 8, x = p & 255;
    float px = zern[p * 35 + 0], py = zern[p * 35 + 1];
    float fx = 2.0f * ((float)x + px) / 255.0f - 1.0f;
    float fy = 2.0f * ((float)y + py) / 255.0f - 1.0f;
    float ix = ((fx + 1.0f) * 256.0f - 1.0f) * 0.5f;
    float iy = ((fy + 1.0f) * 256.0f - 1.0f) * 0.5f;
    ix = fminf(fmaxf(ix, 0.f), 255.f);
    iy = fminf(fmaxf(iy, 0.f), 255.f);
    float x0f = floorf(ix), y0f = floorf(iy);
    float wx = ix - x0f, wy = iy - y0f;
    int x0 = (int)x0f, y0 = (int)y0f;
    int x1 = min(x0 + 1, 255), y1 = min(y0 + 1, 255);
#pragma unroll
    for (int c = 0; c < 3; c++) {
        const float* im = img + c * NPIX;
        float g00 = im[y0 * 256 + x0], g01 = im[y0 * 256 + x1];
        float g10 = im[y1 * 256 + x0], g11 = im[y1 * 256 + x1];
        float top = g00 * (1.f - wx) + g01 * wx;
        float bot = g10 * (1.f - wx) + g11 * wx;
        g_tilt[c * NPIX + p] = top * (1.f - wy) + bot * wy;
    }
}

// ---------------- vertical pass: fp16 coef + HFMA2 s-stage, zero-padded L ----------------
__global__ __launch_bounds__(256, 2) void k_vert(const float* __restrict__ basis_left) {
    extern __shared__ uint32_t smw[];
    uint32_t* cE = smw;                       // 128*51 words (half2 coef, even rows)
    uint32_t* cO = smw + 128 * 51;            // odd rows
    uint32_t* Lh = smw + 2 * 128 * 51;        // 670 half2-dup, rows 0 and 66 zero
    float* tiltS = reinterpret_cast<float*>(Lh + 670);  // 3*257
    int w = blockIdx.x, tid = threadIdx.x;
    int pid = tid & 127, grp = tid >> 7;
    for (int i = tid; i < 670; i += 256) {
        int row = i / 10, col = i % 10;
        float v = (row >= 1 && row <= 65) ? basis_left[(row - 1) * 10 + col] : 0.0f;
        __half hv = __float2half(v);
        __half2 d2; d2.x = hv; d2.y = hv;
        Lh[i] = *reinterpret_cast<uint32_t*>(&d2);
    }
    for (int li = tid; li < 12800; li += 256) {
        int hh = li / 50, q = li % 50;
        uint32_t v = g_coefh[(size_t)(hh * 256 + w) * 50 + q];
        ((hh & 1) ? cO : cE)[(hh >> 1) * 51 + q] = v;
    }
    for (int li = tid; li < 768; li += 256) {
        int k = li >> 8, hh = li & 255;
        tiltS[k * 257 + hh] = g_tilt[k * NPIX + hh * 256 + w];
    }
    __syncthreads();

    const int h1 = 2 * pid;
    const u64 ONEd = dup2(1.0f);
    const __half2 HZERO = __float2half2_rn(0.0f);
    u64 acc1p[20], acc2p[20];
#pragma unroll
    for (int p = 0; p < 20; p++) { acc1p[p] = 0ull; acc2p[p] = 0ull; }

    const int ro0 = grp * 33 - 32;  // grp0: [-32..0], grp1: [1..33]
#pragma unroll 2
    for (int it = 0; it < 33; it++) {
        int ro = ro0 + it;
        int r = h1 + ro;
        r = (r < 0) ? -r : ((r > 255) ? 510 - r : r);
        int t1p = ro + 33, t2p = ro + 32;   // padded L indices (rows 0/66 are zero)
        const uint32_t* crow = ((r & 1) ? cO : cE) + (r >> 1) * 51;
        __half2 s1h[5], s2h[5];
#pragma unroll
        for (int u = 0; u < 5; u++) { s1h[u] = HZERO; s2h[u] = HZERO; }
#pragma unroll
        for (int i = 0; i < 10; i++) {
            uint32_t l1w = Lh[t1p * 10 + i];
            uint32_t l2w = Lh[t2p * 10 + i];
            __half2 L1 = *reinterpret_cast<__half2*>(&l1w);
            __half2 L2 = *reinterpret_cast<__half2*>(&l2w);
#pragma unroll
            for (int u = 0; u < 5; u++) {
                uint32_t cwu = crow[i * 5 + u];
                __half2 cw = *reinterpret_cast<__half2*>(&cwu);
                s1h[u] = __hfma2(L1, cw, s1h[u]);
                s2h[u] = __hfma2(L2, cw, s2h[u]);
            }
        }
        u64 T0d = dup2(tiltS[r]), T1d = dup2(tiltS[257 + r]), T2d = dup2(tiltS[514 + r]);
#pragma unroll
        for (int u = 0; u < 5; u++) {
            float2 f1 = __half22float2(s1h[u]);
            float2 f2 = __half22float2(s2h[u]);
            u64 s1w = pk2(f1.x, f1.y);
            u64 s2w = pk2(f2.x, f2.y);
            fma2(acc1p[u], T0d, s1w);
            fma2(acc1p[5 + u], T1d, s1w);
            fma2(acc1p[10 + u], T2d, s1w);
            fma2(acc1p[15 + u], ONEd, s1w);
            fma2(acc2p[u], T0d, s2w);
            fma2(acc2p[5 + u], T1d, s2w);
            fma2(acc2p[10 + u], T2d, s2w);
            fma2(acc2p[15 + u], ONEd, s2w);
        }
    }

    // ---- cross-group reduction through the coef smem region ----
    __syncthreads();
    u64* scr = reinterpret_cast<u64*>(smw);
    if (grp == 1) {
#pragma unroll
        for (int q = 0; q < 20; q++) scr[q * 128 + pid] = acc1p[q];
#pragma unroll
        for (int q = 0; q < 20; q++) scr[(20 + q) * 128 + pid] = acc2p[q];
    }
    __syncthreads();
    if (grp == 0) {
#pragma unroll
        for (int q = 0; q < 20; q++) add2(acc1p[q], scr[q * 128 + pid]);
#pragma unroll
        for (int q = 0; q < 20; q++) add2(acc2p[q], scr[(20 + q) * 128 + pid]);
#pragma unroll
        for (int img = 0; img < 4; img++) {
#pragma unroll
            for (int u = 0; u < 5; u++) {
                float2 v1 = unpk(acc1p[img * 5 + u]);
                float2 v2 = unpk(acc2p[img * 5 + u]);
                int p = img * 10 + 2 * u;
                g_A[p * NPIX + h1 * 256 + w] = v1.x;
                g_A[(p + 1) * NPIX + h1 * 256 + w] = v1.y;
                g_A[p * NPIX + (h1 + 1) * 256 + w] = v2.x;
                g_A[(p + 1) * NPIX + (h1 + 1) * 256 + w] = v2.y;
            }
        }
    }
}

// ---------------- vertical mu pass (+ denominator constant in block 0) ----------------
__global__ void k_vmu(const float* __restrict__ mu) {
    __shared__ __align__(16) float tiltS[3 * 257];
    __shared__ __align__(16) float Msm[650];
    __shared__ float S2[10];
    int w = blockIdx.x, tid = threadIdx.x;
    for (int i = tid; i < 650; i += 256) Msm[i] = mu[i];
    for (int li = tid; li < 768; li += 256) {
        int k = li >> 8, hh = li & 255;
        tiltS[k * 257 + hh] = g_tilt[k * NPIX + hh * 256 + w];
    }
    if (w == 0 && tid < 10) {
        float s = 0.f;
        for (int t = 0; t < 65; t++) s += mu[t * 10 + tid];
        S2[tid] = s * s;
    }
    __syncthreads();
    if (w == 0 && tid == 0) {
        float d = 0.f;
        for (int m = 0; m < 10; m++) d += S2[m];
        g_denmu = d;
    }
    int h = tid;
    u64 accp[15];
#pragma unroll
    for (int q = 0; q < 15; q++) accp[q] = 0ull;
    for (int t = 0; t < 65; t++) {
        int r = h + t - 32;
        r = (r < 0) ? -r : ((r > 255) ? 510 - r : r);
        u64 T0d = dup2(tiltS[r]), T1d = dup2(tiltS[257 + r]), T2d = dup2(tiltS[514 + r]);
        const u64* mrow = reinterpret_cast<const u64*>(Msm + t * 10);
#pragma unroll
        for (int u = 0; u < 5; u++) {
            u64 mw = mrow[u];
            fma2(accp[u], T0d, mw);
            fma2(accp[5 + u], T1d, mw);
            fma2(accp[10 + u], T2d, mw);
        }
    }
#pragma unroll
    for (int img = 0; img < 3; img++) {
#pragma unroll
        for (int u = 0; u < 5; u++) {
            float2 v = unpk(accp[img * 5 + u]);
            int p = img * 10 + 2 * u;
            g_Bmu[p * NPIX + h * 256 + w] = v.x;
            g_Bmu[(p + 1) * NPIX + h * 256 + w] = v.y;
        }
    }
}

// ---------------- horizontal pass: grid = row x 2 halves, 64 pid x 4 ke-groups ----------------
__global__ __launch_bounds__(256) void k_horiz(const float* __restrict__ basis_right,
                                               const float* __restrict__ mu,
                                               float* __restrict__ out) {
    extern __shared__ float smh[];
    float* P = smh;                 // 70 * 194 (192-col window, even stride)
    float* Rsm = P + 70 * 194;      // 650
    float* Msm = Rsm + 650;         // 650
    int h = blockIdx.x >> 1;
    int half = blockIdx.x & 1;
    int tid = threadIdx.x;
    int pid = tid & 63, grp = tid >> 6;       // 64 pids x 4 ke-groups
    const int base = half ? 64 : 0;           // staged cols [base, base+191]
    for (int i = tid; i < 650; i += 256) {
        Rsm[i] = basis_right[i];
        Msm[i] = mu[i];
    }
    for (int p = 0; p < 40; p++)
        for (int c = tid; c < 192; c += 256) P[p * 194 + c] = g_A[p * NPIX + h * 256 + base + c];
    for (int p = 0; p < 30; p++)
        for (int c = tid; c < 192; c += 256) P[(40 + p) * 194 + c] = g_Bmu[p * NPIX + h * 256 + base + c];
    __syncthreads();

    const int w0 = half * 128 + 2 * pid;
    float n0a = 0, n0b = 0, n1a = 0, n1b = 0, n2a = 0, n2b = 0, dna = 0, dnb = 0;

    // ke-steps s=0..32 (ke = 2s) split: grp0 s[0,9), grp1 [9,17), grp2 [17,25), grp3 [25,33)
    const int s_start = (grp == 0) ? 0 : (9 + (grp - 1) * 8);
    const int s_end = (grp == 0) ? 9 : (s_start + 8);
    for (int s = s_start; s < s_end; s++) {
        int ke = 2 * s;
        int c = w0 + ke - 32;
        bool fast = (c >= base) && (c <= 254);
        int ca = (c < 0) ? -c : ((c > 255) ? 510 - c : c);
        int cd = c + 1;
        int cb = (cd < 0) ? -cd : ((cd > 255) ? 510 - cd : cd);
        int ia = ca - base, ib = cb - base, ic = c - base;

        float Rm[10], R0[10], Rp[10], Mm[10], M0[10], Mp[10];
#pragma unroll
        for (int j = 0; j < 10; j++) {
            R0[j] = Rsm[ke * 10 + j];
            M0[j] = Msm[ke * 10 + j];
            Rp[j] = (ke < 64) ? Rsm[(ke + 1) * 10 + j] : 0.f;
            Mp[j] = (ke < 64) ? Msm[(ke + 1) * 10 + j] : 0.f;
            Rm[j] = (ke > 0) ? Rsm[(ke - 1) * 10 + j] : 0.f;
            Mm[j] = (ke > 0) ? Msm[(ke - 1) * 10 + j] : 0.f;
        }
#pragma unroll
        for (int j = 0; j < 10; j++) {
            float2 g;
#define LOADP(p) (fast ? *(const float2*)&P[(p) * 194 + ic] \
                       : make_float2(P[(p) * 194 + ia], P[(p) * 194 + ib]))
            g = LOADP(j);
            n0a += R0[j] * g.x + Rp[j] * g.y;  n0b += Rm[j] * g.x + R0[j] * g.y;
            g = LOADP(10 + j);
            n1a += R0[j] * g.x + Rp[j] * g.y;  n1b += Rm[j] * g.x + R0[j] * g.y;
            g = LOADP(20 + j);
            n2a += R0[j] * g.x + Rp[j] * g.y;  n2b += Rm[j] * g.x + R0[j] * g.y;
            g = LOADP(30 + j);
            dna += R0[j] * g.x + Rp[j] * g.y;  dnb += Rm[j] * g.x + R0[j] * g.y;
            g = LOADP(40 + j);
            n0a += M0[j] * g.x + Mp[j] * g.y;  n0b += Mm[j] * g.x + M0[j] * g.y;
            g = LOADP(50 + j);
            n1a += M0[j] * g.x + Mp[j] * g.y;  n1b += Mm[j] * g.x + M0[j] * g.y;
            g = LOADP(60 + j);
            n2a += M0[j] * g.x + Mp[j] * g.y;  n2b += Mm[j] * g.x + M0[j] * g.y;
#undef LOADP
        }
    }

    // ---- 4-way reduction through the P region (done with it) ----
    __syncthreads();
    float* scr = P;   // needs 24*64 = 1536 floats
    if (grp > 0) {
        int b = (grp - 1) * 512 + pid;
        scr[b + 0 * 64] = n0a; scr[b + 1 * 64] = n0b;
        scr[b + 2 * 64] = n1a; scr[b + 3 * 64] = n1b;
        scr[b + 4 * 64] = n2a; scr[b + 5 * 64] = n2b;
        scr[b + 6 * 64] = dna; scr[b + 7 * 64] = dnb;
    }
    __syncthreads();
    if (grp == 0) {
#pragma unroll
        for (int g = 0; g < 3; g++) {
            int b = g * 512 + pid;
            n0a += scr[b + 0 * 64]; n0b += scr[b + 1 * 64];
            n1a += scr[b + 2 * 64]; n1b += scr[b + 3 * 64];
            n2a += scr[b + 4 * 64]; n2b += scr[b + 5 * 64];
            dna += scr[b + 6 * 64]; dnb += scr[b + 7 * 64];
        }
        float dmu = g_denmu;
        dna += dmu;
        dnb += dmu;
        size_t obase = (size_t)h * 256 + w0;
        *reinterpret_cast<float2*>(&out[0 * NPIX + obase]) = make_float2(n0a / dna, n0b / dnb);
        *reinterpret_cast<float2*>(&out[1 * NPIX + obase]) = make_float2(n1a / dna, n1b / dnb);
        *reinterpret_cast<float2*>(&out[2 * NPIX + obase]) = make_float2(n2a / dna, n2b / dnb);
    }
}

// ---------------- launcher ----------------
extern "C" void kernel_launch(void* const* d_in, const int* in_sizes, int n_in,
                              void* d_out, int out_size) {
    const float* img  = (const float*)d_in[0];
    const float* zern = (const float*)d_in[1];
    const float* fc1w = (const float*)d_in[2];
    const float* fc1b = (const float*)d_in[3];
    const float* fc2w = (const float*)d_in[4];
    const float* fc2b = (const float*)d_in[5];
    const float* fc3w = (const float*)d_in[6];
    const float* fc3b = (const float*)d_in[7];
    const float* bl   = (const float*)d_in[8];
    const float* br   = (const float*)d_in[9];
    const float* mu   = (const float*)d_in[10];
    float* out = (float*)d_out;

    // k_vert smem: (2*128*51 + 670)*4 + 3*257*4 = 54904 + 3084 = 57988
    // k_horiz smem: 70*194*4 + 2*650*4 = 54320 + 5200 = 59520
    cudaFuncSetAttribute(k_mlp_fused, cudaFuncAttributeMaxDynamicSharedMemorySize, 155744);
    cudaFuncSetAttribute(k_vert, cudaFuncAttributeMaxDynamicSharedMemorySize, 57988);
    cudaFuncSetAttribute(k_horiz, cudaFuncAttributeMaxDynamicSharedMemorySize, 59520);

    uint32_t* coefh;
    cudaGetSymbolAddress((void**)&coefh, g_coefh);

    k_gridsample<<<256, 256>>>(img, zern);
    k_mlp_fused<<<148, 256, 155744>>>(zern, fc1w, fc1b, fc2w, fc2b, fc3w, fc3b, coefh);
    k_vert<<<256, 256, 57988>>>(bl);
    k_vmu<<<256, 256>>>(mu);
    k_horiz<<<512, 256, 59520>>>(br, mu, out);
}

// round 17
// speedup vs baseline: 1.7158x; 1.0016x over previous
#include <cuda_runtime.h>
#include <cuda_fp16.h>
#include <cstdint>

#define NPIX 65536

typedef unsigned long long u64;

// ---------------- scratch (device globals; no allocation) ----------------
__device__ float g_tiltT[3 * NPIX];               // TRANSPOSED: [c][w*256 + h]
__device__ uint32_t g_coefh[(size_t)NPIX * 50];   // coef as half2 pairs (j even/odd)
__device__ float g_A[40 * NPIX];
__device__ float g_Bmu[30 * NPIX];
__device__ float g_denmu;

// ---------------- packed f32x2 helpers (Blackwell) ----------------
__device__ __forceinline__ void fma2(u64& d, u64 a, u64 b) {
    asm("fma.rn.f32x2 %0, %1, %2, %0;" : "+l"(d) : "l"(a), "l"(b));
}
__device__ __forceinline__ void add2(u64& d, u64 a) {
    asm("add.rn.f32x2 %0, %0, %1;" : "+l"(d) : "l"(a));
}
__device__ __forceinline__ u64 dup2(float x) {
    u64 d;
    asm("mov.b64 %0, {%1, %2};" : "=l"(d) : "f"(x), "f"(x));
    return d;
}
__device__ __forceinline__ u64 pk2(float x, float y) {
    u64 d;
    asm("mov.b64 %0, {%1, %2};" : "=l"(d) : "f"(x), "f"(y));
    return d;
}
__device__ __forceinline__ float2 unpk(u64 v) {
    float2 r;
    asm("mov.b64 {%0, %1}, %2;" : "=f"(r.x), "=f"(r.y) : "l"(v));
    return r;
}

// ---------------- warp-mma helpers ----------------
__device__ __forceinline__ void mma_f16(float* c, uint32_t a0, uint32_t a1, uint32_t a2,
                                        uint32_t a3, uint32_t b0, uint32_t b1) {
    asm volatile(
        "mma.sync.aligned.m16n8k16.row.col.f32.f16.f16.f32 "
        "{%0,%1,%2,%3}, {%4,%5,%6,%7}, {%8,%9}, {%0,%1,%2,%3};"
        : "+f"(c[0]), "+f"(c[1]), "+f"(c[2]), "+f"(c[3])
        : "r"(a0), "r"(a1), "r"(a2), "r"(a3), "r"(b0), "r"(b1));
}
__device__ __forceinline__ uint32_t pack_h2(float a, float b) {
    __half2 t;
    t.x = __float2half(a);
    t.y = __float2half(b);
    return *reinterpret_cast<uint32_t*>(&t);
}
__device__ __forceinline__ float lrelu(float v) { return v > 0.f ? v : 0.01f * v; }

// ================= fused 3-layer MLP, fragment-chained =================
__global__ __launch_bounds__(256, 1) void k_mlp_fused(
    const float* __restrict__ zern,
    const float* __restrict__ w1, const float* __restrict__ b1,
    const float* __restrict__ w2, const float* __restrict__ b2,
    const float* __restrict__ w3, const float* __restrict__ b3,
    uint32_t* __restrict__ coefh) {
    constexpr int KS1 = 56;
    constexpr int KS2 = 216;
    constexpr int O1 = 0;
    constexpr int O2 = O1 + 200 * KS1;
    constexpr int O3 = O2 + 200 * KS2;
    constexpr int OEND = O3 + 104 * KS2;

    extern __shared__ char smraw[];
    __half* sw = reinterpret_cast<__half*>(smraw);
    float* bias_s = reinterpret_cast<float*>(sw + OEND);

    int tid = threadIdx.x;
    int lane = tid & 31, warp = tid >> 5;

    for (int idx = tid; idx < 200 * 48; idx += 256) {
        int n = idx / 48, k = idx % 48;
        sw[O1 + n * KS1 + k] = __float2half((k < 33) ? w1[n * 33 + k] : 0.0f);
    }
    for (int idx = tid; idx < 200 * 208; idx += 256) {
        int n = idx / 208, k = idx % 208;
        sw[O2 + n * KS2 + k] = __float2half((k < 200) ? w2[n * 200 + k] : 0.0f);
    }
    for (int idx = tid; idx < 104 * 208; idx += 256) {
        int n = idx / 208, k = idx % 208;
        sw[O3 + n * KS2 + k] = __float2half((n < 100 && k < 200) ? w3[n * 200 + k] : 0.0f);
    }
    for (int i = tid; i < 200; i += 256) {
        bias_s[i] = b1[i];
        bias_s[200 + i] = b2[i];
    }
    for (int i = tid; i < 104; i += 256) bias_s[400 + i] = (i < 100) ? b3[i] : 0.0f;
    __syncthreads();

    const int k0 = (lane & 3) * 2;
    const int nrow = lane >> 2;
    const int gw = blockIdx.x * 8 + warp;
    const int gstride = gridDim.x * 8;

    for (int wt = gw; wt < 4096; wt += gstride) {
        const int row0 = wt * 16 + nrow;
        const int row1 = row0 + 8;
        const float* z0 = zern + (size_t)row0 * 35 + 2;
        const float* z1 = zern + (size_t)row1 * 35 + 2;

        float acc[25][4];
#pragma unroll
        for (int nt = 0; nt < 25; nt++)
#pragma unroll
            for (int q = 0; q < 4; q++) acc[nt][q] = 0.0f;

        // layer 1: K=33
#pragma unroll
        for (int kc = 0; kc < 3; kc++) {
            int kb = kc * 16 + k0;
            float x00 = (kb < 33) ? z0[kb] : 0.f;
            float x01 = (kb + 1 < 33) ? z0[kb + 1] : 0.f;
            float x10 = (kb < 33) ? z1[kb] : 0.f;
            float x11 = (kb + 1 < 33) ? z1[kb + 1] : 0.f;
            float x02 = (kb + 8 < 33) ? z0[kb + 8] : 0.f;
            float x03 = (kb + 9 < 33) ? z0[kb + 9] : 0.f;
            float x12 = (kb + 8 < 33) ? z1[kb + 8] : 0.f;
            float x13 = (kb + 9 < 33) ? z1[kb + 9] : 0.f;
            uint32_t ah0 = pack_h2(x00, x01);
            uint32_t ah1 = pack_h2(x10, x11);
            uint32_t ah2 = pack_h2(x02, x03);
            uint32_t ah3 = pack_h2(x12, x13);
#pragma unroll
            for (int nt = 0; nt < 25; nt++) {
                const __half* ph = sw + O1 + (nt * 8 + nrow) * KS1 + kc * 16 + k0;
                uint32_t bh0 = *reinterpret_cast<const uint32_t*>(ph);
                uint32_t bh1 = *reinterpret_cast<const uint32_t*>(ph + 8);
                mma_f16(acc[nt], ah0, ah1, ah2, ah3, bh0, bh1);
            }
        }

        uint32_t af[13][4];
#pragma unroll
        for (int kc = 0; kc < 13; kc++) {
            {
                int cc = kc * 16 + k0;
                float bv0 = bias_s[cc], bv1 = bias_s[cc + 1];
                af[kc][0] = pack_h2(lrelu(acc[2 * kc][0] + bv0), lrelu(acc[2 * kc][1] + bv1));
                af[kc][1] = pack_h2(lrelu(acc[2 * kc][2] + bv0), lrelu(acc[2 * kc][3] + bv1));
            }
            if (kc < 12) {
                int cc = kc * 16 + 8 + k0;
                float bv0 = bias_s[cc], bv1 = bias_s[cc + 1];
                af[kc][2] = pack_h2(lrelu(acc[2 * kc + 1][0] + bv0), lrelu(acc[2 * kc + 1][1] + bv1));
                af[kc][3] = pack_h2(lrelu(acc[2 * kc + 1][2] + bv0), lrelu(acc[2 * kc + 1][3] + bv1));
            } else {
                af[kc][2] = 0u;
                af[kc][3] = 0u;
            }
        }

        // layer 2
#pragma unroll
        for (int nt = 0; nt < 25; nt++)
#pragma unroll
            for (int q = 0; q < 4; q++) acc[nt][q] = 0.0f;
#pragma unroll
        for (int kc = 0; kc < 13; kc++) {
            uint32_t ah0 = af[kc][0], ah1 = af[kc][1], ah2 = af[kc][2], ah3 = af[kc][3];
#pragma unroll
            for (int nt = 0; nt < 25; nt++) {
                const __half* ph = sw + O2 + (nt * 8 + nrow) * KS2 + kc * 16 + k0;
                uint32_t bh0 = *reinterpret_cast<const uint32_t*>(ph);
                uint32_t bh1 = *reinterpret_cast<const uint32_t*>(ph + 8);
                mma_f16(acc[nt], ah0, ah1, ah2, ah3, bh0, bh1);
            }
        }

#pragma unroll
        for (int kc = 0; kc < 13; kc++) {
            {
                int cc = kc * 16 + k0;
                float bv0 = bias_s[200 + cc], bv1 = bias_s[200 + cc + 1];
                af[kc][0] = pack_h2(lrelu(acc[2 * kc][0] + bv0), lrelu(acc[2 * kc][1] + bv1));
                af[kc][1] = pack_h2(lrelu(acc[2 * kc][2] + bv0), lrelu(acc[2 * kc][3] + bv1));
            }
            if (kc < 12) {
                int cc = kc * 16 + 8 + k0;
                float bv0 = bias_s[200 + cc], bv1 = bias_s[200 + cc + 1];
                af[kc][2] = pack_h2(lrelu(acc[2 * kc + 1][0] + bv0), lrelu(acc[2 * kc + 1][1] + bv1));
                af[kc][3] = pack_h2(lrelu(acc[2 * kc + 1][2] + bv0), lrelu(acc[2 * kc + 1][3] + bv1));
            } else {
                af[kc][2] = 0u;
                af[kc][3] = 0u;
            }
        }

        // layer 3
        float acc3[13][4];
#pragma unroll
        for (int nt = 0; nt < 13; nt++)
#pragma unroll
            for (int q = 0; q < 4; q++) acc3[nt][q] = 0.0f;
#pragma unroll
        for (int kc = 0; kc < 13; kc++) {
            uint32_t ah0 = af[kc][0], ah1 = af[kc][1], ah2 = af[kc][2], ah3 = af[kc][3];
#pragma unroll
            for (int nt = 0; nt < 13; nt++) {
                const __half* ph = sw + O3 + (nt * 8 + nrow) * KS2 + kc * 16 + k0;
                uint32_t bh0 = *reinterpret_cast<const uint32_t*>(ph);
                uint32_t bh1 = *reinterpret_cast<const uint32_t*>(ph + 8);
                mma_f16(acc3[nt], ah0, ah1, ah2, ah3, bh0, bh1);
            }
        }

        // ---- epilogue: bias + pack to half2, store coef ----
        uint32_t* c0 = coefh + (size_t)row0 * 50;
        uint32_t* c1 = coefh + (size_t)row1 * 50;
#pragma unroll
        for (int nt = 0; nt < 13; nt++) {
            int cc = nt * 8 + k0;
            if (cc < 100) {
                float bv0 = bias_s[400 + cc], bv1 = bias_s[400 + cc + 1];
                c0[cc >> 1] = pack_h2(acc3[nt][0] + bv0, acc3[nt][1] + bv1);
                c1[cc >> 1] = pack_h2(acc3[nt][2] + bv0, acc3[nt][3] + bv1);
            }
        }
    }
}

// ---------------- bilinear grid sample (stores tilt TRANSPOSED) ----------------
__global__ void k_gridsample(const float* __restrict__ img, const float* __restrict__ zern) {
    int p = blockIdx.x * blockDim.x + threadIdx.x;
    if (p >= NPIX) return;
    int y = p >> 8, x = p & 255;
    float px = zern[p * 35 + 0], py = zern[p * 35 + 1];
    float fx = 2.0f * ((float)x + px) / 255.0f - 1.0f;
    float fy = 2.0f * ((float)y + py) / 255.0f - 1.0f;
    float ix = ((fx + 1.0f) * 256.0f - 1.0f) * 0.5f;
    float iy = ((fy + 1.0f) * 256.0f - 1.0f) * 0.5f;
    ix = fminf(fmaxf(ix, 0.f), 255.f);
    iy = fminf(fmaxf(iy, 0.f), 255.f);
    float x0f = floorf(ix), y0f = floorf(iy);
    float wx = ix - x0f, wy = iy - y0f;
    int x0 = (int)x0f, y0 = (int)y0f;
    int x1 = min(x0 + 1, 255), y1 = min(y0 + 1, 255);
#pragma unroll
    for (int c = 0; c < 3; c++) {
        const float* im = img + c * NPIX;
        float g00 = im[y0 * 256 + x0], g01 = im[y0 * 256 + x1];
        float g10 = im[y1 * 256 + x0], g11 = im[y1 * 256 + x1];
        float top = g00 * (1.f - wx) + g01 * wx;
        float bot = g10 * (1.f - wx) + g11 * wx;
        g_tiltT[c * NPIX + x * 256 + y] = top * (1.f - wy) + bot * wy;
    }
}

// ---------------- vertical pass: fp16 coef + HFMA2 s-stage, zero-padded L ----------------
__global__ __launch_bounds__(256, 2) void k_vert(const float* __restrict__ basis_left) {
    extern __shared__ uint32_t smw[];
    uint32_t* cE = smw;                       // 128*51 words (half2 coef, even rows)
    uint32_t* cO = smw + 128 * 51;            // odd rows
    uint32_t* Lh = smw + 2 * 128 * 51;        // 670 half2-dup, rows 0 and 66 zero
    float* tiltS = reinterpret_cast<float*>(Lh + 670);  // 3*257
    int w = blockIdx.x, tid = threadIdx.x;
    int pid = tid & 127, grp = tid >> 7;
    for (int i = tid; i < 670; i += 256) {
        int row = i / 10, col = i % 10;
        float v = (row >= 1 && row <= 65) ? basis_left[(row - 1) * 10 + col] : 0.0f;
        __half hv = __float2half(v);
        __half2 d2; d2.x = hv; d2.y = hv;
        Lh[i] = *reinterpret_cast<uint32_t*>(&d2);
    }
    for (int li = tid; li < 12800; li += 256) {
        int hh = li / 50, q = li % 50;
        uint32_t v = g_coefh[(size_t)(hh * 256 + w) * 50 + q];
        ((hh & 1) ? cO : cE)[(hh >> 1) * 51 + q] = v;
    }
    for (int li = tid; li < 768; li += 256) {
        int k = li >> 8, hh = li & 255;
        tiltS[k * 257 + hh] = g_tiltT[k * NPIX + w * 256 + hh];   // coalesced
    }
    __syncthreads();

    const int h1 = 2 * pid;
    const u64 ONEd = dup2(1.0f);
    const __half2 HZERO = __float2half2_rn(0.0f);
    u64 acc1p[20], acc2p[20];
#pragma unroll
    for (int p = 0; p < 20; p++) { acc1p[p] = 0ull; acc2p[p] = 0ull; }

    const int ro0 = grp * 33 - 32;  // grp0: [-32..0], grp1: [1..33]
#pragma unroll 2
    for (int it = 0; it < 33; it++) {
        int ro = ro0 + it;
        int r = h1 + ro;
        r = (r < 0) ? -r : ((r > 255) ? 510 - r : r);
        int t1p = ro + 33, t2p = ro + 32;   // padded L indices (rows 0/66 are zero)
        const uint32_t* crow = ((r & 1) ? cO : cE) + (r >> 1) * 51;
        __half2 s1h[5], s2h[5];
#pragma unroll
        for (int u = 0; u < 5; u++) { s1h[u] = HZERO; s2h[u] = HZERO; }
#pragma unroll
        for (int i = 0; i < 10; i++) {
            uint32_t l1w = Lh[t1p * 10 + i];
            uint32_t l2w = Lh[t2p * 10 + i];
            __half2 L1 = *reinterpret_cast<__half2*>(&l1w);
            __half2 L2 = *reinterpret_cast<__half2*>(&l2w);
#pragma unroll
            for (int u = 0; u < 5; u++) {
                uint32_t cwu = crow[i * 5 + u];
                __half2 cw = *reinterpret_cast<__half2*>(&cwu);
                s1h[u] = __hfma2(L1, cw, s1h[u]);
                s2h[u] = __hfma2(L2, cw, s2h[u]);
            }
        }
        u64 T0d = dup2(tiltS[r]), T1d = dup2(tiltS[257 + r]), T2d = dup2(tiltS[514 + r]);
#pragma unroll
        for (int u = 0; u < 5; u++) {
            float2 f1 = __half22float2(s1h[u]);
            float2 f2 = __half22float2(s2h[u]);
            u64 s1w = pk2(f1.x, f1.y);
            u64 s2w = pk2(f2.x, f2.y);
            fma2(acc1p[u], T0d, s1w);
            fma2(acc1p[5 + u], T1d, s1w);
            fma2(acc1p[10 + u], T2d, s1w);
            fma2(acc1p[15 + u], ONEd, s1w);
            fma2(acc2p[u], T0d, s2w);
            fma2(acc2p[5 + u], T1d, s2w);
            fma2(acc2p[10 + u], T2d, s2w);
            fma2(acc2p[15 + u], ONEd, s2w);
        }
    }

    // ---- cross-group reduction through the coef smem region ----
    __syncthreads();
    u64* scr = reinterpret_cast<u64*>(smw);
    if (grp == 1) {
#pragma unroll
        for (int q = 0; q < 20; q++) scr[q * 128 + pid] = acc1p[q];
#pragma unroll
        for (int q = 0; q < 20; q++) scr[(20 + q) * 128 + pid] = acc2p[q];
    }
    __syncthreads();
    if (grp == 0) {
#pragma unroll
        for (int q = 0; q < 20; q++) add2(acc1p[q], scr[q * 128 + pid]);
#pragma unroll
        for (int q = 0; q < 20; q++) add2(acc2p[q], scr[(20 + q) * 128 + pid]);
#pragma unroll
        for (int img = 0; img < 4; img++) {
#pragma unroll
            for (int u = 0; u < 5; u++) {
                float2 v1 = unpk(acc1p[img * 5 + u]);
                float2 v2 = unpk(acc2p[img * 5 + u]);
                int p = img * 10 + 2 * u;
                g_A[p * NPIX + h1 * 256 + w] = v1.x;
                g_A[(p + 1) * NPIX + h1 * 256 + w] = v1.y;
                g_A[p * NPIX + (h1 + 1) * 256 + w] = v2.x;
                g_A[(p + 1) * NPIX + (h1 + 1) * 256 + w] = v2.y;
            }
        }
    }
}

// ---------------- vertical mu pass: 512 threads, tap-split x2 (+ denmu in block 0) ----------------
// tiltS padded to 772 floats so Msm (read as u64) stays 8-byte aligned.
__global__ __launch_bounds__(512) void k_vmu(const float* __restrict__ mu) {
    extern __shared__ char smvm[];
    u64* scr = reinterpret_cast<u64*>(smvm);                 // 15*256 u64 = 30720B
    float* tiltS = reinterpret_cast<float*>(smvm + 30720);   // 772 floats (3*257 used)
    float* Msm = tiltS + 772;                                // 8B-aligned: 30720+3088
    __shared__ float S2[10];
    int w = blockIdx.x, tid = threadIdx.x;
    int pid = tid & 255, grp = tid >> 8;
    for (int i = tid; i < 650; i += 512) Msm[i] = mu[i];
    for (int li = tid; li < 768; li += 512) {
        int k = li >> 8, hh = li & 255;
        tiltS[k * 257 + hh] = g_tiltT[k * NPIX + w * 256 + hh];   // coalesced
    }
    if (w == 0 && tid < 10) {
        float s = 0.f;
        for (int t = 0; t < 65; t++) s += mu[t * 10 + tid];
        S2[tid] = s * s;
    }
    __syncthreads();
    if (w == 0 && tid == 0) {
        float d = 0.f;
        for (int m = 0; m < 10; m++) d += S2[m];
        g_denmu = d;
    }
    int h = pid;
    u64 accp[15];
#pragma unroll
    for (int q = 0; q < 15; q++) accp[q] = 0ull;
    const int t0 = grp ? 33 : 0;
    const int t1 = grp ? 65 : 33;
#pragma unroll 4
    for (int t = t0; t < t1; t++) {
        int r = h + t - 32;
        r = (r < 0) ? -r : ((r > 255) ? 510 - r : r);
        u64 T0d = dup2(tiltS[r]), T1d = dup2(tiltS[257 + r]), T2d = dup2(tiltS[514 + r]);
        const u64* mrow = reinterpret_cast<const u64*>(Msm + t * 10);
#pragma unroll
        for (int u = 0; u < 5; u++) {
            u64 mw = mrow[u];
            fma2(accp[u], T0d, mw);
            fma2(accp[5 + u], T1d, mw);
            fma2(accp[10 + u], T2d, mw);
        }
    }
    __syncthreads();
    if (grp == 1) {
#pragma unroll
        for (int q = 0; q < 15; q++) scr[q * 256 + pid] = accp[q];
    }
    __syncthreads();
    if (grp == 0) {
#pragma unroll
        for (int q = 0; q < 15; q++) add2(accp[q], scr[q * 256 + pid]);
#pragma unroll
        for (int img = 0; img < 3; img++) {
#pragma unroll
            for (int u = 0; u < 5; u++) {
                float2 v = unpk(accp[img * 5 + u]);
                int p = img * 10 + 2 * u;
                g_Bmu[p * NPIX + h * 256 + w] = v.x;
                g_Bmu[(p + 1) * NPIX + h * 256 + w] = v.y;
            }
        }
    }
}

// ---------------- horizontal pass: grid = row x 2 halves, 64 pid x 4 ke-groups ----------------
__global__ __launch_bounds__(256) void k_horiz(const float* __restrict__ basis_right,
                                               const float* __restrict__ mu,
                                               float* __restrict__ out) {
    extern __shared__ float smh[];
    float* P = smh;                 // 70 * 194 (192-col window, even stride)
    float* Rsm = P + 70 * 194;      // 650
    float* Msm = Rsm + 650;         // 650
    int h = blockIdx.x >> 1;
    int half = blockIdx.x & 1;
    int tid = threadIdx.x;
    int pid = tid & 63, grp = tid >> 6;
    const int base = half ? 64 : 0;
    for (int i = tid; i < 650; i += 256) {
        Rsm[i] = basis_right[i];
        Msm[i] = mu[i];
    }
    for (int p = 0; p < 40; p++)
        for (int c = tid; c < 192; c += 256) P[p * 194 + c] = g_A[p * NPIX + h * 256 + base + c];
    for (int p = 0; p < 30; p++)
        for (int c = tid; c < 192; c += 256) P[(40 + p) * 194 + c] = g_Bmu[p * NPIX + h * 256 + base + c];
    __syncthreads();

    const int w0 = half * 128 + 2 * pid;
    float n0a = 0, n0b = 0, n1a = 0, n1b = 0, n2a = 0, n2b = 0, dna = 0, dnb = 0;

    const int s_start = (grp == 0) ? 0 : (9 + (grp - 1) * 8);
    const int s_end = (grp == 0) ? 9 : (s_start + 8);
    for (int s = s_start; s < s_end; s++) {
        int ke = 2 * s;
        int c = w0 + ke - 32;
        bool fast = (c >= base) && (c <= 254);
        int ca = (c < 0) ? -c : ((c > 255) ? 510 - c : c);
        int cd = c + 1;
        int cb = (cd < 0) ? -cd : ((cd > 255) ? 510 - cd : cd);
        int ia = ca - base, ib = cb - base, ic = c - base;

        float Rm[10], R0[10], Rp[10], Mm[10], M0[10], Mp[10];
#pragma unroll
        for (int j = 0; j < 10; j++) {
            R0[j] = Rsm[ke * 10 + j];
            M0[j] = Msm[ke * 10 + j];
            Rp[j] = (ke < 64) ? Rsm[(ke + 1) * 10 + j] : 0.f;
            Mp[j] = (ke < 64) ? Msm[(ke + 1) * 10 + j] : 0.f;
            Rm[j] = (ke > 0) ? Rsm[(ke - 1) * 10 + j] : 0.f;
            Mm[j] = (ke > 0) ? Msm[(ke - 1) * 10 + j] : 0.f;
        }
#pragma unroll
        for (int j = 0; j < 10; j++) {
            float2 g;
#define LOADP(p) (fast ? *(const float2*)&P[(p) * 194 + ic] \
                       : make_float2(P[(p) * 194 + ia], P[(p) * 194 + ib]))
            g = LOADP(j);
            n0a += R0[j] * g.x + Rp[j] * g.y;  n0b += Rm[j] * g.x + R0[j] * g.y;
            g = LOADP(10 + j);
            n1a += R0[j] * g.x + Rp[j] * g.y;  n1b += Rm[j] * g.x + R0[j] * g.y;
            g = LOADP(20 + j);
            n2a += R0[j] * g.x + Rp[j] * g.y;  n2b += Rm[j] * g.x + R0[j] * g.y;
            g = LOADP(30 + j);
            dna += R0[j] * g.x + Rp[j] * g.y;  dnb += Rm[j] * g.x + R0[j] * g.y;
            g = LOADP(40 + j);
            n0a += M0[j] * g.x + Mp[j] * g.y;  n0b += Mm[j] * g.x + M0[j] * g.y;
            g = LOADP(50 + j);
            n1a += M0[j] * g.x + Mp[j] * g.y;  n1b += Mm[j] * g.x + M0[j] * g.y;
            g = LOADP(60 + j);
            n2a += M0[j] * g.x + Mp[j] * g.y;  n2b += Mm[j] * g.x + M0[j] * g.y;
#undef LOADP
        }
    }

    __syncthreads();
    float* scr = P;
    if (grp > 0) {
        int b = (grp - 1) * 512 + pid;
        scr[b + 0 * 64] = n0a; scr[b + 1 * 64] = n0b;
        scr[b + 2 * 64] = n1a; scr[b + 3 * 64] = n1b;
        scr[b + 4 * 64] = n2a; scr[b + 5 * 64] = n2b;
        scr[b + 6 * 64] = dna; scr[b + 7 * 64] = dnb;
    }
    __syncthreads();
    if (grp == 0) {
#pragma unroll
        for (int g = 0; g < 3; g++) {
            int b = g * 512 + pid;
            n0a += scr[b + 0 * 64]; n0b += scr[b + 1 * 64];
            n1a += scr[b + 2 * 64]; n1b += scr[b + 3 * 64];
            n2a += scr[b + 4 * 64]; n2b += scr[b + 5 * 64];
            dna += scr[b + 6 * 64]; dnb += scr[b + 7 * 64];
        }
        float dmu = g_denmu;
        dna += dmu;
        dnb += dmu;
        size_t obase = (size_t)h * 256 + w0;
        *reinterpret_cast<float2*>(&out[0 * NPIX + obase]) = make_float2(n0a / dna, n0b / dnb);
        *reinterpret_cast<float2*>(&out[1 * NPIX + obase]) = make_float2(n1a / dna, n1b / dnb);
        *reinterpret_cast<float2*>(&out[2 * NPIX + obase]) = make_float2(n2a / dna, n2b / dnb);
    }
}

// ---------------- launcher ----------------
extern "C" void kernel_launch(void* const* d_in, const int* in_sizes, int n_in,
                              void* d_out, int out_size) {
    const float* img  = (const float*)d_in[0];
    const float* zern = (const float*)d_in[1];
    const float* fc1w = (const float*)d_in[2];
    const float* fc1b = (const float*)d_in[3];
    const float* fc2w = (const float*)d_in[4];
    const float* fc2b = (const float*)d_in[5];
    const float* fc3w = (const float*)d_in[6];
    const float* fc3b = (const float*)d_in[7];
    const float* bl   = (const float*)d_in[8];
    const float* br   = (const float*)d_in[9];
    const float* mu   = (const float*)d_in[10];
    float* out = (float*)d_out;

    cudaFuncSetAttribute(k_mlp_fused, cudaFuncAttributeMaxDynamicSharedMemorySize, 155744);
    cudaFuncSetAttribute(k_vert, cudaFuncAttributeMaxDynamicSharedMemorySize, 57988);
    // k_vmu smem: 30720 + 772*4 + 650*4 = 36408
    cudaFuncSetAttribute(k_vmu, cudaFuncAttributeMaxDynamicSharedMemorySize, 36408);
    cudaFuncSetAttribute(k_horiz, cudaFuncAttributeMaxDynamicSharedMemorySize, 59520);

    uint32_t* coefh;
    cudaGetSymbolAddress((void**)&coefh, g_coefh);

    k_gridsample<<<256, 256>>>(img, zern);
    k_mlp_fused<<<148, 256, 155744>>>(zern, fc1w, fc1b, fc2w, fc2b, fc3w, fc3b, coefh);
    k_vert<<<256, 256, 57988>>>(bl);
    k_vmu<<<256, 512, 36408>>>(mu);
    k_horiz<<<512, 256, 59520>>>(br, mu, out);
}